// round 2
// baseline (speedup 1.0000x reference)
#include <cuda_runtime.h>
#include <math.h>
#include <stdint.h>

#define S_IMGC 2048
#define S_TXTC 512
#define S_TOTC 2560
#define DC     1536
#define HC     24
#define DHC    64

// Scratch (device globals: allocation-free rule)
__device__ float g_q[(size_t)HC * S_TOTC * DHC];
__device__ float g_k[(size_t)HC * S_TOTC * DHC];
__device__ float g_v[(size_t)HC * S_TOTC * DHC];
__device__ float g_ao[(size_t)S_TOTC * DC];

// ---------------------------------------------------------------------------
// TF32x3 tensor-core GEMM: C[M x 1536] = X[M x 1536] * W[1536 x 1536]^T + bias
// Block tile 128x128, BK=16, 256 threads (8 warps), warp tile 64x32.
// 3-pass TF32 split (Ah*Bh + Ah*Bl + Al*Bh) for ~fp32 accuracy.
// mode 0: scatter into head-major qkv buffer [h][s_off+m][d] (n = h*64+d)
// mode 1: row-major out[m*DC + n]
// ---------------------------------------------------------------------------

__device__ __forceinline__ void split_tf32(float x, uint32_t& hi, uint32_t& lo) {
    uint32_t h;
    asm("cvt.rna.tf32.f32 %0, %1;" : "=r"(h) : "f"(x));
    float hf = __uint_as_float(h);
    float l = x - hf;
    uint32_t lu;
    asm("cvt.rna.tf32.f32 %0, %1;" : "=r"(lu) : "f"(l));
    hi = h; lo = lu;
}

__device__ __forceinline__ void mma_tf32(float* c, const uint32_t* a, const uint32_t* b) {
    asm volatile(
        "mma.sync.aligned.m16n8k8.row.col.f32.tf32.tf32.f32 "
        "{%0,%1,%2,%3}, {%4,%5,%6,%7}, {%8,%9}, {%0,%1,%2,%3};"
        : "+f"(c[0]), "+f"(c[1]), "+f"(c[2]), "+f"(c[3])
        : "r"(a[0]), "r"(a[1]), "r"(a[2]), "r"(a[3]), "r"(b[0]), "r"(b[1]));
}

__global__ __launch_bounds__(256, 1) void gemm_tf32(
    const float* __restrict__ X, const float* __restrict__ W,
    const float* __restrict__ bias, float* __restrict__ out,
    int s_off, int mode)
{
    // padded to 20 floats/row: conflict-free for both the split-store and
    // the m16n8k8 fragment gather (row-stride 20 -> bank offsets 0,20,8,28,...)
    __shared__ float sAh[128][20];
    __shared__ float sAl[128][20];
    __shared__ float sBh[128][20];
    __shared__ float sBl[128][20];

    const int tid  = threadIdx.x;
    const int wid  = tid >> 5;
    const int lane = tid & 31;
    const int g    = lane >> 2;   // groupID
    const int tig  = lane & 3;    // thread-in-group
    const int wm   = wid & 1;     // warp m index (2)
    const int wn   = wid >> 1;    // warp n index (4)

    const int ldr = tid >> 2;          // 0..63 (load row within half-tile)
    const int ldc = (tid & 3) << 2;    // 0,4,8,12

    const float* Xp = X + (size_t)(blockIdx.y * 128 + ldr) * DC + ldc;
    const float* Wp = W + (size_t)(blockIdx.x * 128 + ldr) * DC + ldc;

    float acc[4][4][4];
    #pragma unroll
    for (int i = 0; i < 4; ++i)
        #pragma unroll
        for (int j = 0; j < 4; ++j)
            #pragma unroll
            for (int r = 0; r < 4; ++r) acc[i][j][r] = 0.0f;

    // register prefetch (double-buffer globals)
    float4 xa0 = *(const float4*)(Xp);
    float4 xa1 = *(const float4*)(Xp + (size_t)64 * DC);
    float4 xb0 = *(const float4*)(Wp);
    float4 xb1 = *(const float4*)(Wp + (size_t)64 * DC);

    for (int kt = 0; kt < DC / 16; ++kt) {
        __syncthreads();
        // split + store current chunk
        {
            const float a0[4] = {xa0.x, xa0.y, xa0.z, xa0.w};
            const float a1[4] = {xa1.x, xa1.y, xa1.z, xa1.w};
            const float b0[4] = {xb0.x, xb0.y, xb0.z, xb0.w};
            const float b1[4] = {xb1.x, xb1.y, xb1.z, xb1.w};
            #pragma unroll
            for (int i = 0; i < 4; ++i) {
                uint32_t h, l;
                split_tf32(a0[i], h, l);
                sAh[ldr][ldc + i] = __uint_as_float(h);
                sAl[ldr][ldc + i] = __uint_as_float(l);
                split_tf32(a1[i], h, l);
                sAh[ldr + 64][ldc + i] = __uint_as_float(h);
                sAl[ldr + 64][ldc + i] = __uint_as_float(l);
                split_tf32(b0[i], h, l);
                sBh[ldr][ldc + i] = __uint_as_float(h);
                sBl[ldr][ldc + i] = __uint_as_float(l);
                split_tf32(b1[i], h, l);
                sBh[ldr + 64][ldc + i] = __uint_as_float(h);
                sBl[ldr + 64][ldc + i] = __uint_as_float(l);
            }
        }
        __syncthreads();

        // prefetch next chunk
        if (kt + 1 < DC / 16) {
            const int ko = (kt + 1) * 16;
            xa0 = *(const float4*)(Xp + ko);
            xa1 = *(const float4*)(Xp + (size_t)64 * DC + ko);
            xb0 = *(const float4*)(Wp + ko);
            xb1 = *(const float4*)(Wp + (size_t)64 * DC + ko);
        }

        // compute: two k8 groups
        #pragma unroll
        for (int kk = 0; kk < 16; kk += 8) {
            uint32_t ah[4][4], al[4][4], bh[4][2], bl[4][2];
            #pragma unroll
            for (int mi = 0; mi < 4; ++mi) {
                const int r = wm * 64 + mi * 16 + g;
                ah[mi][0] = __float_as_uint(sAh[r][kk + tig]);
                ah[mi][1] = __float_as_uint(sAh[r + 8][kk + tig]);
                ah[mi][2] = __float_as_uint(sAh[r][kk + tig + 4]);
                ah[mi][3] = __float_as_uint(sAh[r + 8][kk + tig + 4]);
                al[mi][0] = __float_as_uint(sAl[r][kk + tig]);
                al[mi][1] = __float_as_uint(sAl[r + 8][kk + tig]);
                al[mi][2] = __float_as_uint(sAl[r][kk + tig + 4]);
                al[mi][3] = __float_as_uint(sAl[r + 8][kk + tig + 4]);
            }
            #pragma unroll
            for (int ni = 0; ni < 4; ++ni) {
                const int cn = wn * 32 + ni * 8 + g;
                bh[ni][0] = __float_as_uint(sBh[cn][kk + tig]);
                bh[ni][1] = __float_as_uint(sBh[cn][kk + tig + 4]);
                bl[ni][0] = __float_as_uint(sBl[cn][kk + tig]);
                bl[ni][1] = __float_as_uint(sBl[cn][kk + tig + 4]);
            }
            #pragma unroll
            for (int mi = 0; mi < 4; ++mi)
                #pragma unroll
                for (int ni = 0; ni < 4; ++ni) {
                    mma_tf32(acc[mi][ni], ah[mi], bh[ni]);
                    mma_tf32(acc[mi][ni], ah[mi], bl[ni]);
                    mma_tf32(acc[mi][ni], al[mi], bh[ni]);
                }
        }
    }

    // epilogue
    #pragma unroll
    for (int mi = 0; mi < 4; ++mi) {
        #pragma unroll
        for (int ni = 0; ni < 4; ++ni) {
            const int row0 = blockIdx.y * 128 + wm * 64 + mi * 16 + g;
            const int col0 = blockIdx.x * 128 + wn * 32 + ni * 8 + 2 * tig;
            const float bx = bias[col0], by = bias[col0 + 1];
            float2 v0 = {acc[mi][ni][0] + bx, acc[mi][ni][1] + by};
            float2 v1 = {acc[mi][ni][2] + bx, acc[mi][ni][3] + by};
            if (mode == 0) {
                const int h = col0 >> 6, d = col0 & 63;
                float* p0 = out + ((size_t)h * S_TOTC + (s_off + row0)) * DHC + d;
                float* p1 = out + ((size_t)h * S_TOTC + (s_off + row0 + 8)) * DHC + d;
                *(float2*)p0 = v0;
                *(float2*)p1 = v1;
            } else {
                *(float2*)(out + (size_t)row0 * DC + col0) = v0;
                *(float2*)(out + (size_t)(row0 + 8) * DC + col0) = v1;
            }
        }
    }
}

// ---------------------------------------------------------------------------
// Per-(h,s) RMS-norm + RoPE on q or k (in place). 1 block = 1 row, 32 threads
// ---------------------------------------------------------------------------
__global__ __launch_bounds__(32) void rmsrope(
    float* __restrict__ buf,
    const float* __restrict__ cosb, const float* __restrict__ sinb,
    const float* __restrict__ gtxt, const float* __restrict__ gimg)
{
    const int s = blockIdx.x, h = blockIdx.y, t = threadIdx.x;
    float* p = buf + ((size_t)h * S_TOTC + s) * DHC;
    float x0 = p[2 * t], x1 = p[2 * t + 1];
    float ss = x0 * x0 + x1 * x1;
    #pragma unroll
    for (int o = 16; o; o >>= 1) ss += __shfl_xor_sync(0xffffffffu, ss, o);
    const float r = rsqrtf(ss * (1.0f / 64.0f) + 1e-6f);
    const float* g = (s < S_TXTC) ? gtxt : gimg;
    const float y0 = x0 * r * g[2 * t];
    const float y1 = x1 * r * g[2 * t + 1];
    const float c  = cosb[s * 64 + 2 * t];
    const float sn = sinb[s * 64 + 2 * t];
    p[2 * t]     = y0 * c - y1 * sn;
    p[2 * t + 1] = y1 * c + y0 * sn;
}

// ---------------------------------------------------------------------------
// Flash attention, fp32. 1 block = (head, 64-query tile), 64 threads,
// 1 thread = 1 query row. Online softmax in 16-wide chunks.
// ---------------------------------------------------------------------------
__global__ __launch_bounds__(64) void attn_kernel()
{
    __shared__ float Ks[64][68];
    __shared__ float Vs[64][68];
    const int h = blockIdx.y, qt = blockIdx.x, t = threadIdx.x;

    const float* qp = g_q + ((size_t)h * S_TOTC + qt * 64 + t) * DHC;
    float q[64];
    #pragma unroll
    for (int d = 0; d < 64; ++d) q[d] = qp[d] * 0.125f;

    float m = -3.0e38f, l = 0.0f;
    float acc[64];
    #pragma unroll
    for (int d = 0; d < 64; ++d) acc[d] = 0.0f;

    for (int j0 = 0; j0 < S_TOTC; j0 += 64) {
        __syncthreads();
        const float* kp = g_k + ((size_t)h * S_TOTC + j0 + t) * DHC;
        const float* vp = g_v + ((size_t)h * S_TOTC + j0 + t) * DHC;
        #pragma unroll
        for (int d = 0; d < 64; d += 4) {
            *(float4*)&Ks[t][d] = *(const float4*)(kp + d);
            *(float4*)&Vs[t][d] = *(const float4*)(vp + d);
        }
        __syncthreads();

        #pragma unroll 1
        for (int jc = 0; jc < 64; jc += 16) {
            float sreg[16];
            float mn = m;
            #pragma unroll
            for (int j = 0; j < 16; ++j) {
                float s0 = 0.f, s1 = 0.f, s2 = 0.f, s3 = 0.f;
                #pragma unroll
                for (int d = 0; d < 64; d += 4) {
                    const float4 kv = *(const float4*)&Ks[jc + j][d];
                    s0 = fmaf(q[d + 0], kv.x, s0);
                    s1 = fmaf(q[d + 1], kv.y, s1);
                    s2 = fmaf(q[d + 2], kv.z, s2);
                    s3 = fmaf(q[d + 3], kv.w, s3);
                }
                sreg[j] = (s0 + s1) + (s2 + s3);
                mn = fmaxf(mn, sreg[j]);
            }
            const float corr = __expf(m - mn);
            m = mn;
            l *= corr;
            #pragma unroll
            for (int d = 0; d < 64; ++d) acc[d] *= corr;
            #pragma unroll
            for (int j = 0; j < 16; ++j) {
                const float p = __expf(sreg[j] - mn);
                l += p;
                #pragma unroll
                for (int d = 0; d < 64; d += 4) {
                    const float4 vv = *(const float4*)&Vs[jc + j][d];
                    acc[d + 0] = fmaf(p, vv.x, acc[d + 0]);
                    acc[d + 1] = fmaf(p, vv.y, acc[d + 1]);
                    acc[d + 2] = fmaf(p, vv.z, acc[d + 2]);
                    acc[d + 3] = fmaf(p, vv.w, acc[d + 3]);
                }
            }
        }
    }

    const float inv = 1.0f / l;
    float* op = g_ao + (size_t)(qt * 64 + t) * DC + h * DHC;
    #pragma unroll
    for (int d = 0; d < 64; d += 4) {
        float4 w;
        w.x = acc[d + 0] * inv; w.y = acc[d + 1] * inv;
        w.z = acc[d + 2] * inv; w.w = acc[d + 3] * inv;
        *(float4*)(op + d) = w;
    }
}

// ---------------------------------------------------------------------------
extern "C" void kernel_launch(void* const* d_in, const int* in_sizes, int n_in,
                              void* d_out, int out_size)
{
    (void)in_sizes; (void)n_in; (void)out_size;
    const float* hs  = (const float*)d_in[0];
    const float* ehs = (const float*)d_in[1];
    const float* rc  = (const float*)d_in[2];
    const float* rs  = (const float*)d_in[3];
    const float* Wq  = (const float*)d_in[4];  const float* bq  = (const float*)d_in[5];
    const float* Wk  = (const float*)d_in[6];  const float* bk  = (const float*)d_in[7];
    const float* Wv  = (const float*)d_in[8];  const float* bv  = (const float*)d_in[9];
    const float* Waq = (const float*)d_in[10]; const float* baq = (const float*)d_in[11];
    const float* Wak = (const float*)d_in[12]; const float* bak = (const float*)d_in[13];
    const float* Wav = (const float*)d_in[14]; const float* bav = (const float*)d_in[15];
    const float* Wo  = (const float*)d_in[16]; const float* bo  = (const float*)d_in[17];
    const float* Wao = (const float*)d_in[18]; const float* bao = (const float*)d_in[19];
    const float* gq  = (const float*)d_in[20]; const float* gk  = (const float*)d_in[21];
    const float* gaq = (const float*)d_in[22]; const float* gak = (const float*)d_in[23];
    float* out = (float*)d_out;

    float *qb, *kb, *vb, *aob;
    cudaGetSymbolAddress((void**)&qb,  g_q);
    cudaGetSymbolAddress((void**)&kb,  g_k);
    cudaGetSymbolAddress((void**)&vb,  g_v);
    cudaGetSymbolAddress((void**)&aob, g_ao);

    const dim3 blk(256);
    const dim3 grid_txt(DC / 128, S_TXTC / 128);  // (12, 4)
    const dim3 grid_img(DC / 128, S_IMGC / 128);  // (12, 16)

    // QKV projections (text segment -> s [0,512), image segment -> s [512,2560))
    gemm_tf32<<<grid_txt, blk>>>(ehs, Waq, baq, qb, 0,   0);
    gemm_tf32<<<grid_txt, blk>>>(ehs, Wak, bak, kb, 0,   0);
    gemm_tf32<<<grid_txt, blk>>>(ehs, Wav, bav, vb, 0,   0);
    gemm_tf32<<<grid_img, blk>>>(hs,  Wq,  bq,  qb, 512, 0);
    gemm_tf32<<<grid_img, blk>>>(hs,  Wk,  bk,  kb, 512, 0);
    gemm_tf32<<<grid_img, blk>>>(hs,  Wv,  bv,  vb, 512, 0);

    // RMS norm + RoPE on q and k
    const dim3 rr_grid(S_TOTC, HC);
    rmsrope<<<rr_grid, 32>>>(qb, rc, rs, gaq, gq);
    rmsrope<<<rr_grid, 32>>>(kb, rc, rs, gak, gk);

    // Attention
    attn_kernel<<<dim3(S_TOTC / 64, HC), 64>>>();

    // Output projections
    gemm_tf32<<<grid_img, blk>>>(aob + (size_t)512 * DC, Wo,  bo,  out, 0, 1);
    gemm_tf32<<<grid_txt, blk>>>(aob, Wao, bao, out + (size_t)S_IMGC * DC, 0, 1);
}

// round 3
// speedup vs baseline: 1.7749x; 1.7749x over previous
#include <cuda_runtime.h>
#include <math.h>
#include <stdint.h>

#define S_IMGC 2048
#define S_TXTC 512
#define S_TOTC 2560
#define DC     1536
#define HC     24
#define DHC    64

__device__ float g_q[(size_t)HC * S_TOTC * DHC];
__device__ float g_k[(size_t)HC * S_TOTC * DHC];
__device__ float g_v[(size_t)HC * S_TOTC * DHC];
__device__ float g_ao[(size_t)S_TOTC * DC];

__device__ __forceinline__ void split_tf32(float x, uint32_t& hi, uint32_t& lo) {
    uint32_t h;
    asm("cvt.rna.tf32.f32 %0, %1;" : "=r"(h) : "f"(x));
    float l = x - __uint_as_float(h);
    uint32_t lu;
    asm("cvt.rna.tf32.f32 %0, %1;" : "=r"(lu) : "f"(l));
    hi = h; lo = lu;
}

__device__ __forceinline__ void mma_tf32(float* c, const uint32_t* a, const uint32_t* b) {
    asm volatile(
        "mma.sync.aligned.m16n8k8.row.col.f32.tf32.tf32.f32 "
        "{%0,%1,%2,%3}, {%4,%5,%6,%7}, {%8,%9}, {%0,%1,%2,%3};"
        : "+f"(c[0]), "+f"(c[1]), "+f"(c[2]), "+f"(c[3])
        : "r"(a[0]), "r"(a[1]), "r"(a[2]), "r"(a[3]), "r"(b[0]), "r"(b[1]));
}

// ---------------------------------------------------------------------------
// TF32x3 GEMM: C[M x 1536] = X * Wz^T + bz, Wz selected by blockIdx.z.
// Block 128x128, BK=16, 512 threads (16 warps), warp tile 32x32.
// Double-buffered smem (f32, split on fragment load), 1 sync/iter.
// mode 0: scatter head-major [h][s_off+m][d]; mode 1: row-major.
// ---------------------------------------------------------------------------
__global__ __launch_bounds__(512, 1) void gemm_tf32(
    const float* __restrict__ X,
    const float* __restrict__ W0, const float* __restrict__ W1, const float* __restrict__ W2,
    const float* __restrict__ b0, const float* __restrict__ b1, const float* __restrict__ b2,
    float* __restrict__ o0, float* __restrict__ o1, float* __restrict__ o2,
    int s_off, int mode)
{
    __shared__ float sA[2][128][20];
    __shared__ float sB[2][128][20];

    const int z = blockIdx.z;
    const float* W    = (z == 0) ? W0 : (z == 1) ? W1 : W2;
    const float* bias = (z == 0) ? b0 : (z == 1) ? b1 : b2;
    float* out        = (z == 0) ? o0 : (z == 1) ? o1 : o2;

    const int tid  = threadIdx.x;
    const int wid  = tid >> 5;
    const int lane = tid & 31;
    const int g    = lane >> 2;
    const int tig  = lane & 3;
    const int wm   = wid & 3;    // 4 warp rows
    const int wn   = wid >> 2;   // 4 warp cols

    const int ldr = tid >> 2;          // 0..127
    const int ldc = (tid & 3) << 2;    // 0,4,8,12

    const float* Xp = X + (size_t)(blockIdx.y * 128 + ldr) * DC + ldc;
    const float* Wp = W + (size_t)(blockIdx.x * 128 + ldr) * DC + ldc;

    float acc[2][4][4];
    #pragma unroll
    for (int i = 0; i < 2; ++i)
        #pragma unroll
        for (int j = 0; j < 4; ++j)
            #pragma unroll
            for (int r = 0; r < 4; ++r) acc[i][j][r] = 0.0f;

    float4 ra = *(const float4*)(Xp);
    float4 rb = *(const float4*)(Wp);
    int cur = 0;

    for (int kt = 0; kt < DC / 16; ++kt) {
        *(float4*)&sA[cur][ldr][ldc] = ra;
        *(float4*)&sB[cur][ldr][ldc] = rb;
        __syncthreads();
        if (kt + 1 < DC / 16) {
            ra = *(const float4*)(Xp + (kt + 1) * 16);
            rb = *(const float4*)(Wp + (kt + 1) * 16);
        }
        #pragma unroll
        for (int kk = 0; kk < 16; kk += 8) {
            uint32_t ah[2][4], al[2][4];
            #pragma unroll
            for (int mi = 0; mi < 2; ++mi) {
                const int r = wm * 32 + mi * 16 + g;
                split_tf32(sA[cur][r][kk + tig],     ah[mi][0], al[mi][0]);
                split_tf32(sA[cur][r + 8][kk + tig], ah[mi][1], al[mi][1]);
                split_tf32(sA[cur][r][kk + tig + 4],     ah[mi][2], al[mi][2]);
                split_tf32(sA[cur][r + 8][kk + tig + 4], ah[mi][3], al[mi][3]);
            }
            #pragma unroll
            for (int ni = 0; ni < 4; ++ni) {
                const int cn = wn * 32 + ni * 8 + g;
                uint32_t bh[2], bl[2];
                split_tf32(sB[cur][cn][kk + tig],     bh[0], bl[0]);
                split_tf32(sB[cur][cn][kk + tig + 4], bh[1], bl[1]);
                #pragma unroll
                for (int mi = 0; mi < 2; ++mi) {
                    mma_tf32(acc[mi][ni], ah[mi], bh);
                    mma_tf32(acc[mi][ni], ah[mi], bl);
                    mma_tf32(acc[mi][ni], al[mi], bh);
                }
            }
        }
        cur ^= 1;
    }

    #pragma unroll
    for (int mi = 0; mi < 2; ++mi) {
        #pragma unroll
        for (int ni = 0; ni < 4; ++ni) {
            const int row0 = blockIdx.y * 128 + wm * 32 + mi * 16 + g;
            const int col0 = blockIdx.x * 128 + wn * 32 + ni * 8 + 2 * tig;
            const float bx = bias[col0], by = bias[col0 + 1];
            float2 v0 = {acc[mi][ni][0] + bx, acc[mi][ni][1] + by};
            float2 v1 = {acc[mi][ni][2] + bx, acc[mi][ni][3] + by};
            if (mode == 0) {
                const int h = col0 >> 6, d = col0 & 63;
                *(float2*)(out + ((size_t)h * S_TOTC + (s_off + row0)) * DHC + d) = v0;
                *(float2*)(out + ((size_t)h * S_TOTC + (s_off + row0 + 8)) * DHC + d) = v1;
            } else {
                *(float2*)(out + (size_t)row0 * DC + col0) = v0;
                *(float2*)(out + (size_t)(row0 + 8) * DC + col0) = v1;
            }
        }
    }
}

// ---------------------------------------------------------------------------
// RMS-norm + RoPE (in place).
// ---------------------------------------------------------------------------
__global__ __launch_bounds__(32) void rmsrope(
    float* __restrict__ buf,
    const float* __restrict__ cosb, const float* __restrict__ sinb,
    const float* __restrict__ gtxt, const float* __restrict__ gimg)
{
    const int s = blockIdx.x, h = blockIdx.y, t = threadIdx.x;
    float* p = buf + ((size_t)h * S_TOTC + s) * DHC;
    float x0 = p[2 * t], x1 = p[2 * t + 1];
    float ss = x0 * x0 + x1 * x1;
    #pragma unroll
    for (int o = 16; o; o >>= 1) ss += __shfl_xor_sync(0xffffffffu, ss, o);
    const float r = rsqrtf(ss * (1.0f / 64.0f) + 1e-6f);
    const float* g = (s < S_TXTC) ? gtxt : gimg;
    const float y0 = x0 * r * g[2 * t];
    const float y1 = x1 * r * g[2 * t + 1];
    const float c  = cosb[s * 64 + 2 * t];
    const float sn = sinb[s * 64 + 2 * t];
    p[2 * t]     = y0 * c - y1 * sn;
    p[2 * t + 1] = y1 * c + y0 * sn;
}

// ---------------------------------------------------------------------------
// Tensor-core flash attention (TF32x3 for QK^T and PV).
// 1 block = (64-query tile, head). 128 threads = 4 warps; each warp owns 16
// full query rows (softmax reductions are quad-shuffles only).
// ---------------------------------------------------------------------------
__global__ __launch_bounds__(128) void attn_mma()
{
    extern __shared__ float sm[];
    float (*sQ)[68]  = (float(*)[68])(sm);
    float (*sK)[68]  = (float(*)[68])(sm + 64 * 68);
    float (*sVt)[68] = (float(*)[68])(sm + 2 * 64 * 68);
    float (*sP)[68]  = (float(*)[68])(sm + 3 * 64 * 68);

    const int h = blockIdx.y, qt = blockIdx.x;
    const int tid = threadIdx.x;
    const int w = tid >> 5, lane = tid & 31, g = lane >> 2, tig = lane & 3;
    const int r0 = w * 16 + g, r1 = r0 + 8;

    // Stage Q (pre-scaled)
    const float* qbase = g_q + ((size_t)h * S_TOTC + qt * 64) * DHC;
    for (int idx = tid; idx < 1024; idx += 128) {
        const int row = idx >> 4, col = (idx & 15) << 2;
        float4 v = *(const float4*)(qbase + row * 64 + col);
        v.x *= 0.125f; v.y *= 0.125f; v.z *= 0.125f; v.w *= 0.125f;
        *(float4*)&sQ[row][col] = v;
    }

    float oacc[8][4];
    #pragma unroll
    for (int ni = 0; ni < 8; ++ni)
        #pragma unroll
        for (int r = 0; r < 4; ++r) oacc[ni][r] = 0.0f;
    float m0 = -1e30f, m1 = -1e30f, l0 = 0.0f, l1 = 0.0f;

    const float* kbase = g_k + (size_t)h * S_TOTC * DHC;
    const float* vbase = g_v + (size_t)h * S_TOTC * DHC;

    for (int kt = 0; kt < S_TOTC / 64; ++kt) {
        __syncthreads();
        for (int idx = tid; idx < 1024; idx += 128) {
            const int row = idx >> 4, col = (idx & 15) << 2;
            *(float4*)&sK[row][col] = *(const float4*)(kbase + (size_t)(kt * 64 + row) * 64 + col);
            const float4 v = *(const float4*)(vbase + (size_t)(kt * 64 + row) * 64 + col);
            sVt[col + 0][row] = v.x; sVt[col + 1][row] = v.y;
            sVt[col + 2][row] = v.z; sVt[col + 3][row] = v.w;
        }
        __syncthreads();

        // S = Q K^T (warp: rows r0/r1 family x all 64 key cols)
        float sfrag[8][4];
        #pragma unroll
        for (int ni = 0; ni < 8; ++ni)
            #pragma unroll
            for (int r = 0; r < 4; ++r) sfrag[ni][r] = 0.0f;

        #pragma unroll
        for (int kk = 0; kk < 64; kk += 8) {
            uint32_t ah[4], al[4];
            split_tf32(sQ[r0][kk + tig],     ah[0], al[0]);
            split_tf32(sQ[r1][kk + tig],     ah[1], al[1]);
            split_tf32(sQ[r0][kk + tig + 4], ah[2], al[2]);
            split_tf32(sQ[r1][kk + tig + 4], ah[3], al[3]);
            #pragma unroll
            for (int ni = 0; ni < 8; ++ni) {
                uint32_t bh[2], bl[2];
                split_tf32(sK[ni * 8 + g][kk + tig],     bh[0], bl[0]);
                split_tf32(sK[ni * 8 + g][kk + tig + 4], bh[1], bl[1]);
                mma_tf32(sfrag[ni], ah, bh);
                mma_tf32(sfrag[ni], ah, bl);
                mma_tf32(sfrag[ni], al, bh);
            }
        }

        // Online softmax (rows r0, r1)
        float mx0 = m0, mx1 = m1;
        #pragma unroll
        for (int ni = 0; ni < 8; ++ni) {
            mx0 = fmaxf(mx0, fmaxf(sfrag[ni][0], sfrag[ni][1]));
            mx1 = fmaxf(mx1, fmaxf(sfrag[ni][2], sfrag[ni][3]));
        }
        mx0 = fmaxf(mx0, __shfl_xor_sync(0xffffffffu, mx0, 1));
        mx0 = fmaxf(mx0, __shfl_xor_sync(0xffffffffu, mx0, 2));
        mx1 = fmaxf(mx1, __shfl_xor_sync(0xffffffffu, mx1, 1));
        mx1 = fmaxf(mx1, __shfl_xor_sync(0xffffffffu, mx1, 2));
        const float corr0 = __expf(m0 - mx0);
        const float corr1 = __expf(m1 - mx1);
        m0 = mx0; m1 = mx1;

        float sum0 = 0.0f, sum1 = 0.0f;
        #pragma unroll
        for (int ni = 0; ni < 8; ++ni) {
            const float p00 = __expf(sfrag[ni][0] - m0);
            const float p01 = __expf(sfrag[ni][1] - m0);
            const float p10 = __expf(sfrag[ni][2] - m1);
            const float p11 = __expf(sfrag[ni][3] - m1);
            sum0 += p00 + p01; sum1 += p10 + p11;
            *(float2*)&sP[r0][ni * 8 + 2 * tig] = make_float2(p00, p01);
            *(float2*)&sP[r1][ni * 8 + 2 * tig] = make_float2(p10, p11);
            oacc[ni][0] *= corr0; oacc[ni][1] *= corr0;
            oacc[ni][2] *= corr1; oacc[ni][3] *= corr1;
        }
        sum0 += __shfl_xor_sync(0xffffffffu, sum0, 1);
        sum0 += __shfl_xor_sync(0xffffffffu, sum0, 2);
        sum1 += __shfl_xor_sync(0xffffffffu, sum1, 1);
        sum1 += __shfl_xor_sync(0xffffffffu, sum1, 2);
        l0 = l0 * corr0 + sum0;
        l1 = l1 * corr1 + sum1;
        __syncwarp();

        // O += P * V  (A = P rows from own-warp smem slab, B = Vt)
        #pragma unroll
        for (int kk = 0; kk < 64; kk += 8) {
            uint32_t ah[4], al[4];
            split_tf32(sP[r0][kk + tig],     ah[0], al[0]);
            split_tf32(sP[r1][kk + tig],     ah[1], al[1]);
            split_tf32(sP[r0][kk + tig + 4], ah[2], al[2]);
            split_tf32(sP[r1][kk + tig + 4], ah[3], al[3]);
            #pragma unroll
            for (int ni = 0; ni < 8; ++ni) {
                uint32_t bh[2], bl[2];
                split_tf32(sVt[ni * 8 + g][kk + tig],     bh[0], bl[0]);
                split_tf32(sVt[ni * 8 + g][kk + tig + 4], bh[1], bl[1]);
                mma_tf32(oacc[ni], ah, bh);
                mma_tf32(oacc[ni], ah, bl);
                mma_tf32(oacc[ni], al, bh);
            }
        }
    }

    const float inv0 = 1.0f / l0, inv1 = 1.0f / l1;
    float* obase = g_ao + (size_t)(qt * 64) * DC + h * DHC;
    #pragma unroll
    for (int ni = 0; ni < 8; ++ni) {
        const int c = ni * 8 + 2 * tig;
        *(float2*)(obase + (size_t)r0 * DC + c) = make_float2(oacc[ni][0] * inv0, oacc[ni][1] * inv0);
        *(float2*)(obase + (size_t)r1 * DC + c) = make_float2(oacc[ni][2] * inv1, oacc[ni][3] * inv1);
    }
}

// ---------------------------------------------------------------------------
extern "C" void kernel_launch(void* const* d_in, const int* in_sizes, int n_in,
                              void* d_out, int out_size)
{
    (void)in_sizes; (void)n_in; (void)out_size;
    const float* hs  = (const float*)d_in[0];
    const float* ehs = (const float*)d_in[1];
    const float* rc  = (const float*)d_in[2];
    const float* rs  = (const float*)d_in[3];
    const float* Wq  = (const float*)d_in[4];  const float* bq  = (const float*)d_in[5];
    const float* Wk  = (const float*)d_in[6];  const float* bk  = (const float*)d_in[7];
    const float* Wv  = (const float*)d_in[8];  const float* bv  = (const float*)d_in[9];
    const float* Waq = (const float*)d_in[10]; const float* baq = (const float*)d_in[11];
    const float* Wak = (const float*)d_in[12]; const float* bak = (const float*)d_in[13];
    const float* Wav = (const float*)d_in[14]; const float* bav = (const float*)d_in[15];
    const float* Wo  = (const float*)d_in[16]; const float* bo  = (const float*)d_in[17];
    const float* Wao = (const float*)d_in[18]; const float* bao = (const float*)d_in[19];
    const float* gq  = (const float*)d_in[20]; const float* gk  = (const float*)d_in[21];
    const float* gaq = (const float*)d_in[22]; const float* gak = (const float*)d_in[23];
    float* out = (float*)d_out;

    float *qb, *kb, *vb, *aob;
    cudaGetSymbolAddress((void**)&qb,  g_q);
    cudaGetSymbolAddress((void**)&kb,  g_k);
    cudaGetSymbolAddress((void**)&vb,  g_v);
    cudaGetSymbolAddress((void**)&aob, g_ao);

    static int smem_set = 0;
    const int attn_smem = 4 * 64 * 68 * (int)sizeof(float);
    if (!smem_set) {
        cudaFuncSetAttribute(attn_mma, cudaFuncAttributeMaxDynamicSharedMemorySize, attn_smem);
        smem_set = 1;
    }

    const dim3 blk(512);
    // QKV projections: one launch per segment, z selects Q/K/V weight set
    gemm_tf32<<<dim3(12, 16, 3), blk>>>(hs,  Wq, Wk, Wv, bq, bk, bv, qb, kb, vb, 512, 0);
    gemm_tf32<<<dim3(12, 4, 3),  blk>>>(ehs, Waq, Wak, Wav, baq, bak, bav, qb, kb, vb, 0, 0);

    const dim3 rr_grid(S_TOTC, HC);
    rmsrope<<<rr_grid, 32>>>(qb, rc, rs, gaq, gq);
    rmsrope<<<rr_grid, 32>>>(kb, rc, rs, gak, gk);

    attn_mma<<<dim3(S_TOTC / 64, HC), 128, attn_smem>>>();

    gemm_tf32<<<dim3(12, 16, 1), blk>>>(aob + (size_t)512 * DC, Wo, Wo, Wo, bo, bo, bo,
                                        out, out, out, 0, 1);
    gemm_tf32<<<dim3(12, 4, 1),  blk>>>(aob, Wao, Wao, Wao, bao, bao, bao,
                                        out + (size_t)S_IMGC * DC, out + (size_t)S_IMGC * DC,
                                        out + (size_t)S_IMGC * DC, 0, 1);
}

// round 4
// speedup vs baseline: 2.6639x; 1.5008x over previous
#include <cuda_runtime.h>
#include <math.h>
#include <stdint.h>

#define S_IMGC 2048
#define S_TXTC 512
#define S_TOTC 2560
#define DC     1536
#define HC     24
#define DHC    64

__device__ float g_q[(size_t)HC * S_TOTC * DHC];
__device__ float g_k[(size_t)HC * S_TOTC * DHC];
__device__ float g_v[(size_t)HC * S_TOTC * DHC];
__device__ float g_ao[(size_t)S_TOTC * DC];

__device__ __forceinline__ uint32_t cvt_tf32(float x) {
    uint32_t r;
    asm("cvt.rna.tf32.f32 %0, %1;" : "=r"(r) : "f"(x));
    return r;
}

__device__ __forceinline__ void split_tf32(float x, uint32_t& hi, uint32_t& lo) {
    uint32_t h;
    asm("cvt.rna.tf32.f32 %0, %1;" : "=r"(h) : "f"(x));
    float l = x - __uint_as_float(h);
    uint32_t lu;
    asm("cvt.rna.tf32.f32 %0, %1;" : "=r"(lu) : "f"(l));
    hi = h; lo = lu;
}

__device__ __forceinline__ void mma_tf32(float* c, const uint32_t* a, const uint32_t* b) {
    asm volatile(
        "mma.sync.aligned.m16n8k8.row.col.f32.tf32.tf32.f32 "
        "{%0,%1,%2,%3}, {%4,%5,%6,%7}, {%8,%9}, {%0,%1,%2,%3};"
        : "+f"(c[0]), "+f"(c[1]), "+f"(c[2]), "+f"(c[3])
        : "r"(a[0]), "r"(a[1]), "r"(a[2]), "r"(a[3]), "r"(b[0]), "r"(b[1]));
}

// ---------------------------------------------------------------------------
// TF32x3 GEMM (projections; full fp32-class accuracy retained).
// Block 128x128, BK=16, 512 threads, warp tile 32x32, double-buffered smem.
// ---------------------------------------------------------------------------
__global__ __launch_bounds__(512, 1) void gemm_tf32(
    const float* __restrict__ X,
    const float* __restrict__ W0, const float* __restrict__ W1, const float* __restrict__ W2,
    const float* __restrict__ b0, const float* __restrict__ b1, const float* __restrict__ b2,
    float* __restrict__ o0, float* __restrict__ o1, float* __restrict__ o2,
    int s_off, int mode)
{
    __shared__ float sA[2][128][20];
    __shared__ float sB[2][128][20];

    const int z = blockIdx.z;
    const float* W    = (z == 0) ? W0 : (z == 1) ? W1 : W2;
    const float* bias = (z == 0) ? b0 : (z == 1) ? b1 : b2;
    float* out        = (z == 0) ? o0 : (z == 1) ? o1 : o2;

    const int tid  = threadIdx.x;
    const int wid  = tid >> 5;
    const int lane = tid & 31;
    const int g    = lane >> 2;
    const int tig  = lane & 3;
    const int wm   = wid & 3;
    const int wn   = wid >> 2;

    const int ldr = tid >> 2;
    const int ldc = (tid & 3) << 2;

    const float* Xp = X + (size_t)(blockIdx.y * 128 + ldr) * DC + ldc;
    const float* Wp = W + (size_t)(blockIdx.x * 128 + ldr) * DC + ldc;

    float acc[2][4][4];
    #pragma unroll
    for (int i = 0; i < 2; ++i)
        #pragma unroll
        for (int j = 0; j < 4; ++j)
            #pragma unroll
            for (int r = 0; r < 4; ++r) acc[i][j][r] = 0.0f;

    float4 ra = *(const float4*)(Xp);
    float4 rb = *(const float4*)(Wp);
    int cur = 0;

    for (int kt = 0; kt < DC / 16; ++kt) {
        *(float4*)&sA[cur][ldr][ldc] = ra;
        *(float4*)&sB[cur][ldr][ldc] = rb;
        __syncthreads();
        if (kt + 1 < DC / 16) {
            ra = *(const float4*)(Xp + (kt + 1) * 16);
            rb = *(const float4*)(Wp + (kt + 1) * 16);
        }
        #pragma unroll
        for (int kk = 0; kk < 16; kk += 8) {
            uint32_t ah[2][4], al[2][4];
            #pragma unroll
            for (int mi = 0; mi < 2; ++mi) {
                const int r = wm * 32 + mi * 16 + g;
                split_tf32(sA[cur][r][kk + tig],     ah[mi][0], al[mi][0]);
                split_tf32(sA[cur][r + 8][kk + tig], ah[mi][1], al[mi][1]);
                split_tf32(sA[cur][r][kk + tig + 4],     ah[mi][2], al[mi][2]);
                split_tf32(sA[cur][r + 8][kk + tig + 4], ah[mi][3], al[mi][3]);
            }
            #pragma unroll
            for (int ni = 0; ni < 4; ++ni) {
                const int cn = wn * 32 + ni * 8 + g;
                uint32_t bh[2], bl[2];
                split_tf32(sB[cur][cn][kk + tig],     bh[0], bl[0]);
                split_tf32(sB[cur][cn][kk + tig + 4], bh[1], bl[1]);
                #pragma unroll
                for (int mi = 0; mi < 2; ++mi) {
                    mma_tf32(acc[mi][ni], ah[mi], bh);
                    mma_tf32(acc[mi][ni], ah[mi], bl);
                    mma_tf32(acc[mi][ni], al[mi], bh);
                }
            }
        }
        cur ^= 1;
    }

    #pragma unroll
    for (int mi = 0; mi < 2; ++mi) {
        #pragma unroll
        for (int ni = 0; ni < 4; ++ni) {
            const int row0 = blockIdx.y * 128 + wm * 32 + mi * 16 + g;
            const int col0 = blockIdx.x * 128 + wn * 32 + ni * 8 + 2 * tig;
            const float bx = bias[col0], by = bias[col0 + 1];
            float2 v0 = {acc[mi][ni][0] + bx, acc[mi][ni][1] + by};
            float2 v1 = {acc[mi][ni][2] + bx, acc[mi][ni][3] + by};
            if (mode == 0) {
                const int h = col0 >> 6, d = col0 & 63;
                *(float2*)(out + ((size_t)h * S_TOTC + (s_off + row0)) * DHC + d) = v0;
                *(float2*)(out + ((size_t)h * S_TOTC + (s_off + row0 + 8)) * DHC + d) = v1;
            } else {
                *(float2*)(out + (size_t)row0 * DC + col0) = v0;
                *(float2*)(out + (size_t)(row0 + 8) * DC + col0) = v1;
            }
        }
    }
}

// ---------------------------------------------------------------------------
// RMS-norm + RoPE on q (z=0) and k (z=1). 256 threads = 8 rows per block.
// ---------------------------------------------------------------------------
__global__ __launch_bounds__(256) void rmsrope2(
    float* __restrict__ qbuf, float* __restrict__ kbuf,
    const float* __restrict__ cosb, const float* __restrict__ sinb,
    const float* __restrict__ gaq, const float* __restrict__ gq,
    const float* __restrict__ gak, const float* __restrict__ gk)
{
    const int z = blockIdx.z;
    float* buf = z ? kbuf : qbuf;
    const int s = blockIdx.x * 8 + (threadIdx.x >> 5);
    const int h = blockIdx.y;
    const int t = threadIdx.x & 31;

    float* p = buf + ((size_t)h * S_TOTC + s) * DHC;
    float2 x = *(float2*)(p + 2 * t);
    float ss = x.x * x.x + x.y * x.y;
    #pragma unroll
    for (int o = 16; o; o >>= 1) ss += __shfl_xor_sync(0xffffffffu, ss, o);
    const float r = rsqrtf(ss * (1.0f / 64.0f) + 1e-6f);
    const float* g = z ? ((s < S_TXTC) ? gak : gk) : ((s < S_TXTC) ? gaq : gq);
    const float y0 = x.x * r * g[2 * t];
    const float y1 = x.y * r * g[2 * t + 1];
    const float c  = cosb[s * 64 + 2 * t];
    const float sn = sinb[s * 64 + 2 * t];
    *(float2*)(p + 2 * t) = make_float2(y0 * c - y1 * sn, y1 * c + y0 * sn);
}

// ---------------------------------------------------------------------------
// Tensor-core flash attention, single-pass TF32.
// 1 block = (128-query tile, head), 128 threads = 4 warps.
// Each warp owns 32 query rows (two 16-row MMA fragments) x all 64 keys.
// K and V both stored row-major [key][d]; V serves as PV's col-major B directly.
// ---------------------------------------------------------------------------
__global__ __launch_bounds__(128) void attn_mma()
{
    extern __shared__ float sm[];
    float (*sQ)[68] = (float(*)[68])(sm);               // 128 rows
    float (*sK)[68] = (float(*)[68])(sm + 128 * 68);    // 64 rows
    float (*sV)[68] = (float(*)[68])(sm + 192 * 68);    // 64 rows
    float (*sP)[68] = (float(*)[68])(sm + 256 * 68);    // 128 rows

    const int h = blockIdx.y, qt = blockIdx.x;
    const int tid = threadIdx.x;
    const int w = tid >> 5, lane = tid & 31, g = lane >> 2, tig = lane & 3;
    const int wr = w * 32;

    // Stage Q (pre-scaled by DH^-0.5)
    const float* qbase = g_q + ((size_t)h * S_TOTC + qt * 128) * DHC;
    for (int idx = tid; idx < 2048; idx += 128) {
        const int row = idx >> 4, col = (idx & 15) << 2;
        float4 v = *(const float4*)(qbase + row * 64 + col);
        v.x *= 0.125f; v.y *= 0.125f; v.z *= 0.125f; v.w *= 0.125f;
        *(float4*)&sQ[row][col] = v;
    }

    float oacc[2][8][4];
    #pragma unroll
    for (int mi = 0; mi < 2; ++mi)
        #pragma unroll
        for (int ni = 0; ni < 8; ++ni)
            #pragma unroll
            for (int r = 0; r < 4; ++r) oacc[mi][ni][r] = 0.0f;
    float mrow[4] = {-1e30f, -1e30f, -1e30f, -1e30f};
    float lrow[4] = {0.0f, 0.0f, 0.0f, 0.0f};

    const float* kbase = g_k + (size_t)h * S_TOTC * DHC;
    const float* vbase = g_v + (size_t)h * S_TOTC * DHC;

    for (int kt = 0; kt < S_TOTC / 64; ++kt) {
        __syncthreads();
        for (int idx = tid; idx < 1024; idx += 128) {
            const int row = idx >> 4, col = (idx & 15) << 2;
            *(float4*)&sK[row][col] = *(const float4*)(kbase + (size_t)(kt * 64 + row) * 64 + col);
            *(float4*)&sV[row][col] = *(const float4*)(vbase + (size_t)(kt * 64 + row) * 64 + col);
        }
        __syncthreads();

        // S = Q K^T
        float sfrag[2][8][4];
        #pragma unroll
        for (int mi = 0; mi < 2; ++mi)
            #pragma unroll
            for (int ni = 0; ni < 8; ++ni)
                #pragma unroll
                for (int r = 0; r < 4; ++r) sfrag[mi][ni][r] = 0.0f;

        #pragma unroll
        for (int kk = 0; kk < 64; kk += 8) {
            uint32_t a[2][4];
            #pragma unroll
            for (int mi = 0; mi < 2; ++mi) {
                const int r = wr + mi * 16 + g;
                a[mi][0] = cvt_tf32(sQ[r][kk + tig]);
                a[mi][1] = cvt_tf32(sQ[r + 8][kk + tig]);
                a[mi][2] = cvt_tf32(sQ[r][kk + tig + 4]);
                a[mi][3] = cvt_tf32(sQ[r + 8][kk + tig + 4]);
            }
            #pragma unroll
            for (int ni = 0; ni < 8; ++ni) {
                uint32_t b[2];
                b[0] = cvt_tf32(sK[ni * 8 + g][kk + tig]);
                b[1] = cvt_tf32(sK[ni * 8 + g][kk + tig + 4]);
                mma_tf32(sfrag[0][ni], a[0], b);
                mma_tf32(sfrag[1][ni], a[1], b);
            }
        }

        // Online softmax: 4 row families per thread
        #pragma unroll
        for (int f = 0; f < 4; ++f) {
            const int mi = f >> 1, cb = (f & 1) << 1;
            float mx = mrow[f];
            #pragma unroll
            for (int ni = 0; ni < 8; ++ni)
                mx = fmaxf(mx, fmaxf(sfrag[mi][ni][cb], sfrag[mi][ni][cb + 1]));
            mx = fmaxf(mx, __shfl_xor_sync(0xffffffffu, mx, 1));
            mx = fmaxf(mx, __shfl_xor_sync(0xffffffffu, mx, 2));
            const float corr = __expf(mrow[f] - mx);
            mrow[f] = mx;
            float sum = 0.0f;
            const int prow = wr + mi * 16 + ((f & 1) << 3) + g;
            #pragma unroll
            for (int ni = 0; ni < 8; ++ni) {
                const float p0 = __expf(sfrag[mi][ni][cb]     - mx);
                const float p1 = __expf(sfrag[mi][ni][cb + 1] - mx);
                sum += p0 + p1;
                *(float2*)&sP[prow][ni * 8 + 2 * tig] = make_float2(p0, p1);
                oacc[mi][ni][cb]     *= corr;
                oacc[mi][ni][cb + 1] *= corr;
            }
            sum += __shfl_xor_sync(0xffffffffu, sum, 1);
            sum += __shfl_xor_sync(0xffffffffu, sum, 2);
            lrow[f] = lrow[f] * corr + sum;
        }
        __syncwarp();

        // O += P V (B read directly from row-major sV as col-major fragment)
        #pragma unroll
        for (int kk = 0; kk < 64; kk += 8) {
            uint32_t a[2][4];
            #pragma unroll
            for (int mi = 0; mi < 2; ++mi) {
                const int r = wr + mi * 16 + g;
                a[mi][0] = cvt_tf32(sP[r][kk + tig]);
                a[mi][1] = cvt_tf32(sP[r + 8][kk + tig]);
                a[mi][2] = cvt_tf32(sP[r][kk + tig + 4]);
                a[mi][3] = cvt_tf32(sP[r + 8][kk + tig + 4]);
            }
            #pragma unroll
            for (int ni = 0; ni < 8; ++ni) {
                uint32_t b[2];
                b[0] = cvt_tf32(sV[kk + tig][ni * 8 + g]);
                b[1] = cvt_tf32(sV[kk + tig + 4][ni * 8 + g]);
                mma_tf32(oacc[0][ni], a[0], b);
                mma_tf32(oacc[1][ni], a[1], b);
            }
        }
    }

    const float inv[4] = {1.0f / lrow[0], 1.0f / lrow[1], 1.0f / lrow[2], 1.0f / lrow[3]};
    float* obase = g_ao + (size_t)(qt * 128) * DC + h * DHC;
    #pragma unroll
    for (int mi = 0; mi < 2; ++mi) {
        const int r0 = wr + mi * 16 + g;
        const float i0 = inv[mi * 2], i1 = inv[mi * 2 + 1];
        #pragma unroll
        for (int ni = 0; ni < 8; ++ni) {
            const int c = ni * 8 + 2 * tig;
            *(float2*)(obase + (size_t)r0 * DC + c) =
                make_float2(oacc[mi][ni][0] * i0, oacc[mi][ni][1] * i0);
            *(float2*)(obase + (size_t)(r0 + 8) * DC + c) =
                make_float2(oacc[mi][ni][2] * i1, oacc[mi][ni][3] * i1);
        }
    }
}

// ---------------------------------------------------------------------------
extern "C" void kernel_launch(void* const* d_in, const int* in_sizes, int n_in,
                              void* d_out, int out_size)
{
    (void)in_sizes; (void)n_in; (void)out_size;
    const float* hs  = (const float*)d_in[0];
    const float* ehs = (const float*)d_in[1];
    const float* rc  = (const float*)d_in[2];
    const float* rs  = (const float*)d_in[3];
    const float* Wq  = (const float*)d_in[4];  const float* bq  = (const float*)d_in[5];
    const float* Wk  = (const float*)d_in[6];  const float* bk  = (const float*)d_in[7];
    const float* Wv  = (const float*)d_in[8];  const float* bv  = (const float*)d_in[9];
    const float* Waq = (const float*)d_in[10]; const float* baq = (const float*)d_in[11];
    const float* Wak = (const float*)d_in[12]; const float* bak = (const float*)d_in[13];
    const float* Wav = (const float*)d_in[14]; const float* bav = (const float*)d_in[15];
    const float* Wo  = (const float*)d_in[16]; const float* bo  = (const float*)d_in[17];
    const float* Wao = (const float*)d_in[18]; const float* bao = (const float*)d_in[19];
    const float* gq  = (const float*)d_in[20]; const float* gk  = (const float*)d_in[21];
    const float* gaq = (const float*)d_in[22]; const float* gak = (const float*)d_in[23];
    float* out = (float*)d_out;

    float *qb, *kb, *vb, *aob;
    cudaGetSymbolAddress((void**)&qb,  g_q);
    cudaGetSymbolAddress((void**)&kb,  g_k);
    cudaGetSymbolAddress((void**)&vb,  g_v);
    cudaGetSymbolAddress((void**)&aob, g_ao);

    const int attn_smem = 384 * 68 * (int)sizeof(float);  // 104448
    cudaFuncSetAttribute(attn_mma, cudaFuncAttributeMaxDynamicSharedMemorySize, attn_smem);

    const dim3 blk(512);
    gemm_tf32<<<dim3(12, 16, 3), blk>>>(hs,  Wq, Wk, Wv, bq, bk, bv, qb, kb, vb, 512, 0);
    gemm_tf32<<<dim3(12, 4, 3),  blk>>>(ehs, Waq, Wak, Wav, baq, bak, bav, qb, kb, vb, 0, 0);

    rmsrope2<<<dim3(S_TOTC / 8, HC, 2), 256>>>(qb, kb, rc, rs, gaq, gq, gak, gk);

    attn_mma<<<dim3(S_TOTC / 128, HC), 128, attn_smem>>>();

    gemm_tf32<<<dim3(12, 16, 1), blk>>>(aob + (size_t)512 * DC, Wo, Wo, Wo, bo, bo, bo,
                                        out, out, out, 0, 1);
    gemm_tf32<<<dim3(12, 4, 1),  blk>>>(aob, Wao, Wao, Wao, bao, bao, bao,
                                        out + (size_t)S_IMGC * DC, out + (size_t)S_IMGC * DC,
                                        out + (size_t)S_IMGC * DC, 0, 1);
}

// round 5
// speedup vs baseline: 3.5791x; 1.3436x over previous
#include <cuda_runtime.h>
#include <cuda_fp16.h>
#include <math.h>
#include <stdint.h>

#define S_IMGC 2048
#define S_TXTC 512
#define S_TOTC 2560
#define DC     1536
#define HC     24
#define DHC    64
#define WELEM  (DC * DC)

// ---------------- device scratch (allocation-free rule) ----------------
__device__ float  g_q [(size_t)HC * S_TOTC * DHC];
__device__ float  g_k [(size_t)HC * S_TOTC * DHC];
__device__ __half g_vh[(size_t)HC * DHC * S_TOTC];   // [h][d][s] transposed
__device__ __half g_vl[(size_t)HC * DHC * S_TOTC];   // unscaled residual
__device__ float  g_ao[(size_t)S_TOTC * DC];
__device__ __half g_xh[(size_t)S_TOTC * DC];         // rows 0..2047 img, 2048..2559 txt
__device__ __half g_xl[(size_t)S_TOTC * DC];         // residual * 2048
__device__ __half g_wh[(size_t)8 * WELEM];
__device__ __half g_wl[(size_t)8 * WELEM];           // residual * 2048
__device__ __half g_aoh[(size_t)S_TOTC * DC];
__device__ __half g_aol[(size_t)S_TOTC * DC];

__device__ __forceinline__ uint32_t packh2(float a, float b) {
    __half2 h = __floats2half2_rn(a, b);
    return *(uint32_t*)&h;
}

__device__ __forceinline__ void mma_f16(float* c, const uint32_t* a, const uint32_t* b) {
    asm volatile(
        "mma.sync.aligned.m16n8k16.row.col.f32.f16.f16.f32 "
        "{%0,%1,%2,%3}, {%4,%5,%6,%7}, {%8,%9}, {%0,%1,%2,%3};"
        : "+f"(c[0]), "+f"(c[1]), "+f"(c[2]), "+f"(c[3])
        : "r"(a[0]), "r"(a[1]), "r"(a[2]), "r"(a[3]), "r"(b[0]), "r"(b[1]));
}

// ---------------------------------------------------------------------------
// Elementwise fp32 -> (h, l*2048) fp16 split. grid.y selects job.
// ---------------------------------------------------------------------------
struct SplitJob  { const float* s; __half* h; __half* l; int n; };
struct SplitJobs { SplitJob j[10]; };

__global__ __launch_bounds__(256) void split_kernel(SplitJobs jobs) {
    const SplitJob J = jobs.j[blockIdx.y];
    const int i = (blockIdx.x * 256 + threadIdx.x) * 4;
    if (i >= J.n) return;
    const float4 v = *(const float4*)(J.s + i);
    const __half h0 = __float2half_rn(v.x), h1 = __float2half_rn(v.y);
    const __half h2 = __float2half_rn(v.z), h3 = __float2half_rn(v.w);
    uint2 hw, lw;
    hw.x = packh2(__half2float(h0), 0.f) & 0xffff;  // rebuilt below properly
    // pack h
    { __half2 p0 = __halves2half2(h0, h1), p1 = __halves2half2(h2, h3);
      hw.x = *(uint32_t*)&p0; hw.y = *(uint32_t*)&p1; }
    // residuals * 2048
    const float r0 = (v.x - __half2float(h0)) * 2048.f;
    const float r1 = (v.y - __half2float(h1)) * 2048.f;
    const float r2 = (v.z - __half2float(h2)) * 2048.f;
    const float r3 = (v.w - __half2float(h3)) * 2048.f;
    lw.x = packh2(r0, r1); lw.y = packh2(r2, r3);
    *(uint2*)(J.h + i) = hw;
    *(uint2*)(J.l + i) = lw;
}

// ---------------------------------------------------------------------------
// fp16x3 GEMM: C[M x 1536] = X * W^T + bias  (W = g_wh/g_wl matrix widx(z))
// Block 128(M) x 64(N), BK=16, 256 threads (8 warps), warp tile 32x32.
// mode 0: z0->g_q, z1->g_k (fp32 head-major [h][s_off+m][d]); z2 -> vh/vl [h][d][s].
// mode 1: fp32 row-major to outp.
// ---------------------------------------------------------------------------
__global__ __launch_bounds__(256, 2) void gemm_h3(
    const __half* __restrict__ Xh, const __half* __restrict__ Xl,
    int w0, int w1, int w2,
    const float* __restrict__ b0, const float* __restrict__ b1, const float* __restrict__ b2,
    float* __restrict__ outp, int s_off, int mode)
{
    __shared__ uint32_t sAh[2][128][12], sAl[2][128][12];
    __shared__ uint32_t sBh[2][64][12],  sBl[2][64][12];

    const int z = blockIdx.z;
    const int widx      = (z == 0) ? w0 : (z == 1) ? w1 : w2;
    const float* bias   = (z == 0) ? b0 : (z == 1) ? b1 : b2;

    const int tid = threadIdx.x, wid = tid >> 5, lane = tid & 31;
    const int g = lane >> 2, tig = lane & 3;
    const int wm = wid & 3, wn = wid >> 2;

    // loaders
    const int arow = tid >> 1, akoff = (tid & 1) * 8;        // A: 128 rows x 16 halfs
    const int brow = (tid & 127) >> 1, bkoff = (tid & 1) * 8;
    const bool bIsH = (tid < 128);

    const __half* Ah = Xh + (size_t)(blockIdx.y * 128 + arow) * DC + akoff;
    const __half* Al = Xl + (size_t)(blockIdx.y * 128 + arow) * DC + akoff;
    const __half* Bp = (bIsH ? g_wh : g_wl) + (size_t)widx * WELEM
                       + (size_t)(blockIdx.x * 64 + brow) * DC + bkoff;

    float accm[2][4][4] = {}, accc[2][4][4] = {};

    uint4 rah = *(const uint4*)(Ah);
    uint4 ral = *(const uint4*)(Al);
    uint4 rb  = *(const uint4*)(Bp);
    int cur = 0;

    for (int kt = 0; kt < DC / 16; ++kt) {
        *(uint4*)&sAh[cur][arow][akoff >> 1] = rah;
        *(uint4*)&sAl[cur][arow][akoff >> 1] = ral;
        if (bIsH) *(uint4*)&sBh[cur][brow][bkoff >> 1] = rb;
        else      *(uint4*)&sBl[cur][brow][bkoff >> 1] = rb;
        __syncthreads();
        if (kt + 1 < DC / 16) {
            rah = *(const uint4*)(Ah + (kt + 1) * 16);
            ral = *(const uint4*)(Al + (kt + 1) * 16);
            rb  = *(const uint4*)(Bp + (kt + 1) * 16);
        }

        uint32_t ah[2][4], al[2][4];
        #pragma unroll
        for (int mi = 0; mi < 2; ++mi) {
            const int r = wm * 32 + mi * 16 + g;
            ah[mi][0] = sAh[cur][r][tig];     ah[mi][1] = sAh[cur][r + 8][tig];
            ah[mi][2] = sAh[cur][r][tig + 4]; ah[mi][3] = sAh[cur][r + 8][tig + 4];
            al[mi][0] = sAl[cur][r][tig];     al[mi][1] = sAl[cur][r + 8][tig];
            al[mi][2] = sAl[cur][r][tig + 4]; al[mi][3] = sAl[cur][r + 8][tig + 4];
        }
        #pragma unroll
        for (int ni = 0; ni < 4; ++ni) {
            const int cn = wn * 32 + ni * 8 + g;
            uint32_t bh[2], bl[2];
            bh[0] = sBh[cur][cn][tig]; bh[1] = sBh[cur][cn][tig + 4];
            bl[0] = sBl[cur][cn][tig]; bl[1] = sBl[cur][cn][tig + 4];
            #pragma unroll
            for (int mi = 0; mi < 2; ++mi) {
                mma_f16(accm[mi][ni], ah[mi], bh);
                mma_f16(accc[mi][ni], ah[mi], bl);
                mma_f16(accc[mi][ni], al[mi], bh);
            }
        }
        cur ^= 1;
    }

    const float rescale = 1.0f / 2048.0f;
    #pragma unroll
    for (int mi = 0; mi < 2; ++mi) {
        #pragma unroll
        for (int ni = 0; ni < 4; ++ni) {
            const int row0 = blockIdx.y * 128 + wm * 32 + mi * 16 + g;
            const int col0 = blockIdx.x * 64 + wn * 32 + ni * 8 + 2 * tig;
            const float bx = bias[col0], by = bias[col0 + 1];
            const float v00 = accm[mi][ni][0] + accc[mi][ni][0] * rescale + bx;
            const float v01 = accm[mi][ni][1] + accc[mi][ni][1] * rescale + by;
            const float v10 = accm[mi][ni][2] + accc[mi][ni][2] * rescale + bx;
            const float v11 = accm[mi][ni][3] + accc[mi][ni][3] * rescale + by;
            if (mode == 0) {
                if (z < 2) {
                    float* dst = z ? g_k : g_q;
                    const int h = col0 >> 6, d = col0 & 63;
                    *(float2*)(dst + ((size_t)h * S_TOTC + (s_off + row0)) * DHC + d) =
                        make_float2(v00, v01);
                    *(float2*)(dst + ((size_t)h * S_TOTC + (s_off + row0 + 8)) * DHC + d) =
                        make_float2(v10, v11);
                } else {
                    // V: transposed half output [n=(h*64+d)][s], h + unscaled residual
                    const int s0 = s_off + row0;
                    #pragma unroll
                    for (int e = 0; e < 2; ++e) {
                        const float va = e ? v01 : v00;
                        const float vb = e ? v11 : v10;
                        const size_t base = (size_t)(col0 + e) * S_TOTC;
                        const __half ha = __float2half_rn(va);
                        const __half hb = __float2half_rn(vb);
                        g_vh[base + s0]     = ha;
                        g_vh[base + s0 + 8] = hb;
                        g_vl[base + s0]     = __float2half_rn(va - __half2float(ha));
                        g_vl[base + s0 + 8] = __float2half_rn(vb - __half2float(hb));
                    }
                }
            } else {
                *(float2*)(outp + (size_t)row0 * DC + col0) = make_float2(v00, v01);
                *(float2*)(outp + (size_t)(row0 + 8) * DC + col0) = make_float2(v10, v11);
            }
        }
    }
}

// ---------------------------------------------------------------------------
// RMS-norm + RoPE on q (z=0) and k (z=1), fp32 in place.
// ---------------------------------------------------------------------------
__global__ __launch_bounds__(256) void rmsrope2(
    const float* __restrict__ cosb, const float* __restrict__ sinb,
    const float* __restrict__ gaq, const float* __restrict__ gq,
    const float* __restrict__ gak, const float* __restrict__ gk)
{
    const int z = blockIdx.z;
    float* buf = z ? g_k : g_q;
    const int s = blockIdx.x * 8 + (threadIdx.x >> 5);
    const int h = blockIdx.y;
    const int t = threadIdx.x & 31;

    float* p = buf + ((size_t)h * S_TOTC + s) * DHC;
    float2 x = *(float2*)(p + 2 * t);
    float ss = x.x * x.x + x.y * x.y;
    #pragma unroll
    for (int o = 16; o; o >>= 1) ss += __shfl_xor_sync(0xffffffffu, ss, o);
    const float r = rsqrtf(ss * (1.0f / 64.0f) + 1e-6f);
    const float* gg = z ? ((s < S_TXTC) ? gak : gk) : ((s < S_TXTC) ? gaq : gq);
    const float y0 = x.x * r * gg[2 * t];
    const float y1 = x.y * r * gg[2 * t + 1];
    const float c  = cosb[s * 64 + 2 * t];
    const float sn = sinb[s * 64 + 2 * t];
    *(float2*)(p + 2 * t) = make_float2(y0 * c - y1 * sn, y1 * c + y0 * sn);
}

// ---------------------------------------------------------------------------
// fp16 flash attention with register-resident P.
// Block = (128 q, head), 128 thr = 4 warps, warp = 32 q rows.
// QK^T: fp16 single-pass (A=Q, B=K row-major-as-colmajor-KT).
// PV: O^T = V^T P^T. P^T B-fragments come straight from QK accumulators.
// V staged from pre-transposed g_vh/g_vl (h + residual, same fp32 accumulator).
// ---------------------------------------------------------------------------
__global__ __launch_bounds__(128) void attn_h()
{
    __shared__ uint32_t sQ[128][36];   // half2 words, row = q, 32 data + 4 pad
    __shared__ uint32_t sK[64][36];    // row = key
    __shared__ uint32_t sVh[64][36];   // row = d, cols = keys (transposed V)
    __shared__ uint32_t sVl[64][36];

    const int h = blockIdx.y, qt = blockIdx.x;
    const int tid = threadIdx.x;
    const int w = tid >> 5, lane = tid & 31, g = lane >> 2, tig = lane & 3;
    const int wr = w * 32;

    // Stage Q (scaled by DH^-0.5, cvt fp16)
    const float* qbase = g_q + ((size_t)h * S_TOTC + qt * 128) * DHC;
    for (int i = tid; i < 2048; i += 128) {
        const int row = i >> 4, c4 = i & 15;
        float4 v = *(const float4*)(qbase + row * 64 + c4 * 4);
        sQ[row][c4 * 2]     = packh2(v.x * 0.125f, v.y * 0.125f);
        sQ[row][c4 * 2 + 1] = packh2(v.z * 0.125f, v.w * 0.125f);
    }

    float oacc[4][4][4] = {};                   // [d-frag][q-block][4] = O^T
    float mrow[4] = {-1e30f, -1e30f, -1e30f, -1e30f};
    float lrow[4] = {0.f, 0.f, 0.f, 0.f};

    const float* kbase = g_k + (size_t)h * S_TOTC * DHC;
    const __half* vhb = g_vh + (size_t)h * DHC * S_TOTC;
    const __half* vlb = g_vl + (size_t)h * DHC * S_TOTC;

    for (int kt = 0; kt < S_TOTC / 64; ++kt) {
        __syncthreads();
        for (int i = tid; i < 1024; i += 128) {       // K: 64x64 floats -> fp16
            const int row = i >> 4, c4 = i & 15;
            float4 v = *(const float4*)(kbase + (size_t)(kt * 64 + row) * 64 + c4 * 4);
            sK[row][c4 * 2]     = packh2(v.x, v.y);
            sK[row][c4 * 2 + 1] = packh2(v.z, v.w);
        }
        for (int u = tid; u < 512; u += 128) {        // V halves: pure copy
            const int d = u >> 3, j = u & 7;
            const size_t off = (size_t)d * S_TOTC + kt * 64 + j * 8;
            *(uint4*)&sVh[d][j * 4] = *(const uint4*)(vhb + off);
            *(uint4*)&sVl[d][j * 4] = *(const uint4*)(vlb + off);
        }
        __syncthreads();

        // ---- S = Q K^T ----
        float sfrag[2][8][4] = {};
        #pragma unroll
        for (int kk2 = 0; kk2 < 32; kk2 += 8) {
            uint32_t a[2][4];
            #pragma unroll
            for (int mi = 0; mi < 2; ++mi) {
                const int r = wr + mi * 16 + g;
                a[mi][0] = sQ[r][kk2 + tig];     a[mi][1] = sQ[r + 8][kk2 + tig];
                a[mi][2] = sQ[r][kk2 + tig + 4]; a[mi][3] = sQ[r + 8][kk2 + tig + 4];
            }
            #pragma unroll
            for (int ni = 0; ni < 8; ++ni) {
                const int kr = ni * 8 + g;
                uint32_t b[2] = { sK[kr][kk2 + tig], sK[kr][kk2 + tig + 4] };
                mma_f16(sfrag[0][ni], a[0], b);
                mma_f16(sfrag[1][ni], a[1], b);
            }
        }

        // ---- online softmax; build register P fragments ----
        uint32_t ph[2][8][2];
        float corrv[4];
        #pragma unroll
        for (int f = 0; f < 4; ++f) {
            const int mi = f >> 1, cb = (f & 1) << 1;
            float mx = mrow[f];
            #pragma unroll
            for (int ni = 0; ni < 8; ++ni)
                mx = fmaxf(mx, fmaxf(sfrag[mi][ni][cb], sfrag[mi][ni][cb + 1]));
            mx = fmaxf(mx, __shfl_xor_sync(0xffffffffu, mx, 1));
            mx = fmaxf(mx, __shfl_xor_sync(0xffffffffu, mx, 2));
            corrv[f] = __expf(mrow[f] - mx);
            mrow[f] = mx;
            float sum = 0.f;
            #pragma unroll
            for (int ni = 0; ni < 8; ++ni) {
                const float p0 = __expf(sfrag[mi][ni][cb]     - mx);
                const float p1 = __expf(sfrag[mi][ni][cb + 1] - mx);
                sum += p0 + p1;
                ph[mi][ni][f & 1] = packh2(p0, p1);
            }
            sum += __shfl_xor_sync(0xffffffffu, sum, 1);
            sum += __shfl_xor_sync(0xffffffffu, sum, 2);
            lrow[f] = lrow[f] * corrv[f] + sum;
        }

        // rescale O^T: per q-block, columns 2tig / 2tig+1 need row-stats of q rows
        // 2tig / 2tig+1 (held quad-uniformly by lanes with g = that row).
        #pragma unroll
        for (int qb = 0; qb < 4; ++qb) {
            const float cA = __shfl_sync(0xffffffffu, corrv[qb], 8 * tig);
            const float cB = __shfl_sync(0xffffffffu, corrv[qb], 8 * tig + 4);
            #pragma unroll
            for (int md = 0; md < 4; ++md) {
                oacc[md][qb][0] *= cA; oacc[md][qb][1] *= cB;
                oacc[md][qb][2] *= cA; oacc[md][qb][3] *= cB;
            }
        }

        // ---- O^T += V^T P^T ----
        #pragma unroll
        for (int kk2 = 0; kk2 < 32; kk2 += 8) {
            const int ni0 = kk2 >> 2;    // key S-block pair (kk2/4)
            uint32_t av[4][4], avl[4][4];
            #pragma unroll
            for (int md = 0; md < 4; ++md) {
                const int r = md * 16 + g;
                av[md][0]  = sVh[r][kk2 + tig];     av[md][1]  = sVh[r + 8][kk2 + tig];
                av[md][2]  = sVh[r][kk2 + tig + 4]; av[md][3]  = sVh[r + 8][kk2 + tig + 4];
                avl[md][0] = sVl[r][kk2 + tig];     avl[md][1] = sVl[r + 8][kk2 + tig];
                avl[md][2] = sVl[r][kk2 + tig + 4]; avl[md][3] = sVl[r + 8][kk2 + tig + 4];
            }
            #pragma unroll
            for (int qb = 0; qb < 4; ++qb) {
                uint32_t b[2] = { ph[qb >> 1][ni0][qb & 1], ph[qb >> 1][ni0 + 1][qb & 1] };
                #pragma unroll
                for (int md = 0; md < 4; ++md) {
                    mma_f16(oacc[md][qb], av[md], b);
                    mma_f16(oacc[md][qb], avl[md], b);
                }
            }
        }
    }

    // ---- epilogue: O = (O^T)^T / l ----
    #pragma unroll
    for (int qb = 0; qb < 4; ++qb) {
        const float lA = __shfl_sync(0xffffffffu, lrow[qb], 8 * tig);
        const float lB = __shfl_sync(0xffffffffu, lrow[qb], 8 * tig + 4);
        const float iA = 1.0f / lA, iB = 1.0f / lB;
        const int q0 = qt * 128 + wr + qb * 8 + 2 * tig;
        #pragma unroll
        for (int md = 0; md < 4; ++md) {
            const int d0 = h * 64 + md * 16 + g;
            g_ao[(size_t)q0 * DC + d0]           = oacc[md][qb][0] * iA;
            g_ao[(size_t)(q0 + 1) * DC + d0]     = oacc[md][qb][1] * iB;
            g_ao[(size_t)q0 * DC + d0 + 8]       = oacc[md][qb][2] * iA;
            g_ao[(size_t)(q0 + 1) * DC + d0 + 8] = oacc[md][qb][3] * iB;
        }
    }
}

// ---------------------------------------------------------------------------
extern "C" void kernel_launch(void* const* d_in, const int* in_sizes, int n_in,
                              void* d_out, int out_size)
{
    (void)in_sizes; (void)n_in; (void)out_size;
    const float* hs  = (const float*)d_in[0];
    const float* ehs = (const float*)d_in[1];
    const float* rc  = (const float*)d_in[2];
    const float* rs  = (const float*)d_in[3];
    const float* bq  = (const float*)d_in[5];
    const float* bk  = (const float*)d_in[7];
    const float* bv  = (const float*)d_in[9];
    const float* baq = (const float*)d_in[11];
    const float* bak = (const float*)d_in[13];
    const float* bav = (const float*)d_in[15];
    const float* bo  = (const float*)d_in[17];
    const float* bao = (const float*)d_in[19];
    const float* gq  = (const float*)d_in[20];
    const float* gk  = (const float*)d_in[21];
    const float* gaq = (const float*)d_in[22];
    const float* gak = (const float*)d_in[23];
    float* out = (float*)d_out;

    __half *xh, *xl, *wh, *wl, *aoh, *aol;
    float *aob;
    cudaGetSymbolAddress((void**)&xh,  g_xh);
    cudaGetSymbolAddress((void**)&xl,  g_xl);
    cudaGetSymbolAddress((void**)&wh,  g_wh);
    cudaGetSymbolAddress((void**)&wl,  g_wl);
    cudaGetSymbolAddress((void**)&aoh, g_aoh);
    cudaGetSymbolAddress((void**)&aol, g_aol);
    cudaGetSymbolAddress((void**)&aob, g_ao);

    // ---- presplit inputs + weights ----
    SplitJobs jobs;
    jobs.j[0] = { hs,  xh,                    xl,                    S_IMGC * DC };
    jobs.j[1] = { ehs, xh + (size_t)S_IMGC * DC, xl + (size_t)S_IMGC * DC, S_TXTC * DC };
    const int wsrc[8] = {4, 6, 8, 10, 12, 14, 16, 18};  // Wq,Wk,Wv,Waq,Wak,Wav,Wo,Wao
    for (int i = 0; i < 8; ++i)
        jobs.j[2 + i] = { (const float*)d_in[wsrc[i]],
                          wh + (size_t)i * WELEM, wl + (size_t)i * WELEM, WELEM };
    {
        const int maxn = S_IMGC * DC;                    // largest job
        dim3 grid((maxn / 4 + 255) / 256, 10);
        split_kernel<<<grid, 256>>>(jobs);
    }

    // ---- QKV projections ----
    gemm_h3<<<dim3(DC / 64, S_IMGC / 128, 3), 256>>>(
        xh, xl, 0, 1, 2, bq, bk, bv, nullptr, 512, 0);
    gemm_h3<<<dim3(DC / 64, S_TXTC / 128, 3), 256>>>(
        xh + (size_t)S_IMGC * DC, xl + (size_t)S_IMGC * DC,
        3, 4, 5, baq, bak, bav, nullptr, 0, 0);

    // ---- RMS + RoPE ----
    rmsrope2<<<dim3(S_TOTC / 8, HC, 2), 256>>>(rc, rs, gaq, gq, gak, gk);

    // ---- attention ----
    attn_h<<<dim3(S_TOTC / 128, HC), 128>>>();

    // ---- split attention output ----
    {
        SplitJobs j2;
        j2.j[0] = { aob, aoh, aol, S_TOTC * DC };
        dim3 grid((S_TOTC * DC / 4 + 255) / 256, 1);
        split_kernel<<<grid, 256>>>(j2);
    }

    // ---- output projections ----
    gemm_h3<<<dim3(DC / 64, S_IMGC / 128, 1), 256>>>(
        aoh + (size_t)S_TXTC * DC, aol + (size_t)S_TXTC * DC,
        6, 6, 6, bo, bo, bo, out, 0, 1);
    gemm_h3<<<dim3(DC / 64, S_TXTC / 128, 1), 256>>>(
        aoh, aol, 7, 7, 7, bao, bao, bao, out + (size_t)S_IMGC * DC, 0, 1);
}

// round 7
// speedup vs baseline: 3.7587x; 1.0502x over previous
#include <cuda_runtime.h>
#include <cuda_fp16.h>
#include <math.h>
#include <stdint.h>

#define S_IMGC 2048
#define S_TXTC 512
#define S_TOTC 2560
#define DC     1536
#define HC     24
#define DHC    64
#define WELEM  (DC * DC)

// ---------------- device scratch (allocation-free rule) ----------------
__device__ float  g_q [(size_t)HC * S_TOTC * DHC];
__device__ float  g_k [(size_t)HC * S_TOTC * DHC];
__device__ __half g_qh[(size_t)HC * S_TOTC * DHC];   // fp16, pre-scaled by 0.125
__device__ __half g_kh[(size_t)HC * S_TOTC * DHC];
__device__ __half g_vh[(size_t)HC * DHC * S_TOTC];   // [h][d][s] transposed
__device__ __half g_vl[(size_t)HC * DHC * S_TOTC];   // residual
__device__ float  g_ao[(size_t)S_TOTC * DC];
__device__ __half g_xh[(size_t)S_TOTC * DC];
__device__ __half g_xl[(size_t)S_TOTC * DC];
__device__ __half g_wh[(size_t)8 * WELEM];
__device__ __half g_wl[(size_t)8 * WELEM];
__device__ __half g_aoh[(size_t)S_TOTC * DC];
__device__ __half g_aol[(size_t)S_TOTC * DC];

__device__ __forceinline__ uint32_t packh2(float a, float b) {
    __half2 h = __floats2half2_rn(a, b);
    return *(uint32_t*)&h;
}

__device__ __forceinline__ void mma_f16(float* c, const uint32_t* a, const uint32_t* b) {
    asm volatile(
        "mma.sync.aligned.m16n8k16.row.col.f32.f16.f16.f32 "
        "{%0,%1,%2,%3}, {%4,%5,%6,%7}, {%8,%9}, {%0,%1,%2,%3};"
        : "+f"(c[0]), "+f"(c[1]), "+f"(c[2]), "+f"(c[3])
        : "r"(a[0]), "r"(a[1]), "r"(a[2]), "r"(a[3]), "r"(b[0]), "r"(b[1]));
}

__device__ __forceinline__ void ldsm4(uint32_t* r, const void* p) {
    uint32_t a = (uint32_t)__cvta_generic_to_shared(p);
    asm volatile("ldmatrix.sync.aligned.m8n8.x4.shared.b16 {%0,%1,%2,%3}, [%4];"
        : "=r"(r[0]), "=r"(r[1]), "=r"(r[2]), "=r"(r[3]) : "r"(a));
}

// ---------------------------------------------------------------------------
// Elementwise fp32 -> (h, l*2048) fp16 split.
// ---------------------------------------------------------------------------
struct SplitJob  { const float* s; __half* h; __half* l; int n; };
struct SplitJobs { SplitJob j[10]; };

__global__ __launch_bounds__(256) void split_kernel(SplitJobs jobs) {
    const SplitJob J = jobs.j[blockIdx.y];
    const int i = (blockIdx.x * 256 + threadIdx.x) * 4;
    if (i >= J.n) return;
    const float4 v = *(const float4*)(J.s + i);
    const __half h0 = __float2half_rn(v.x), h1 = __float2half_rn(v.y);
    const __half h2 = __float2half_rn(v.z), h3 = __float2half_rn(v.w);
    uint2 hw, lw;
    { __half2 p0 = __halves2half2(h0, h1), p1 = __halves2half2(h2, h3);
      hw.x = *(uint32_t*)&p0; hw.y = *(uint32_t*)&p1; }
    const float r0 = (v.x - __half2float(h0)) * 2048.f;
    const float r1 = (v.y - __half2float(h1)) * 2048.f;
    const float r2 = (v.z - __half2float(h2)) * 2048.f;
    const float r3 = (v.w - __half2float(h3)) * 2048.f;
    lw.x = packh2(r0, r1); lw.y = packh2(r2, r3);
    *(uint2*)(J.h + i) = hw;
    *(uint2*)(J.l + i) = lw;
}

// ---------------------------------------------------------------------------
// fp16x3 GEMM with ldmatrix fragment loads.
// Block 128(M) x 64(N), BK=16, 256 threads (8 warps), warp tile 32x32.
// ---------------------------------------------------------------------------
__global__ __launch_bounds__(256, 2) void gemm_h3(
    const __half* __restrict__ Xh, const __half* __restrict__ Xl,
    int w0, int w1, int w2,
    const float* __restrict__ b0, const float* __restrict__ b1, const float* __restrict__ b2,
    float* __restrict__ outp, int s_off, int mode)
{
    __shared__ uint32_t sAh[2][128][12], sAl[2][128][12];
    __shared__ uint32_t sBh[2][64][12],  sBl[2][64][12];

    const int z = blockIdx.z;
    const int widx    = (z == 0) ? w0 : (z == 1) ? w1 : w2;
    const float* bias = (z == 0) ? b0 : (z == 1) ? b1 : b2;

    const int tid = threadIdx.x, wid = tid >> 5, lane = tid & 31;
    const int g = lane >> 2, tig = lane & 3;
    const int wm = wid & 3, wn = wid >> 2;
    const int lr16 = lane & 15, lch = lane >> 4;

    const int arow = tid >> 1, akoff = (tid & 1) * 8;
    const int brow = (tid & 127) >> 1, bkoff = (tid & 1) * 8;
    const bool bIsH = (tid < 128);

    const __half* Ah = Xh + (size_t)(blockIdx.y * 128 + arow) * DC + akoff;
    const __half* Al = Xl + (size_t)(blockIdx.y * 128 + arow) * DC + akoff;
    const __half* Bp = (bIsH ? g_wh : g_wl) + (size_t)widx * WELEM
                       + (size_t)(blockIdx.x * 64 + brow) * DC + bkoff;

    float accm[2][4][4] = {}, accc[2][4][4] = {};

    uint4 rah = *(const uint4*)(Ah);
    uint4 ral = *(const uint4*)(Al);
    uint4 rb  = *(const uint4*)(Bp);
    int cur = 0;

    for (int kt = 0; kt < DC / 16; ++kt) {
        *(uint4*)&sAh[cur][arow][akoff >> 1] = rah;
        *(uint4*)&sAl[cur][arow][akoff >> 1] = ral;
        if (bIsH) *(uint4*)&sBh[cur][brow][bkoff >> 1] = rb;
        else      *(uint4*)&sBl[cur][brow][bkoff >> 1] = rb;
        __syncthreads();
        if (kt + 1 < DC / 16) {
            rah = *(const uint4*)(Ah + (kt + 1) * 16);
            ral = *(const uint4*)(Al + (kt + 1) * 16);
            rb  = *(const uint4*)(Bp + (kt + 1) * 16);
        }

        uint32_t ah[2][4], al[2][4], bh[2][4], bl[2][4];
        ldsm4(ah[0], &sAh[cur][wm * 32 + lr16][lch * 4]);
        ldsm4(ah[1], &sAh[cur][wm * 32 + 16 + lr16][lch * 4]);
        ldsm4(al[0], &sAl[cur][wm * 32 + lr16][lch * 4]);
        ldsm4(al[1], &sAl[cur][wm * 32 + 16 + lr16][lch * 4]);
        ldsm4(bh[0], &sBh[cur][wn * 32 + lr16][lch * 4]);
        ldsm4(bh[1], &sBh[cur][wn * 32 + 16 + lr16][lch * 4]);
        ldsm4(bl[0], &sBl[cur][wn * 32 + lr16][lch * 4]);
        ldsm4(bl[1], &sBl[cur][wn * 32 + 16 + lr16][lch * 4]);

        #pragma unroll
        for (int p = 0; p < 2; ++p)
            #pragma unroll
            for (int e = 0; e < 2; ++e) {
                const int ni = p * 2 + e;
                uint32_t bhf[2] = { bh[p][e], bh[p][e + 2] };
                uint32_t blf[2] = { bl[p][e], bl[p][e + 2] };
                #pragma unroll
                for (int mi = 0; mi < 2; ++mi) {
                    mma_f16(accm[mi][ni], ah[mi], bhf);
                    mma_f16(accc[mi][ni], ah[mi], blf);
                    mma_f16(accc[mi][ni], al[mi], bhf);
                }
            }
        cur ^= 1;
    }

    const float rescale = 1.0f / 2048.0f;
    #pragma unroll
    for (int mi = 0; mi < 2; ++mi) {
        #pragma unroll
        for (int ni = 0; ni < 4; ++ni) {
            const int row0 = blockIdx.y * 128 + wm * 32 + mi * 16 + g;
            const int col0 = blockIdx.x * 64 + wn * 32 + ni * 8 + 2 * tig;
            const float bx = bias[col0], by = bias[col0 + 1];
            const float v00 = accm[mi][ni][0] + accc[mi][ni][0] * rescale + bx;
            const float v01 = accm[mi][ni][1] + accc[mi][ni][1] * rescale + by;
            const float v10 = accm[mi][ni][2] + accc[mi][ni][2] * rescale + bx;
            const float v11 = accm[mi][ni][3] + accc[mi][ni][3] * rescale + by;
            if (mode == 0) {
                if (z < 2) {
                    float* dst = z ? g_k : g_q;
                    const int h = col0 >> 6, d = col0 & 63;
                    *(float2*)(dst + ((size_t)h * S_TOTC + (s_off + row0)) * DHC + d) =
                        make_float2(v00, v01);
                    *(float2*)(dst + ((size_t)h * S_TOTC + (s_off + row0 + 8)) * DHC + d) =
                        make_float2(v10, v11);
                } else {
                    const int s0 = s_off + row0;
                    #pragma unroll
                    for (int e = 0; e < 2; ++e) {
                        const float va = e ? v01 : v00;
                        const float vb = e ? v11 : v10;
                        const size_t base = (size_t)(col0 + e) * S_TOTC;
                        const __half ha = __float2half_rn(va);
                        const __half hb = __float2half_rn(vb);
                        g_vh[base + s0]     = ha;
                        g_vh[base + s0 + 8] = hb;
                        g_vl[base + s0]     = __float2half_rn(va - __half2float(ha));
                        g_vl[base + s0 + 8] = __float2half_rn(vb - __half2float(hb));
                    }
                }
            } else {
                *(float2*)(outp + (size_t)row0 * DC + col0) = make_float2(v00, v01);
                *(float2*)(outp + (size_t)(row0 + 8) * DC + col0) = make_float2(v10, v11);
            }
        }
    }
}

// ---------------------------------------------------------------------------
// RMS-norm + RoPE; emits fp16 q (pre-scaled by DH^-0.5) and fp16 k.
// ---------------------------------------------------------------------------
__global__ __launch_bounds__(256) void rmsrope2(
    const float* __restrict__ cosb, const float* __restrict__ sinb,
    const float* __restrict__ gaq, const float* __restrict__ gq,
    const float* __restrict__ gak, const float* __restrict__ gk)
{
    const int z = blockIdx.z;
    const float* buf = z ? g_k : g_q;
    __half* outh = z ? g_kh : g_qh;
    const int s = blockIdx.x * 8 + (threadIdx.x >> 5);
    const int h = blockIdx.y;
    const int t = threadIdx.x & 31;

    const float* p = buf + ((size_t)h * S_TOTC + s) * DHC;
    float2 x = *(const float2*)(p + 2 * t);
    float ss = x.x * x.x + x.y * x.y;
    #pragma unroll
    for (int o = 16; o; o >>= 1) ss += __shfl_xor_sync(0xffffffffu, ss, o);
    const float r = rsqrtf(ss * (1.0f / 64.0f) + 1e-6f);
    const float* gg = z ? ((s < S_TXTC) ? gak : gk) : ((s < S_TXTC) ? gaq : gq);
    const float y0 = x.x * r * gg[2 * t];
    const float y1 = x.y * r * gg[2 * t + 1];
    const float c  = cosb[s * 64 + 2 * t];
    const float sn = sinb[s * 64 + 2 * t];
    float o0 = y0 * c - y1 * sn;
    float o1 = y1 * c + y0 * sn;
    if (z == 0) { o0 *= 0.125f; o1 *= 0.125f; }
    *(uint32_t*)(outh + ((size_t)h * S_TOTC + s) * DHC + 2 * t) = packh2(o0, o1);
}

// ---------------------------------------------------------------------------
// fp16 flash attention: register-resident P, ldmatrix fragment loads,
// pre-converted fp16 Q/K/V staged with pure vector copies.
// ---------------------------------------------------------------------------
__global__ __launch_bounds__(128) void attn_h()
{
    __shared__ uint32_t sQ[128][36];
    __shared__ uint32_t sK[64][36];
    __shared__ uint32_t sVh[64][36];
    __shared__ uint32_t sVl[64][36];

    const int h = blockIdx.y, qt = blockIdx.x;
    const int tid = threadIdx.x;
    const int w = tid >> 5, lane = tid & 31, g = lane >> 2, tig = lane & 3;
    const int wr = w * 32;
    const int lr16 = lane & 15, lch = lane >> 4;

    const __half* qhb = g_qh + ((size_t)h * S_TOTC + qt * 128) * DHC;
    for (int i = tid; i < 1024; i += 128) {
        const int row = i >> 3, j = i & 7;
        *(uint4*)&sQ[row][j * 4] = *(const uint4*)(qhb + row * 64 + j * 8);
    }

    float oacc[4][4][4] = {};
    float mrow[4] = {-1e30f, -1e30f, -1e30f, -1e30f};
    float lrow[4] = {0.f, 0.f, 0.f, 0.f};

    const __half* khb = g_kh + (size_t)h * S_TOTC * DHC;
    const __half* vhb = g_vh + (size_t)h * DHC * S_TOTC;
    const __half* vlb = g_vl + (size_t)h * DHC * S_TOTC;

    for (int kt = 0; kt < S_TOTC / 64; ++kt) {
        __syncthreads();
        for (int i = tid; i < 512; i += 128) {
            const int row = i >> 3, j = i & 7;
            *(uint4*)&sK[row][j * 4] = *(const uint4*)(khb + (size_t)(kt * 64 + row) * 64 + j * 8);
        }
        for (int u = tid; u < 256; u += 128) {   // 64 rows x 4 chunks of 16 halfs
            const int d = u >> 2, j = u & 3;
            const size_t off = (size_t)d * S_TOTC + kt * 64 + j * 16;
            *(uint4*)&sVh[d][j * 8]     = *(const uint4*)(vhb + off);
            *(uint4*)&sVh[d][j * 8 + 4] = *(const uint4*)(vhb + off + 8);
            *(uint4*)&sVl[d][j * 8]     = *(const uint4*)(vlb + off);
            *(uint4*)&sVl[d][j * 8 + 4] = *(const uint4*)(vlb + off + 8);
        }
        __syncthreads();

        // ---- S = Q K^T ----
        float sfrag[2][8][4] = {};
        #pragma unroll
        for (int kk2 = 0; kk2 < 32; kk2 += 8) {
            uint32_t a[2][4];
            ldsm4(a[0], &sQ[wr + lr16][kk2 + lch * 4]);
            ldsm4(a[1], &sQ[wr + 16 + lr16][kk2 + lch * 4]);
            #pragma unroll
            for (int p = 0; p < 4; ++p) {
                uint32_t bb[4];
                ldsm4(bb, &sK[p * 16 + lr16][kk2 + lch * 4]);
                #pragma unroll
                for (int e = 0; e < 2; ++e) {
                    uint32_t bf[2] = { bb[e], bb[e + 2] };
                    mma_f16(sfrag[0][p * 2 + e], a[0], bf);
                    mma_f16(sfrag[1][p * 2 + e], a[1], bf);
                }
            }
        }

        // ---- online softmax; register P ----
        uint32_t ph[2][8][2];
        float corrv[4];
        #pragma unroll
        for (int f = 0; f < 4; ++f) {
            const int mi = f >> 1, cb = (f & 1) << 1;
            float mx = mrow[f];
            #pragma unroll
            for (int ni = 0; ni < 8; ++ni)
                mx = fmaxf(mx, fmaxf(sfrag[mi][ni][cb], sfrag[mi][ni][cb + 1]));
            mx = fmaxf(mx, __shfl_xor_sync(0xffffffffu, mx, 1));
            mx = fmaxf(mx, __shfl_xor_sync(0xffffffffu, mx, 2));
            corrv[f] = __expf(mrow[f] - mx);
            mrow[f] = mx;
            float sum = 0.f;
            #pragma unroll
            for (int ni = 0; ni < 8; ++ni) {
                const float p0 = __expf(sfrag[mi][ni][cb]     - mx);
                const float p1 = __expf(sfrag[mi][ni][cb + 1] - mx);
                sum += p0 + p1;
                ph[mi][ni][f & 1] = packh2(p0, p1);
            }
            sum += __shfl_xor_sync(0xffffffffu, sum, 1);
            sum += __shfl_xor_sync(0xffffffffu, sum, 2);
            lrow[f] = lrow[f] * corrv[f] + sum;
        }

        #pragma unroll
        for (int qb = 0; qb < 4; ++qb) {
            const float cA = __shfl_sync(0xffffffffu, corrv[qb], 8 * tig);
            const float cB = __shfl_sync(0xffffffffu, corrv[qb], 8 * tig + 4);
            #pragma unroll
            for (int md = 0; md < 4; ++md) {
                oacc[md][qb][0] *= cA; oacc[md][qb][1] *= cB;
                oacc[md][qb][2] *= cA; oacc[md][qb][3] *= cB;
            }
        }

        // ---- O^T += V^T P^T ----
        #pragma unroll
        for (int kk2 = 0; kk2 < 32; kk2 += 8) {
            const int ni0 = kk2 >> 2;
            uint32_t av[4][4], avl[4][4];
            #pragma unroll
            for (int md = 0; md < 4; ++md) {
                ldsm4(av[md],  &sVh[md * 16 + lr16][kk2 + lch * 4]);
                ldsm4(avl[md], &sVl[md * 16 + lr16][kk2 + lch * 4]);
            }
            #pragma unroll
            for (int qb = 0; qb < 4; ++qb) {
                uint32_t b[2] = { ph[qb >> 1][ni0][qb & 1], ph[qb >> 1][ni0 + 1][qb & 1] };
                #pragma unroll
                for (int md = 0; md < 4; ++md) {
                    mma_f16(oacc[md][qb], av[md], b);
                    mma_f16(oacc[md][qb], avl[md], b);
                }
            }
        }
    }

    #pragma unroll
    for (int qb = 0; qb < 4; ++qb) {
        const float lA = __shfl_sync(0xffffffffu, lrow[qb], 8 * tig);
        const float lB = __shfl_sync(0xffffffffu, lrow[qb], 8 * tig + 4);
        const float iA = 1.0f / lA, iB = 1.0f / lB;
        const int q0 = qt * 128 + wr + qb * 8 + 2 * tig;
        #pragma unroll
        for (int md = 0; md < 4; ++md) {
            const int d0 = h * 64 + md * 16 + g;
            g_ao[(size_t)q0 * DC + d0]           = oacc[md][qb][0] * iA;
            g_ao[(size_t)(q0 + 1) * DC + d0]     = oacc[md][qb][1] * iB;
            g_ao[(size_t)q0 * DC + d0 + 8]       = oacc[md][qb][2] * iA;
            g_ao[(size_t)(q0 + 1) * DC + d0 + 8] = oacc[md][qb][3] * iB;
        }
    }
}

// ---------------------------------------------------------------------------
extern "C" void kernel_launch(void* const* d_in, const int* in_sizes, int n_in,
                              void* d_out, int out_size)
{
    (void)in_sizes; (void)n_in; (void)out_size;
    const float* hs  = (const float*)d_in[0];
    const float* ehs = (const float*)d_in[1];
    const float* rc  = (const float*)d_in[2];
    const float* rs  = (const float*)d_in[3];
    const float* bq  = (const float*)d_in[5];
    const float* bk  = (const float*)d_in[7];
    const float* bv  = (const float*)d_in[9];
    const float* baq = (const float*)d_in[11];
    const float* bak = (const float*)d_in[13];
    const float* bav = (const float*)d_in[15];
    const float* bo  = (const float*)d_in[17];
    const float* bao = (const float*)d_in[19];
    const float* gq  = (const float*)d_in[20];
    const float* gk  = (const float*)d_in[21];
    const float* gaq = (const float*)d_in[22];
    const float* gak = (const float*)d_in[23];
    float* out = (float*)d_out;

    __half *xh, *xl, *wh, *wl, *aoh, *aol;
    float *aob;
    cudaGetSymbolAddress((void**)&xh,  g_xh);
    cudaGetSymbolAddress((void**)&xl,  g_xl);
    cudaGetSymbolAddress((void**)&wh,  g_wh);
    cudaGetSymbolAddress((void**)&wl,  g_wl);
    cudaGetSymbolAddress((void**)&aoh, g_aoh);
    cudaGetSymbolAddress((void**)&aol, g_aol);
    cudaGetSymbolAddress((void**)&aob, g_ao);

    SplitJobs jobs;
    jobs.j[0] = { hs,  xh,                       xl,                       S_IMGC * DC };
    jobs.j[1] = { ehs, xh + (size_t)S_IMGC * DC, xl + (size_t)S_IMGC * DC, S_TXTC * DC };
    const int wsrc[8] = {4, 6, 8, 10, 12, 14, 16, 18};
    for (int i = 0; i < 8; ++i)
        jobs.j[2 + i] = { (const float*)d_in[wsrc[i]],
                          wh + (size_t)i * WELEM, wl + (size_t)i * WELEM, WELEM };
    {
        dim3 grid((S_IMGC * DC / 4 + 255) / 256, 10);
        split_kernel<<<grid, 256>>>(jobs);
    }

    gemm_h3<<<dim3(DC / 64, S_IMGC / 128, 3), 256>>>(
        xh, xl, 0, 1, 2, bq, bk, bv, nullptr, 512, 0);
    gemm_h3<<<dim3(DC / 64, S_TXTC / 128, 3), 256>>>(
        xh + (size_t)S_IMGC * DC, xl + (size_t)S_IMGC * DC,
        3, 4, 5, baq, bak, bav, nullptr, 0, 0);

    rmsrope2<<<dim3(S_TOTC / 8, HC, 2), 256>>>(rc, rs, gaq, gq, gak, gk);

    attn_h<<<dim3(S_TOTC / 128, HC), 128>>>();

    {
        SplitJobs j2;
        j2.j[0] = { aob, aoh, aol, S_TOTC * DC };
        dim3 grid((S_TOTC * DC / 4 + 255) / 256, 1);
        split_kernel<<<grid, 256>>>(j2);
    }

    gemm_h3<<<dim3(DC / 64, S_IMGC / 128, 1), 256>>>(
        aoh + (size_t)S_TXTC * DC, aol + (size_t)S_TXTC * DC,
        6, 6, 6, bo, bo, bo, out, 0, 1);
    gemm_h3<<<dim3(DC / 64, S_TXTC / 128, 1), 256>>>(
        aoh, aol, 7, 7, 7, bao, bao, bao, out + (size_t)S_IMGC * DC, 0, 1);
}

// round 8
// speedup vs baseline: 4.4681x; 1.1887x over previous
#include <cuda_runtime.h>
#include <cuda_fp16.h>
#include <math.h>
#include <stdint.h>

#define S_IMGC 2048
#define S_TXTC 512
#define S_TOTC 2560
#define DC     1536
#define HC     24
#define DHC    64
#define WELEM  (DC * DC)

// ---------------- device scratch (allocation-free rule) ----------------
__device__ float  g_q [(size_t)HC * S_TOTC * DHC];
__device__ float  g_k [(size_t)HC * S_TOTC * DHC];
__device__ __half g_qh[(size_t)HC * S_TOTC * DHC];   // fp16, pre-scaled by 0.125
__device__ __half g_kh[(size_t)HC * S_TOTC * DHC];
__device__ __half g_vh[(size_t)HC * DHC * S_TOTC];   // [h][d][s] transposed
__device__ __half g_vl[(size_t)HC * DHC * S_TOTC];   // residual
__device__ float  g_ao[(size_t)S_TOTC * DC];
__device__ __half g_xh[(size_t)S_TOTC * DC];
__device__ __half g_xl[(size_t)S_TOTC * DC];
__device__ __half g_wh[(size_t)8 * WELEM];
__device__ __half g_wl[(size_t)8 * WELEM];
__device__ __half g_aoh[(size_t)S_TOTC * DC];
__device__ __half g_aol[(size_t)S_TOTC * DC];

__device__ __forceinline__ uint32_t packh2(float a, float b) {
    __half2 h = __floats2half2_rn(a, b);
    return *(uint32_t*)&h;
}

__device__ __forceinline__ void mma_f16(float* c, const uint32_t* a, const uint32_t* b) {
    asm volatile(
        "mma.sync.aligned.m16n8k16.row.col.f32.f16.f16.f32 "
        "{%0,%1,%2,%3}, {%4,%5,%6,%7}, {%8,%9}, {%0,%1,%2,%3};"
        : "+f"(c[0]), "+f"(c[1]), "+f"(c[2]), "+f"(c[3])
        : "r"(a[0]), "r"(a[1]), "r"(a[2]), "r"(a[3]), "r"(b[0]), "r"(b[1]));
}

__device__ __forceinline__ void ldsm4(uint32_t* r, const void* p) {
    uint32_t a = (uint32_t)__cvta_generic_to_shared(p);
    asm volatile("ldmatrix.sync.aligned.m8n8.x4.shared.b16 {%0,%1,%2,%3}, [%4];"
        : "=r"(r[0]), "=r"(r[1]), "=r"(r[2]), "=r"(r[3]) : "r"(a));
}

__device__ __forceinline__ void ldsm4s(uint32_t* r, uint32_t saddr) {
    asm volatile("ldmatrix.sync.aligned.m8n8.x4.shared.b16 {%0,%1,%2,%3}, [%4];"
        : "=r"(r[0]), "=r"(r[1]), "=r"(r[2]), "=r"(r[3]) : "r"(saddr));
}

__device__ __forceinline__ void cp16(uint32_t s, const void* g) {
    asm volatile("cp.async.ca.shared.global [%0], [%1], 16;" :: "r"(s), "l"(g));
}

// ---------------------------------------------------------------------------
// Elementwise fp32 -> (h, l*2048) fp16 split.
// ---------------------------------------------------------------------------
struct SplitJob  { const float* s; __half* h; __half* l; int n; };
struct SplitJobs { SplitJob j[10]; };

__global__ __launch_bounds__(256) void split_kernel(SplitJobs jobs) {
    const SplitJob J = jobs.j[blockIdx.y];
    const int i = (blockIdx.x * 256 + threadIdx.x) * 4;
    if (i >= J.n) return;
    const float4 v = *(const float4*)(J.s + i);
    const __half h0 = __float2half_rn(v.x), h1 = __float2half_rn(v.y);
    const __half h2 = __float2half_rn(v.z), h3 = __float2half_rn(v.w);
    uint2 hw, lw;
    { __half2 p0 = __halves2half2(h0, h1), p1 = __halves2half2(h2, h3);
      hw.x = *(uint32_t*)&p0; hw.y = *(uint32_t*)&p1; }
    const float r0 = (v.x - __half2float(h0)) * 2048.f;
    const float r1 = (v.y - __half2float(h1)) * 2048.f;
    const float r2 = (v.z - __half2float(h2)) * 2048.f;
    const float r3 = (v.w - __half2float(h3)) * 2048.f;
    lw.x = packh2(r0, r1); lw.y = packh2(r2, r3);
    *(uint2*)(J.h + i) = hw;
    *(uint2*)(J.l + i) = lw;
}

// ---------------------------------------------------------------------------
// fp16x3 GEMM, cp.async 3-stage pipeline, BK=32.
// Block 128(M) x 64(N), 256 threads (8 warps), warp tile 32x32.
// smem stage layout (bytes, row stride 80 = 20 u32, data 16 u32):
//   AH [128][20u32] @0, AL @10240, BH [64][20u32] @20480, BL @25600; stage=30720
// ---------------------------------------------------------------------------
#define GST_AH 0u
#define GST_AL 10240u
#define GST_BH 20480u
#define GST_BL 25600u
#define GST_SZ 30720u
#define GNK    (DC / 32)

__global__ __launch_bounds__(256, 2) void gemm_h3(
    const __half* __restrict__ Xh, const __half* __restrict__ Xl,
    int w0, int w1, int w2,
    const float* __restrict__ b0, const float* __restrict__ b1, const float* __restrict__ b2,
    float* __restrict__ outp, int s_off, int mode)
{
    extern __shared__ uint32_t dynsm[];
    const uint32_t smb = (uint32_t)__cvta_generic_to_shared(dynsm);

    const int z = blockIdx.z;
    const int widx    = (z == 0) ? w0 : (z == 1) ? w1 : w2;
    const float* bias = (z == 0) ? b0 : (z == 1) ? b1 : b2;

    const int tid = threadIdx.x, wid = tid >> 5, lane = tid & 31;
    const int g = lane >> 2, tig = lane & 3;
    const int wm = wid & 3, wn = wid >> 2;
    const int lr16 = lane & 15, lch = lane >> 4;

    // loader indexing: row = tid>>2 (0..63), chunk c = tid&3 (8 halfs each)
    const int ldrow = tid >> 2;
    const int ldc   = tid & 3;

    const __half* AhG = Xh + (size_t)(blockIdx.y * 128 + ldrow) * DC + ldc * 8;
    const __half* AlG = Xl + (size_t)(blockIdx.y * 128 + ldrow) * DC + ldc * 8;
    const __half* BhG = g_wh + (size_t)widx * WELEM + (size_t)(blockIdx.x * 64 + ldrow) * DC + ldc * 8;
    const __half* BlG = g_wl + (size_t)widx * WELEM + (size_t)(blockIdx.x * 64 + ldrow) * DC + ldc * 8;
    const size_t rstep = (size_t)64 * DC;

    float accm[2][4][4] = {}, accc[2][4][4] = {};

    // ---- pipeline load helper (stage st, ktile kt) ----
    auto load_stage = [&](int st, int kt) {
        const uint32_t sb = smb + (uint32_t)st * GST_SZ;
        const uint32_t ro = (uint32_t)ldrow * 80 + (uint32_t)ldc * 16;
        const size_t go = (size_t)kt * 32;
        cp16(sb + GST_AH + ro,              AhG + go);
        cp16(sb + GST_AH + ro + 64 * 80,    AhG + go + rstep);
        cp16(sb + GST_AL + ro,              AlG + go);
        cp16(sb + GST_AL + ro + 64 * 80,    AlG + go + rstep);
        cp16(sb + GST_BH + ro,              BhG + go);
        cp16(sb + GST_BL + ro,              BlG + go);
    };

    load_stage(0, 0);
    asm volatile("cp.async.commit_group;" ::: "memory");
    load_stage(1, 1);
    asm volatile("cp.async.commit_group;" ::: "memory");

    for (int kt = 0; kt < GNK; ++kt) {
        asm volatile("cp.async.wait_group 1;" ::: "memory");
        __syncthreads();
        if (kt + 2 < GNK) load_stage((kt + 2) % 3, kt + 2);
        asm volatile("cp.async.commit_group;" ::: "memory");

        const uint32_t sb = smb + (uint32_t)(kt % 3) * GST_SZ;
        const uint32_t arow0 = (uint32_t)(wm * 32 + lr16) * 80;
        const uint32_t arow1 = (uint32_t)(wm * 32 + 16 + lr16) * 80;
        const uint32_t brow0 = (uint32_t)(wn * 32 + lr16) * 80;
        const uint32_t brow1 = (uint32_t)(wn * 32 + 16 + lr16) * 80;

        #pragma unroll
        for (int ks = 0; ks < 16; ks += 8) {   // two k16 sub-steps (u32 col units)
            const uint32_t co = (uint32_t)(ks + lch * 4) * 4;
            uint32_t ah[2][4], al[2][4], bh[2][4], bl[2][4];
            ldsm4s(ah[0], sb + GST_AH + arow0 + co);
            ldsm4s(ah[1], sb + GST_AH + arow1 + co);
            ldsm4s(al[0], sb + GST_AL + arow0 + co);
            ldsm4s(al[1], sb + GST_AL + arow1 + co);
            ldsm4s(bh[0], sb + GST_BH + brow0 + co);
            ldsm4s(bh[1], sb + GST_BH + brow1 + co);
            ldsm4s(bl[0], sb + GST_BL + brow0 + co);
            ldsm4s(bl[1], sb + GST_BL + brow1 + co);

            #pragma unroll
            for (int p = 0; p < 2; ++p)
                #pragma unroll
                for (int e = 0; e < 2; ++e) {
                    const int ni = p * 2 + e;
                    uint32_t bhf[2] = { bh[p][e], bh[p][e + 2] };
                    uint32_t blf[2] = { bl[p][e], bl[p][e + 2] };
                    #pragma unroll
                    for (int mi = 0; mi < 2; ++mi) {
                        mma_f16(accm[mi][ni], ah[mi], bhf);
                        mma_f16(accc[mi][ni], ah[mi], blf);
                        mma_f16(accc[mi][ni], al[mi], bhf);
                    }
                }
        }
    }

    const float rescale = 1.0f / 2048.0f;
    #pragma unroll
    for (int mi = 0; mi < 2; ++mi) {
        #pragma unroll
        for (int ni = 0; ni < 4; ++ni) {
            const int row0 = blockIdx.y * 128 + wm * 32 + mi * 16 + g;
            const int col0 = blockIdx.x * 64 + wn * 32 + ni * 8 + 2 * tig;
            const float bx = bias[col0], by = bias[col0 + 1];
            const float v00 = accm[mi][ni][0] + accc[mi][ni][0] * rescale + bx;
            const float v01 = accm[mi][ni][1] + accc[mi][ni][1] * rescale + by;
            const float v10 = accm[mi][ni][2] + accc[mi][ni][2] * rescale + bx;
            const float v11 = accm[mi][ni][3] + accc[mi][ni][3] * rescale + by;
            if (mode == 0) {
                if (z < 2) {
                    float* dst = z ? g_k : g_q;
                    const int h = col0 >> 6, d = col0 & 63;
                    *(float2*)(dst + ((size_t)h * S_TOTC + (s_off + row0)) * DHC + d) =
                        make_float2(v00, v01);
                    *(float2*)(dst + ((size_t)h * S_TOTC + (s_off + row0 + 8)) * DHC + d) =
                        make_float2(v10, v11);
                } else {
                    const int s0 = s_off + row0;
                    #pragma unroll
                    for (int e = 0; e < 2; ++e) {
                        const float va = e ? v01 : v00;
                        const float vb = e ? v11 : v10;
                        const size_t base = (size_t)(col0 + e) * S_TOTC;
                        const __half ha = __float2half_rn(va);
                        const __half hb = __float2half_rn(vb);
                        g_vh[base + s0]     = ha;
                        g_vh[base + s0 + 8] = hb;
                        g_vl[base + s0]     = __float2half_rn(va - __half2float(ha));
                        g_vl[base + s0 + 8] = __float2half_rn(vb - __half2float(hb));
                    }
                }
            } else {
                *(float2*)(outp + (size_t)row0 * DC + col0) = make_float2(v00, v01);
                *(float2*)(outp + (size_t)(row0 + 8) * DC + col0) = make_float2(v10, v11);
            }
        }
    }
}

// ---------------------------------------------------------------------------
// RMS-norm + RoPE; emits fp16 q (pre-scaled by DH^-0.5) and fp16 k.
// ---------------------------------------------------------------------------
__global__ __launch_bounds__(256) void rmsrope2(
    const float* __restrict__ cosb, const float* __restrict__ sinb,
    const float* __restrict__ gaq, const float* __restrict__ gq,
    const float* __restrict__ gak, const float* __restrict__ gk)
{
    const int z = blockIdx.z;
    const float* buf = z ? g_k : g_q;
    __half* outh = z ? g_kh : g_qh;
    const int s = blockIdx.x * 8 + (threadIdx.x >> 5);
    const int h = blockIdx.y;
    const int t = threadIdx.x & 31;

    const float* p = buf + ((size_t)h * S_TOTC + s) * DHC;
    float2 x = *(const float2*)(p + 2 * t);
    float ss = x.x * x.x + x.y * x.y;
    #pragma unroll
    for (int o = 16; o; o >>= 1) ss += __shfl_xor_sync(0xffffffffu, ss, o);
    const float r = rsqrtf(ss * (1.0f / 64.0f) + 1e-6f);
    const float* gg = z ? ((s < S_TXTC) ? gak : gk) : ((s < S_TXTC) ? gaq : gq);
    const float y0 = x.x * r * gg[2 * t];
    const float y1 = x.y * r * gg[2 * t + 1];
    const float c  = cosb[s * 64 + 2 * t];
    const float sn = sinb[s * 64 + 2 * t];
    float o0 = y0 * c - y1 * sn;
    float o1 = y1 * c + y0 * sn;
    if (z == 0) { o0 *= 0.125f; o1 *= 0.125f; }
    *(uint32_t*)(outh + ((size_t)h * S_TOTC + s) * DHC + 2 * t) = packh2(o0, o1);
}

// ---------------------------------------------------------------------------
// fp16 flash attention: register-resident P, ldmatrix fragment loads.
// ---------------------------------------------------------------------------
__global__ __launch_bounds__(128) void attn_h()
{
    __shared__ uint32_t sQ[128][36];
    __shared__ uint32_t sK[64][36];
    __shared__ uint32_t sVh[64][36];
    __shared__ uint32_t sVl[64][36];

    const int h = blockIdx.y, qt = blockIdx.x;
    const int tid = threadIdx.x;
    const int w = tid >> 5, lane = tid & 31, g = lane >> 2, tig = lane & 3;
    const int wr = w * 32;
    const int lr16 = lane & 15, lch = lane >> 4;

    const __half* qhb = g_qh + ((size_t)h * S_TOTC + qt * 128) * DHC;
    for (int i = tid; i < 1024; i += 128) {
        const int row = i >> 3, j = i & 7;
        *(uint4*)&sQ[row][j * 4] = *(const uint4*)(qhb + row * 64 + j * 8);
    }

    float oacc[4][4][4] = {};
    float mrow[4] = {-1e30f, -1e30f, -1e30f, -1e30f};
    float lrow[4] = {0.f, 0.f, 0.f, 0.f};

    const __half* khb = g_kh + (size_t)h * S_TOTC * DHC;
    const __half* vhb = g_vh + (size_t)h * DHC * S_TOTC;
    const __half* vlb = g_vl + (size_t)h * DHC * S_TOTC;

    for (int kt = 0; kt < S_TOTC / 64; ++kt) {
        __syncthreads();
        for (int i = tid; i < 512; i += 128) {
            const int row = i >> 3, j = i & 7;
            *(uint4*)&sK[row][j * 4] = *(const uint4*)(khb + (size_t)(kt * 64 + row) * 64 + j * 8);
        }
        for (int u = tid; u < 256; u += 128) {
            const int d = u >> 2, j = u & 3;
            const size_t off = (size_t)d * S_TOTC + kt * 64 + j * 16;
            *(uint4*)&sVh[d][j * 8]     = *(const uint4*)(vhb + off);
            *(uint4*)&sVh[d][j * 8 + 4] = *(const uint4*)(vhb + off + 8);
            *(uint4*)&sVl[d][j * 8]     = *(const uint4*)(vlb + off);
            *(uint4*)&sVl[d][j * 8 + 4] = *(const uint4*)(vlb + off + 8);
        }
        __syncthreads();

        float sfrag[2][8][4] = {};
        #pragma unroll
        for (int kk2 = 0; kk2 < 32; kk2 += 8) {
            uint32_t a[2][4];
            ldsm4(a[0], &sQ[wr + lr16][kk2 + lch * 4]);
            ldsm4(a[1], &sQ[wr + 16 + lr16][kk2 + lch * 4]);
            #pragma unroll
            for (int p = 0; p < 4; ++p) {
                uint32_t bb[4];
                ldsm4(bb, &sK[p * 16 + lr16][kk2 + lch * 4]);
                #pragma unroll
                for (int e = 0; e < 2; ++e) {
                    uint32_t bf[2] = { bb[e], bb[e + 2] };
                    mma_f16(sfrag[0][p * 2 + e], a[0], bf);
                    mma_f16(sfrag[1][p * 2 + e], a[1], bf);
                }
            }
        }

        uint32_t ph[2][8][2];
        float corrv[4];
        #pragma unroll
        for (int f = 0; f < 4; ++f) {
            const int mi = f >> 1, cb = (f & 1) << 1;
            float mx = mrow[f];
            #pragma unroll
            for (int ni = 0; ni < 8; ++ni)
                mx = fmaxf(mx, fmaxf(sfrag[mi][ni][cb], sfrag[mi][ni][cb + 1]));
            mx = fmaxf(mx, __shfl_xor_sync(0xffffffffu, mx, 1));
            mx = fmaxf(mx, __shfl_xor_sync(0xffffffffu, mx, 2));
            corrv[f] = __expf(mrow[f] - mx);
            mrow[f] = mx;
            float sum = 0.f;
            #pragma unroll
            for (int ni = 0; ni < 8; ++ni) {
                const float p0 = __expf(sfrag[mi][ni][cb]     - mx);
                const float p1 = __expf(sfrag[mi][ni][cb + 1] - mx);
                sum += p0 + p1;
                ph[mi][ni][f & 1] = packh2(p0, p1);
            }
            sum += __shfl_xor_sync(0xffffffffu, sum, 1);
            sum += __shfl_xor_sync(0xffffffffu, sum, 2);
            lrow[f] = lrow[f] * corrv[f] + sum;
        }

        #pragma unroll
        for (int qb = 0; qb < 4; ++qb) {
            const float cA = __shfl_sync(0xffffffffu, corrv[qb], 8 * tig);
            const float cB = __shfl_sync(0xffffffffu, corrv[qb], 8 * tig + 4);
            #pragma unroll
            for (int md = 0; md < 4; ++md) {
                oacc[md][qb][0] *= cA; oacc[md][qb][1] *= cB;
                oacc[md][qb][2] *= cA; oacc[md][qb][3] *= cB;
            }
        }

        #pragma unroll
        for (int kk2 = 0; kk2 < 32; kk2 += 8) {
            const int ni0 = kk2 >> 2;
            uint32_t av[4][4], avl[4][4];
            #pragma unroll
            for (int md = 0; md < 4; ++md) {
                ldsm4(av[md],  &sVh[md * 16 + lr16][kk2 + lch * 4]);
                ldsm4(avl[md], &sVl[md * 16 + lr16][kk2 + lch * 4]);
            }
            #pragma unroll
            for (int qb = 0; qb < 4; ++qb) {
                uint32_t b[2] = { ph[qb >> 1][ni0][qb & 1], ph[qb >> 1][ni0 + 1][qb & 1] };
                #pragma unroll
                for (int md = 0; md < 4; ++md) {
                    mma_f16(oacc[md][qb], av[md], b);
                    mma_f16(oacc[md][qb], avl[md], b);
                }
            }
        }
    }

    #pragma unroll
    for (int qb = 0; qb < 4; ++qb) {
        const float lA = __shfl_sync(0xffffffffu, lrow[qb], 8 * tig);
        const float lB = __shfl_sync(0xffffffffu, lrow[qb], 8 * tig + 4);
        const float iA = 1.0f / lA, iB = 1.0f / lB;
        const int q0 = qt * 128 + wr + qb * 8 + 2 * tig;
        #pragma unroll
        for (int md = 0; md < 4; ++md) {
            const int d0 = h * 64 + md * 16 + g;
            g_ao[(size_t)q0 * DC + d0]           = oacc[md][qb][0] * iA;
            g_ao[(size_t)(q0 + 1) * DC + d0]     = oacc[md][qb][1] * iB;
            g_ao[(size_t)q0 * DC + d0 + 8]       = oacc[md][qb][2] * iA;
            g_ao[(size_t)(q0 + 1) * DC + d0 + 8] = oacc[md][qb][3] * iB;
        }
    }
}

// ---------------------------------------------------------------------------
extern "C" void kernel_launch(void* const* d_in, const int* in_sizes, int n_in,
                              void* d_out, int out_size)
{
    (void)in_sizes; (void)n_in; (void)out_size;
    const float* hs  = (const float*)d_in[0];
    const float* ehs = (const float*)d_in[1];
    const float* rc  = (const float*)d_in[2];
    const float* rs  = (const float*)d_in[3];
    const float* bq  = (const float*)d_in[5];
    const float* bk  = (const float*)d_in[7];
    const float* bv  = (const float*)d_in[9];
    const float* baq = (const float*)d_in[11];
    const float* bak = (const float*)d_in[13];
    const float* bav = (const float*)d_in[15];
    const float* bo  = (const float*)d_in[17];
    const float* bao = (const float*)d_in[19];
    const float* gq  = (const float*)d_in[20];
    const float* gk  = (const float*)d_in[21];
    const float* gaq = (const float*)d_in[22];
    const float* gak = (const float*)d_in[23];
    float* out = (float*)d_out;

    __half *xh, *xl, *wh, *wl, *aoh, *aol;
    float *aob;
    cudaGetSymbolAddress((void**)&xh,  g_xh);
    cudaGetSymbolAddress((void**)&xl,  g_xl);
    cudaGetSymbolAddress((void**)&wh,  g_wh);
    cudaGetSymbolAddress((void**)&wl,  g_wl);
    cudaGetSymbolAddress((void**)&aoh, g_aoh);
    cudaGetSymbolAddress((void**)&aol, g_aol);
    cudaGetSymbolAddress((void**)&aob, g_ao);

    const int gemm_smem = 3 * 30720;   // 92160 B
    cudaFuncSetAttribute(gemm_h3, cudaFuncAttributeMaxDynamicSharedMemorySize, gemm_smem);

    SplitJobs jobs;
    jobs.j[0] = { hs,  xh,                       xl,                       S_IMGC * DC };
    jobs.j[1] = { ehs, xh + (size_t)S_IMGC * DC, xl + (size_t)S_IMGC * DC, S_TXTC * DC };
    const int wsrc[8] = {4, 6, 8, 10, 12, 14, 16, 18};
    for (int i = 0; i < 8; ++i)
        jobs.j[2 + i] = { (const float*)d_in[wsrc[i]],
                          wh + (size_t)i * WELEM, wl + (size_t)i * WELEM, WELEM };
    {
        dim3 grid((S_IMGC * DC / 4 + 255) / 256, 10);
        split_kernel<<<grid, 256>>>(jobs);
    }

    gemm_h3<<<dim3(DC / 64, S_IMGC / 128, 3), 256, gemm_smem>>>(
        xh, xl, 0, 1, 2, bq, bk, bv, nullptr, 512, 0);
    gemm_h3<<<dim3(DC / 64, S_TXTC / 128, 3), 256, gemm_smem>>>(
        xh + (size_t)S_IMGC * DC, xl + (size_t)S_IMGC * DC,
        3, 4, 5, baq, bak, bav, nullptr, 0, 0);

    rmsrope2<<<dim3(S_TOTC / 8, HC, 2), 256>>>(rc, rs, gaq, gq, gak, gk);

    attn_h<<<dim3(S_TOTC / 128, HC), 128>>>();

    {
        SplitJobs j2;
        j2.j[0] = { aob, aoh, aol, S_TOTC * DC };
        dim3 grid((S_TOTC * DC / 4 + 255) / 256, 1);
        split_kernel<<<grid, 256>>>(j2);
    }

    gemm_h3<<<dim3(DC / 64, S_IMGC / 128, 1), 256, gemm_smem>>>(
        aoh + (size_t)S_TXTC * DC, aol + (size_t)S_TXTC * DC,
        6, 6, 6, bo, bo, bo, out, 0, 1);
    gemm_h3<<<dim3(DC / 64, S_TXTC / 128, 1), 256, gemm_smem>>>(
        aoh, aol, 7, 7, 7, bao, bao, bao, out + (size_t)S_IMGC * DC, 0, 1);
}

// round 10
// speedup vs baseline: 5.0744x; 1.1357x over previous
#include <cuda_runtime.h>
#include <cuda_fp16.h>
#include <math.h>
#include <stdint.h>

#define S_IMGC 2048
#define S_TXTC 512
#define S_TOTC 2560
#define DC     1536
#define HC     24
#define DHC    64
#define WELEM  (DC * DC)

// ---------------- device scratch (allocation-free rule) ----------------
__device__ float  g_q [(size_t)HC * S_TOTC * DHC];
__device__ float  g_k [(size_t)HC * S_TOTC * DHC];
__device__ __half g_qh[(size_t)HC * S_TOTC * DHC];   // fp16, pre-scaled by 0.125
__device__ __half g_kh[(size_t)HC * S_TOTC * DHC];
__device__ __half g_vh[(size_t)HC * DHC * S_TOTC];   // [h][d][s] transposed
__device__ __half g_vl[(size_t)HC * DHC * S_TOTC];   // residual
__device__ __half g_xh[(size_t)S_TOTC * DC];
__device__ __half g_xl[(size_t)S_TOTC * DC];
__device__ __half g_wh[(size_t)8 * WELEM];
__device__ __half g_wl[(size_t)8 * WELEM];
__device__ __half g_aoh[(size_t)S_TOTC * DC];
__device__ __half g_aol[(size_t)S_TOTC * DC];

__device__ __forceinline__ uint32_t packh2(float a, float b) {
    __half2 h = __floats2half2_rn(a, b);
    return *(uint32_t*)&h;
}

__device__ __forceinline__ void mma_f16(float* c, const uint32_t* a, const uint32_t* b) {
    asm volatile(
        "mma.sync.aligned.m16n8k16.row.col.f32.f16.f16.f32 "
        "{%0,%1,%2,%3}, {%4,%5,%6,%7}, {%8,%9}, {%0,%1,%2,%3};"
        : "+f"(c[0]), "+f"(c[1]), "+f"(c[2]), "+f"(c[3])
        : "r"(a[0]), "r"(a[1]), "r"(a[2]), "r"(a[3]), "r"(b[0]), "r"(b[1]));
}

__device__ __forceinline__ void ldsm4s(uint32_t* r, uint32_t saddr) {
    asm volatile("ldmatrix.sync.aligned.m8n8.x4.shared.b16 {%0,%1,%2,%3}, [%4];"
        : "=r"(r[0]), "=r"(r[1]), "=r"(r[2]), "=r"(r[3]) : "r"(saddr));
}

__device__ __forceinline__ void cp16(uint32_t s, const void* g) {
    asm volatile("cp.async.ca.shared.global [%0], [%1], 16;" :: "r"(s), "l"(g));
}

// ---------------------------------------------------------------------------
// Elementwise fp32 -> (h, l*2048) fp16 split.
// ---------------------------------------------------------------------------
struct SplitJob  { const float* s; __half* h; __half* l; int n; };
struct SplitJobs { SplitJob j[10]; };

__global__ __launch_bounds__(256) void split_kernel(SplitJobs jobs) {
    const SplitJob J = jobs.j[blockIdx.y];
    const int i = (blockIdx.x * 256 + threadIdx.x) * 4;
    if (i >= J.n) return;
    const float4 v = *(const float4*)(J.s + i);
    const __half h0 = __float2half_rn(v.x), h1 = __float2half_rn(v.y);
    const __half h2 = __float2half_rn(v.z), h3 = __float2half_rn(v.w);
    uint2 hw, lw;
    { __half2 p0 = __halves2half2(h0, h1), p1 = __halves2half2(h2, h3);
      hw.x = *(uint32_t*)&p0; hw.y = *(uint32_t*)&p1; }
    const float r0 = (v.x - __half2float(h0)) * 2048.f;
    const float r1 = (v.y - __half2float(h1)) * 2048.f;
    const float r2 = (v.z - __half2float(h2)) * 2048.f;
    const float r3 = (v.w - __half2float(h3)) * 2048.f;
    lw.x = packh2(r0, r1); lw.y = packh2(r2, r3);
    *(uint2*)(J.h + i) = hw;
    *(uint2*)(J.l + i) = lw;
}

// ---------------------------------------------------------------------------
// fp16x3 GEMM, cp.async 3-stage pipeline, BK=32.
// ---------------------------------------------------------------------------
#define GST_AH 0u
#define GST_AL 10240u
#define GST_BH 20480u
#define GST_BL 25600u
#define GST_SZ 30720u
#define GNK    (DC / 32)

__global__ __launch_bounds__(256, 2) void gemm_h3(
    const __half* __restrict__ Xh, const __half* __restrict__ Xl,
    int w0, int w1, int w2,
    const float* __restrict__ b0, const float* __restrict__ b1, const float* __restrict__ b2,
    float* __restrict__ outp, int s_off, int mode)
{
    extern __shared__ uint32_t dynsm[];
    const uint32_t smb = (uint32_t)__cvta_generic_to_shared(dynsm);

    const int z = blockIdx.z;
    const int widx    = (z == 0) ? w0 : (z == 1) ? w1 : w2;
    const float* bias = (z == 0) ? b0 : (z == 1) ? b1 : b2;

    const int tid = threadIdx.x, wid = tid >> 5, lane = tid & 31;
    const int g = lane >> 2, tig = lane & 3;
    const int wm = wid & 3, wn = wid >> 2;
    const int lr16 = lane & 15, lch = lane >> 4;

    const int ldrow = tid >> 2;
    const int ldc   = tid & 3;

    const __half* AhG = Xh + (size_t)(blockIdx.y * 128 + ldrow) * DC + ldc * 8;
    const __half* AlG = Xl + (size_t)(blockIdx.y * 128 + ldrow) * DC + ldc * 8;
    const __half* BhG = g_wh + (size_t)widx * WELEM + (size_t)(blockIdx.x * 64 + ldrow) * DC + ldc * 8;
    const __half* BlG = g_wl + (size_t)widx * WELEM + (size_t)(blockIdx.x * 64 + ldrow) * DC + ldc * 8;
    const size_t rstep = (size_t)64 * DC;

    float accm[2][4][4] = {}, accc[2][4][4] = {};

    auto load_stage = [&](int st, int kt) {
        const uint32_t sb = smb + (uint32_t)st * GST_SZ;
        const uint32_t ro = (uint32_t)ldrow * 80 + (uint32_t)ldc * 16;
        const size_t go = (size_t)kt * 32;
        cp16(sb + GST_AH + ro,              AhG + go);
        cp16(sb + GST_AH + ro + 64 * 80,    AhG + go + rstep);
        cp16(sb + GST_AL + ro,              AlG + go);
        cp16(sb + GST_AL + ro + 64 * 80,    AlG + go + rstep);
        cp16(sb + GST_BH + ro,              BhG + go);
        cp16(sb + GST_BL + ro,              BlG + go);
    };

    load_stage(0, 0);
    asm volatile("cp.async.commit_group;" ::: "memory");
    load_stage(1, 1);
    asm volatile("cp.async.commit_group;" ::: "memory");

    for (int kt = 0; kt < GNK; ++kt) {
        asm volatile("cp.async.wait_group 1;" ::: "memory");
        __syncthreads();
        if (kt + 2 < GNK) load_stage((kt + 2) % 3, kt + 2);
        asm volatile("cp.async.commit_group;" ::: "memory");

        const uint32_t sb = smb + (uint32_t)(kt % 3) * GST_SZ;
        const uint32_t arow0 = (uint32_t)(wm * 32 + lr16) * 80;
        const uint32_t arow1 = (uint32_t)(wm * 32 + 16 + lr16) * 80;
        const uint32_t brow0 = (uint32_t)(wn * 32 + lr16) * 80;
        const uint32_t brow1 = (uint32_t)(wn * 32 + 16 + lr16) * 80;

        #pragma unroll
        for (int ks = 0; ks < 16; ks += 8) {
            const uint32_t co = (uint32_t)(ks + lch * 4) * 4;
            uint32_t ah[2][4], al[2][4], bh[2][4], bl[2][4];
            ldsm4s(ah[0], sb + GST_AH + arow0 + co);
            ldsm4s(ah[1], sb + GST_AH + arow1 + co);
            ldsm4s(al[0], sb + GST_AL + arow0 + co);
            ldsm4s(al[1], sb + GST_AL + arow1 + co);
            ldsm4s(bh[0], sb + GST_BH + brow0 + co);
            ldsm4s(bh[1], sb + GST_BH + brow1 + co);
            ldsm4s(bl[0], sb + GST_BL + brow0 + co);
            ldsm4s(bl[1], sb + GST_BL + brow1 + co);

            #pragma unroll
            for (int p = 0; p < 2; ++p)
                #pragma unroll
                for (int e = 0; e < 2; ++e) {
                    const int ni = p * 2 + e;
                    uint32_t bhf[2] = { bh[p][e], bh[p][e + 2] };
                    uint32_t blf[2] = { bl[p][e], bl[p][e + 2] };
                    #pragma unroll
                    for (int mi = 0; mi < 2; ++mi) {
                        mma_f16(accm[mi][ni], ah[mi], bhf);
                        mma_f16(accc[mi][ni], ah[mi], blf);
                        mma_f16(accc[mi][ni], al[mi], bhf);
                    }
                }
        }
    }

    const float rescale = 1.0f / 2048.0f;
    #pragma unroll
    for (int mi = 0; mi < 2; ++mi) {
        #pragma unroll
        for (int ni = 0; ni < 4; ++ni) {
            const int row0 = blockIdx.y * 128 + wm * 32 + mi * 16 + g;
            const int col0 = blockIdx.x * 64 + wn * 32 + ni * 8 + 2 * tig;
            const float bx = bias[col0], by = bias[col0 + 1];
            const float v00 = accm[mi][ni][0] + accc[mi][ni][0] * rescale + bx;
            const float v01 = accm[mi][ni][1] + accc[mi][ni][1] * rescale + by;
            const float v10 = accm[mi][ni][2] + accc[mi][ni][2] * rescale + bx;
            const float v11 = accm[mi][ni][3] + accc[mi][ni][3] * rescale + by;
            if (mode == 0) {
                if (z < 2) {
                    float* dst = z ? g_k : g_q;
                    const int h = col0 >> 6, d = col0 & 63;
                    *(float2*)(dst + ((size_t)h * S_TOTC + (s_off + row0)) * DHC + d) =
                        make_float2(v00, v01);
                    *(float2*)(dst + ((size_t)h * S_TOTC + (s_off + row0 + 8)) * DHC + d) =
                        make_float2(v10, v11);
                } else {
                    const int s0 = s_off + row0;
                    #pragma unroll
                    for (int e = 0; e < 2; ++e) {
                        const float va = e ? v01 : v00;
                        const float vb = e ? v11 : v10;
                        const size_t base = (size_t)(col0 + e) * S_TOTC;
                        const __half ha = __float2half_rn(va);
                        const __half hb = __float2half_rn(vb);
                        g_vh[base + s0]     = ha;
                        g_vh[base + s0 + 8] = hb;
                        g_vl[base + s0]     = __float2half_rn(va - __half2float(ha));
                        g_vl[base + s0 + 8] = __float2half_rn(vb - __half2float(hb));
                    }
                }
            } else {
                *(float2*)(outp + (size_t)row0 * DC + col0) = make_float2(v00, v01);
                *(float2*)(outp + (size_t)(row0 + 8) * DC + col0) = make_float2(v10, v11);
            }
        }
    }
}

// ---------------------------------------------------------------------------
// RMS-norm + RoPE; emits fp16 q (pre-scaled by DH^-0.5) and fp16 k.
// ---------------------------------------------------------------------------
__global__ __launch_bounds__(256) void rmsrope2(
    const float* __restrict__ cosb, const float* __restrict__ sinb,
    const float* __restrict__ gaq, const float* __restrict__ gq,
    const float* __restrict__ gak, const float* __restrict__ gk)
{
    const int z = blockIdx.z;
    const float* buf = z ? g_k : g_q;
    __half* outh = z ? g_kh : g_qh;
    const int s = blockIdx.x * 8 + (threadIdx.x >> 5);
    const int h = blockIdx.y;
    const int t = threadIdx.x & 31;

    const float* p = buf + ((size_t)h * S_TOTC + s) * DHC;
    float2 x = *(const float2*)(p + 2 * t);
    float ss = x.x * x.x + x.y * x.y;
    #pragma unroll
    for (int o = 16; o; o >>= 1) ss += __shfl_xor_sync(0xffffffffu, ss, o);
    const float r = rsqrtf(ss * (1.0f / 64.0f) + 1e-6f);
    const float* gg = z ? ((s < S_TXTC) ? gak : gk) : ((s < S_TXTC) ? gaq : gq);
    const float y0 = x.x * r * gg[2 * t];
    const float y1 = x.y * r * gg[2 * t + 1];
    const float c  = cosb[s * 64 + 2 * t];
    const float sn = sinb[s * 64 + 2 * t];
    float o0 = y0 * c - y1 * sn;
    float o1 = y1 * c + y0 * sn;
    if (z == 0) { o0 *= 0.125f; o1 *= 0.125f; }
    *(uint32_t*)(outh + ((size_t)h * S_TOTC + s) * DHC + 2 * t) = packh2(o0, o1);
}

// ---------------------------------------------------------------------------
// fp16 flash attention: cp.async double-buffered K/V, register-resident P,
// fused fp16-split epilogue (writes g_aoh/g_aol directly).
// Dynamic smem layout (u32 units):
//   sQ   [128][36] @ 0          (4608)
//   stage st in {0,1}: K [64][36] @ 4608+st*6912
//                      Vh[64][36] @ 4608+st*6912+2304
//                      Vl[64][36] @ 4608+st*6912+4608
// total 18432 u32 = 73728 B.
// ---------------------------------------------------------------------------
#define AQ_U32   0u
#define AK_U32(st)   (4608u + (uint32_t)(st) * 6912u)
#define AVH_U32(st)  (4608u + (uint32_t)(st) * 6912u + 2304u)
#define AVL_U32(st)  (4608u + (uint32_t)(st) * 6912u + 4608u)
#define ATT_SMEM (18432 * 4)
#define NKT (S_TOTC / 64)

__global__ __launch_bounds__(128, 2) void attn_h()
{
    extern __shared__ uint32_t dynsm[];
    const uint32_t smb = (uint32_t)__cvta_generic_to_shared(dynsm);

    const int h = blockIdx.y, qt = blockIdx.x;
    const int tid = threadIdx.x;
    const int w = tid >> 5, lane = tid & 31, g = lane >> 2, tig = lane & 3;
    const int wr = w * 32;
    const int lr16 = lane & 15, lch = lane >> 4;

    const __half* khb = g_kh + (size_t)h * S_TOTC * DHC;
    const __half* vhb = g_vh + (size_t)h * DHC * S_TOTC;
    const __half* vlb = g_vl + (size_t)h * DHC * S_TOTC;

    // K/V stage loader: 512 chunks each of K/Vh/Vl -> 12 cp16 per thread
    auto load_stage = [&](int st, int kt) {
        #pragma unroll
        for (int i = tid; i < 512; i += 128) {
            const int row = i >> 3, j = i & 7;
            cp16(smb + (AK_U32(st) + (uint32_t)(row * 36 + j * 4)) * 4,
                 khb + (size_t)(kt * 64 + row) * 64 + j * 8);
        }
        #pragma unroll
        for (int u = tid; u < 512; u += 128) {
            const int d = u >> 3, j = u & 7;
            const size_t off = (size_t)d * S_TOTC + kt * 64 + j * 8;
            cp16(smb + (AVH_U32(st) + (uint32_t)(d * 36 + j * 4)) * 4, vhb + off);
            cp16(smb + (AVL_U32(st) + (uint32_t)(d * 36 + j * 4)) * 4, vlb + off);
        }
    };

    // Stage Q while first K/V stage is in flight
    load_stage(0, 0);
    asm volatile("cp.async.commit_group;" ::: "memory");

    const __half* qhb = g_qh + ((size_t)h * S_TOTC + qt * 128) * DHC;
    for (int i = tid; i < 1024; i += 128) {
        const int row = i >> 3, j = i & 7;
        *(uint4*)&dynsm[AQ_U32 + row * 36 + j * 4] = *(const uint4*)(qhb + row * 64 + j * 8);
    }

    float oacc[4][4][4] = {};
    float mrow[4] = {-1e30f, -1e30f, -1e30f, -1e30f};
    float lrow[4] = {0.f, 0.f, 0.f, 0.f};

    for (int kt = 0; kt < NKT; ++kt) {
        __syncthreads();   // prior compute done with buffer (kt+1)&1
        if (kt + 1 < NKT) load_stage((kt + 1) & 1, kt + 1);
        asm volatile("cp.async.commit_group;" ::: "memory");
        if (kt + 1 < NKT) { asm volatile("cp.async.wait_group 1;" ::: "memory"); }
        else              { asm volatile("cp.async.wait_group 0;" ::: "memory"); }
        __syncthreads();

        const uint32_t sbK  = smb + AK_U32(kt & 1) * 4;
        const uint32_t sbVh = smb + AVH_U32(kt & 1) * 4;
        const uint32_t sbVl = smb + AVL_U32(kt & 1) * 4;
        const uint32_t sbQ  = smb;

        // ---- S = Q K^T ----
        float sfrag[2][8][4] = {};
        #pragma unroll
        for (int kk2 = 0; kk2 < 32; kk2 += 8) {
            const uint32_t co = (uint32_t)(kk2 + lch * 4) * 4;
            uint32_t a[2][4];
            ldsm4s(a[0], sbQ + (uint32_t)(wr + lr16) * 144 + co);
            ldsm4s(a[1], sbQ + (uint32_t)(wr + 16 + lr16) * 144 + co);
            #pragma unroll
            for (int p = 0; p < 4; ++p) {
                uint32_t bb[4];
                ldsm4s(bb, sbK + (uint32_t)(p * 16 + lr16) * 144 + co);
                #pragma unroll
                for (int e = 0; e < 2; ++e) {
                    uint32_t bf[2] = { bb[e], bb[e + 2] };
                    mma_f16(sfrag[0][p * 2 + e], a[0], bf);
                    mma_f16(sfrag[1][p * 2 + e], a[1], bf);
                }
            }
        }

        // ---- online softmax; register P ----
        uint32_t ph[2][8][2];
        float corrv[4];
        #pragma unroll
        for (int f = 0; f < 4; ++f) {
            const int mi = f >> 1, cb = (f & 1) << 1;
            float mx = mrow[f];
            #pragma unroll
            for (int ni = 0; ni < 8; ++ni)
                mx = fmaxf(mx, fmaxf(sfrag[mi][ni][cb], sfrag[mi][ni][cb + 1]));
            mx = fmaxf(mx, __shfl_xor_sync(0xffffffffu, mx, 1));
            mx = fmaxf(mx, __shfl_xor_sync(0xffffffffu, mx, 2));
            corrv[f] = __expf(mrow[f] - mx);
            mrow[f] = mx;
            float sum = 0.f;
            #pragma unroll
            for (int ni = 0; ni < 8; ++ni) {
                const float p0 = __expf(sfrag[mi][ni][cb]     - mx);
                const float p1 = __expf(sfrag[mi][ni][cb + 1] - mx);
                sum += p0 + p1;
                ph[mi][ni][f & 1] = packh2(p0, p1);
            }
            sum += __shfl_xor_sync(0xffffffffu, sum, 1);
            sum += __shfl_xor_sync(0xffffffffu, sum, 2);
            lrow[f] = lrow[f] * corrv[f] + sum;
        }

        #pragma unroll
        for (int qb = 0; qb < 4; ++qb) {
            const float cA = __shfl_sync(0xffffffffu, corrv[qb], 8 * tig);
            const float cB = __shfl_sync(0xffffffffu, corrv[qb], 8 * tig + 4);
            #pragma unroll
            for (int md = 0; md < 4; ++md) {
                oacc[md][qb][0] *= cA; oacc[md][qb][1] *= cB;
                oacc[md][qb][2] *= cA; oacc[md][qb][3] *= cB;
            }
        }

        // ---- O^T += V^T P^T ----
        #pragma unroll
        for (int kk2 = 0; kk2 < 32; kk2 += 8) {
            const int ni0 = kk2 >> 2;
            const uint32_t co = (uint32_t)(kk2 + lch * 4) * 4;
            uint32_t av[4][4], avl[4][4];
            #pragma unroll
            for (int md = 0; md < 4; ++md) {
                ldsm4s(av[md],  sbVh + (uint32_t)(md * 16 + lr16) * 144 + co);
                ldsm4s(avl[md], sbVl + (uint32_t)(md * 16 + lr16) * 144 + co);
            }
            #pragma unroll
            for (int qb = 0; qb < 4; ++qb) {
                uint32_t b[2] = { ph[qb >> 1][ni0][qb & 1], ph[qb >> 1][ni0 + 1][qb & 1] };
                #pragma unroll
                for (int md = 0; md < 4; ++md) {
                    mma_f16(oacc[md][qb], av[md], b);
                    mma_f16(oacc[md][qb], avl[md], b);
                }
            }
        }
    }

    // ---- fused epilogue: O = (O^T)^T / l, split to fp16 h/l directly ----
    #pragma unroll
    for (int qb = 0; qb < 4; ++qb) {
        const float lA = __shfl_sync(0xffffffffu, lrow[qb], 8 * tig);
        const float lB = __shfl_sync(0xffffffffu, lrow[qb], 8 * tig + 4);
        const float iA = 1.0f / lA, iB = 1.0f / lB;
        const int q0 = qt * 128 + wr + qb * 8 + 2 * tig;
        #pragma unroll
        for (int md = 0; md < 4; ++md) {
            const int d0 = h * 64 + md * 16 + g;
            const float v00 = oacc[md][qb][0] * iA;
            const float v01 = oacc[md][qb][1] * iB;
            const float v10 = oacc[md][qb][2] * iA;
            const float v11 = oacc[md][qb][3] * iB;
            const __half h00 = __float2half_rn(v00), h01 = __float2half_rn(v01);
            const __half h10 = __float2half_rn(v10), h11 = __float2half_rn(v11);
            g_aoh[(size_t)q0 * DC + d0]           = h00;
            g_aoh[(size_t)(q0 + 1) * DC + d0]     = h01;
            g_aoh[(size_t)q0 * DC + d0 + 8]       = h10;
            g_aoh[(size_t)(q0 + 1) * DC + d0 + 8] = h11;
            g_aol[(size_t)q0 * DC + d0]           = __float2half_rn((v00 - __half2float(h00)) * 2048.f);
            g_aol[(size_t)(q0 + 1) * DC + d0]     = __float2half_rn((v01 - __half2float(h01)) * 2048.f);
            g_aol[(size_t)q0 * DC + d0 + 8]       = __float2half_rn((v10 - __half2float(h10)) * 2048.f);
            g_aol[(size_t)(q0 + 1) * DC + d0 + 8] = __float2half_rn((v11 - __half2float(h11)) * 2048.f);
        }
    }
}

// ---------------------------------------------------------------------------
extern "C" void kernel_launch(void* const* d_in, const int* in_sizes, int n_in,
                              void* d_out, int out_size)
{
    (void)in_sizes; (void)n_in; (void)out_size;
    const float* hs  = (const float*)d_in[0];
    const float* ehs = (const float*)d_in[1];
    const float* rc  = (const float*)d_in[2];
    const float* rs  = (const float*)d_in[3];
    const float* bq  = (const float*)d_in[5];
    const float* bk  = (const float*)d_in[7];
    const float* bv  = (const float*)d_in[9];
    const float* baq = (const float*)d_in[11];
    const float* bak = (const float*)d_in[13];
    const float* bav = (const float*)d_in[15];
    const float* bo  = (const float*)d_in[17];
    const float* bao = (const float*)d_in[19];
    const float* gq  = (const float*)d_in[20];
    const float* gk  = (const float*)d_in[21];
    const float* gaq = (const float*)d_in[22];
    const float* gak = (const float*)d_in[23];
    float* out = (float*)d_out;

    __half *xh, *xl, *wh, *wl, *aoh, *aol;
    cudaGetSymbolAddress((void**)&xh,  g_xh);
    cudaGetSymbolAddress((void**)&xl,  g_xl);
    cudaGetSymbolAddress((void**)&wh,  g_wh);
    cudaGetSymbolAddress((void**)&wl,  g_wl);
    cudaGetSymbolAddress((void**)&aoh, g_aoh);
    cudaGetSymbolAddress((void**)&aol, g_aol);

    const int gemm_smem = 3 * 30720;
    cudaFuncSetAttribute(gemm_h3, cudaFuncAttributeMaxDynamicSharedMemorySize, gemm_smem);
    cudaFuncSetAttribute(attn_h, cudaFuncAttributeMaxDynamicSharedMemorySize, ATT_SMEM);

    SplitJobs jobs;
    jobs.j[0] = { hs,  xh,                       xl,                       S_IMGC * DC };
    jobs.j[1] = { ehs, xh + (size_t)S_IMGC * DC, xl + (size_t)S_IMGC * DC, S_TXTC * DC };
    const int wsrc[8] = {4, 6, 8, 10, 12, 14, 16, 18};
    for (int i = 0; i < 8; ++i)
        jobs.j[2 + i] = { (const float*)d_in[wsrc[i]],
                          wh + (size_t)i * WELEM, wl + (size_t)i * WELEM, WELEM };
    {
        dim3 grid((S_IMGC * DC / 4 + 255) / 256, 10);
        split_kernel<<<grid, 256>>>(jobs);
    }

    gemm_h3<<<dim3(DC / 64, S_IMGC / 128, 3), 256, gemm_smem>>>(
        xh, xl, 0, 1, 2, bq, bk, bv, nullptr, 512, 0);
    gemm_h3<<<dim3(DC / 64, S_TXTC / 128, 3), 256, gemm_smem>>>(
        xh + (size_t)S_IMGC * DC, xl + (size_t)S_IMGC * DC,
        3, 4, 5, baq, bak, bav, nullptr, 0, 0);

    rmsrope2<<<dim3(S_TOTC / 8, HC, 2), 256>>>(rc, rs, gaq, gq, gak, gk);

    attn_h<<<dim3(S_TOTC / 128, HC), 128, ATT_SMEM>>>();

    gemm_h3<<<dim3(DC / 64, S_IMGC / 128, 1), 256, gemm_smem>>>(
        aoh + (size_t)S_TXTC * DC, aol + (size_t)S_TXTC * DC,
        6, 6, 6, bo, bo, bo, out, 0, 1);
    gemm_h3<<<dim3(DC / 64, S_TXTC / 128, 1), 256, gemm_smem>>>(
        aoh, aol, 7, 7, 7, bao, bao, bao, out + (size_t)S_IMGC * DC, 0, 1);
}

// round 12
// speedup vs baseline: 6.8099x; 1.3420x over previous
#include <cuda_runtime.h>
#include <cuda_fp16.h>
#include <math.h>
#include <stdint.h>

#define S_IMGC 2048
#define S_TXTC 512
#define S_TOTC 2560
#define DC     1536
#define HC     24
#define DHC    64
#define WELEM  (DC * DC)

// ---------------- device scratch (allocation-free rule) ----------------
__device__ float  g_q [(size_t)HC * S_TOTC * DHC];
__device__ float  g_k [(size_t)HC * S_TOTC * DHC];
__device__ __half g_qh[(size_t)HC * S_TOTC * DHC];   // fp16, pre-scaled by 0.125
__device__ __half g_kh[(size_t)HC * S_TOTC * DHC];
__device__ __half g_vh[(size_t)HC * DHC * S_TOTC];   // [h][d][s] transposed
__device__ __half g_vl[(size_t)HC * DHC * S_TOTC];   // residual
__device__ __half g_xh[(size_t)S_TOTC * DC];
__device__ __half g_wh[(size_t)8 * WELEM];
__device__ __half g_wl[(size_t)8 * WELEM];
__device__ __half g_aoh[(size_t)S_TOTC * DC];

__device__ __forceinline__ uint32_t packh2(float a, float b) {
    __half2 h = __floats2half2_rn(a, b);
    return *(uint32_t*)&h;
}

__device__ __forceinline__ void mma_f16(float* c, const uint32_t* a, const uint32_t* b) {
    asm volatile(
        "mma.sync.aligned.m16n8k16.row.col.f32.f16.f16.f32 "
        "{%0,%1,%2,%3}, {%4,%5,%6,%7}, {%8,%9}, {%0,%1,%2,%3};"
        : "+f"(c[0]), "+f"(c[1]), "+f"(c[2]), "+f"(c[3])
        : "r"(a[0]), "r"(a[1]), "r"(a[2]), "r"(a[3]), "r"(b[0]), "r"(b[1]));
}

__device__ __forceinline__ void ldsm4s(uint32_t* r, uint32_t saddr) {
    asm volatile("ldmatrix.sync.aligned.m8n8.x4.shared.b16 {%0,%1,%2,%3}, [%4];"
        : "=r"(r[0]), "=r"(r[1]), "=r"(r[2]), "=r"(r[3]) : "r"(saddr));
}

__device__ __forceinline__ void cp16(uint32_t s, const void* g) {
    asm volatile("cp.async.ca.shared.global [%0], [%1], 16;" :: "r"(s), "l"(g));
}

// ---------------------------------------------------------------------------
// Elementwise fp32 -> fp16 h (+ optional l = residual*2048) split.
// ---------------------------------------------------------------------------
struct SplitJob  { const float* s; __half* h; __half* l; int n; };
struct SplitJobs { SplitJob j[10]; };

__global__ __launch_bounds__(256) void split_kernel(SplitJobs jobs) {
    const SplitJob J = jobs.j[blockIdx.y];
    const int i = (blockIdx.x * 256 + threadIdx.x) * 4;
    if (i >= J.n) return;
    const float4 v = *(const float4*)(J.s + i);
    const __half h0 = __float2half_rn(v.x), h1 = __float2half_rn(v.y);
    const __half h2 = __float2half_rn(v.z), h3 = __float2half_rn(v.w);
    uint2 hw;
    { __half2 p0 = __halves2half2(h0, h1), p1 = __halves2half2(h2, h3);
      hw.x = *(uint32_t*)&p0; hw.y = *(uint32_t*)&p1; }
    *(uint2*)(J.h + i) = hw;
    if (J.l) {
        const float r0 = (v.x - __half2float(h0)) * 2048.f;
        const float r1 = (v.y - __half2float(h1)) * 2048.f;
        const float r2 = (v.z - __half2float(h2)) * 2048.f;
        const float r3 = (v.w - __half2float(h3)) * 2048.f;
        uint2 lw;
        lw.x = packh2(r0, r1); lw.y = packh2(r2, r3);
        *(uint2*)(J.l + i) = lw;
    }
}

// ---------------------------------------------------------------------------
// fp16x2 GEMM (weight residual corrected; activations single fp16):
// C = Xh*(Wh + Wl/2048)^T + bias.  cp.async 4-stage pipeline, BK=32.
// Block 128(M) x 64(N), 256 threads (8 warps), warp tile 32x32.
// Stage layout (bytes, row stride 80): AH[128] @0, BH[64] @10240, BL[64] @15360.
// ---------------------------------------------------------------------------
#define GST_AH 0u
#define GST_BH 10240u
#define GST_BL 15360u
#define GST_SZ 20480u
#define GNK    (DC / 32)

__global__ __launch_bounds__(256, 2) void gemm_h2(
    const __half* __restrict__ Xh,
    int w0, int w1, int w2,
    const float* __restrict__ b0, const float* __restrict__ b1, const float* __restrict__ b2,
    float* __restrict__ outp, int s_off, int mode)
{
    extern __shared__ uint32_t dynsm[];
    const uint32_t smb = (uint32_t)__cvta_generic_to_shared(dynsm);

    const int z = blockIdx.z;
    const int widx    = (z == 0) ? w0 : (z == 1) ? w1 : w2;
    const float* bias = (z == 0) ? b0 : (z == 1) ? b1 : b2;

    const int tid = threadIdx.x, wid = tid >> 5, lane = tid & 31;
    const int g = lane >> 2, tig = lane & 3;
    const int wm = wid & 3, wn = wid >> 2;
    const int lr16 = lane & 15, lch = lane >> 4;

    const int ldrow = tid >> 2;
    const int ldc   = tid & 3;

    const __half* AhG = Xh + (size_t)(blockIdx.y * 128 + ldrow) * DC + ldc * 8;
    const __half* BhG = g_wh + (size_t)widx * WELEM + (size_t)(blockIdx.x * 64 + ldrow) * DC + ldc * 8;
    const __half* BlG = g_wl + (size_t)widx * WELEM + (size_t)(blockIdx.x * 64 + ldrow) * DC + ldc * 8;
    const size_t rstep = (size_t)64 * DC;

    float accm[2][4][4] = {}, accc[2][4][4] = {};

    auto load_stage = [&](int st, int kt) {
        const uint32_t sb = smb + (uint32_t)st * GST_SZ;
        const uint32_t ro = (uint32_t)ldrow * 80 + (uint32_t)ldc * 16;
        const size_t go = (size_t)kt * 32;
        cp16(sb + GST_AH + ro,           AhG + go);
        cp16(sb + GST_AH + ro + 64 * 80, AhG + go + rstep);
        cp16(sb + GST_BH + ro,           BhG + go);
        cp16(sb + GST_BL + ro,           BlG + go);
    };

    load_stage(0, 0);
    asm volatile("cp.async.commit_group;" ::: "memory");
    load_stage(1, 1);
    asm volatile("cp.async.commit_group;" ::: "memory");
    load_stage(2, 2);
    asm volatile("cp.async.commit_group;" ::: "memory");

    for (int kt = 0; kt < GNK; ++kt) {
        asm volatile("cp.async.wait_group 2;" ::: "memory");
        __syncthreads();
        if (kt + 3 < GNK) load_stage((kt + 3) & 3, kt + 3);
        asm volatile("cp.async.commit_group;" ::: "memory");

        const uint32_t sb = smb + (uint32_t)(kt & 3) * GST_SZ;
        const uint32_t arow0 = (uint32_t)(wm * 32 + lr16) * 80;
        const uint32_t arow1 = (uint32_t)(wm * 32 + 16 + lr16) * 80;
        const uint32_t brow0 = (uint32_t)(wn * 32 + lr16) * 80;
        const uint32_t brow1 = (uint32_t)(wn * 32 + 16 + lr16) * 80;

        #pragma unroll
        for (int ks = 0; ks < 16; ks += 8) {
            const uint32_t co = (uint32_t)(ks + lch * 4) * 4;
            uint32_t ah[2][4], bh[2][4], bl[2][4];
            ldsm4s(ah[0], sb + GST_AH + arow0 + co);
            ldsm4s(ah[1], sb + GST_AH + arow1 + co);
            ldsm4s(bh[0], sb + GST_BH + brow0 + co);
            ldsm4s(bh[1], sb + GST_BH + brow1 + co);
            ldsm4s(bl[0], sb + GST_BL + brow0 + co);
            ldsm4s(bl[1], sb + GST_BL + brow1 + co);

            #pragma unroll
            for (int p = 0; p < 2; ++p)
                #pragma unroll
                for (int e = 0; e < 2; ++e) {
                    const int ni = p * 2 + e;
                    uint32_t bhf[2] = { bh[p][e], bh[p][e + 2] };
                    uint32_t blf[2] = { bl[p][e], bl[p][e + 2] };
                    #pragma unroll
                    for (int mi = 0; mi < 2; ++mi) {
                        mma_f16(accm[mi][ni], ah[mi], bhf);
                        mma_f16(accc[mi][ni], ah[mi], blf);
                    }
                }
        }
    }

    const float rescale = 1.0f / 2048.0f;
    #pragma unroll
    for (int mi = 0; mi < 2; ++mi) {
        #pragma unroll
        for (int ni = 0; ni < 4; ++ni) {
            const int row0 = blockIdx.y * 128 + wm * 32 + mi * 16 + g;
            const int col0 = blockIdx.x * 64 + wn * 32 + ni * 8 + 2 * tig;
            const float bx = bias[col0], by = bias[col0 + 1];
            const float v00 = accm[mi][ni][0] + accc[mi][ni][0] * rescale + bx;
            const float v01 = accm[mi][ni][1] + accc[mi][ni][1] * rescale + by;
            const float v10 = accm[mi][ni][2] + accc[mi][ni][2] * rescale + bx;
            const float v11 = accm[mi][ni][3] + accc[mi][ni][3] * rescale + by;
            if (mode == 0) {
                if (z < 2) {
                    float* dst = z ? g_k : g_q;
                    const int h = col0 >> 6, d = col0 & 63;
                    *(float2*)(dst + ((size_t)h * S_TOTC + (s_off + row0)) * DHC + d) =
                        make_float2(v00, v01);
                    *(float2*)(dst + ((size_t)h * S_TOTC + (s_off + row0 + 8)) * DHC + d) =
                        make_float2(v10, v11);
                } else {
                    const int s0 = s_off + row0;
                    #pragma unroll
                    for (int e = 0; e < 2; ++e) {
                        const float va = e ? v01 : v00;
                        const float vb = e ? v11 : v10;
                        const size_t base = (size_t)(col0 + e) * S_TOTC;
                        const __half ha = __float2half_rn(va);
                        const __half hb = __float2half_rn(vb);
                        g_vh[base + s0]     = ha;
                        g_vh[base + s0 + 8] = hb;
                        g_vl[base + s0]     = __float2half_rn(va - __half2float(ha));
                        g_vl[base + s0 + 8] = __float2half_rn(vb - __half2float(hb));
                    }
                }
            } else {
                *(float2*)(outp + (size_t)row0 * DC + col0) = make_float2(v00, v01);
                *(float2*)(outp + (size_t)(row0 + 8) * DC + col0) = make_float2(v10, v11);
            }
        }
    }
}

// ---------------------------------------------------------------------------
// RMS-norm + RoPE; emits fp16 q (pre-scaled by DH^-0.5) and fp16 k.
// ---------------------------------------------------------------------------
__global__ __launch_bounds__(256) void rmsrope2(
    const float* __restrict__ cosb, const float* __restrict__ sinb,
    const float* __restrict__ gaq, const float* __restrict__ gq,
    const float* __restrict__ gak, const float* __restrict__ gk)
{
    const int z = blockIdx.z;
    const float* buf = z ? g_k : g_q;
    __half* outh = z ? g_kh : g_qh;
    const int s = blockIdx.x * 8 + (threadIdx.x >> 5);
    const int h = blockIdx.y;
    const int t = threadIdx.x & 31;

    const float* p = buf + ((size_t)h * S_TOTC + s) * DHC;
    float2 x = *(const float2*)(p + 2 * t);
    float ss = x.x * x.x + x.y * x.y;
    #pragma unroll
    for (int o = 16; o; o >>= 1) ss += __shfl_xor_sync(0xffffffffu, ss, o);
    const float r = rsqrtf(ss * (1.0f / 64.0f) + 1e-6f);
    const float* gg = z ? ((s < S_TXTC) ? gak : gk) : ((s < S_TXTC) ? gaq : gq);
    const float y0 = x.x * r * gg[2 * t];
    const float y1 = x.y * r * gg[2 * t + 1];
    const float c  = cosb[s * 64 + 2 * t];
    const float sn = sinb[s * 64 + 2 * t];
    float o0 = y0 * c - y1 * sn;
    float o1 = y1 * c + y0 * sn;
    if (z == 0) { o0 *= 0.125f; o1 *= 0.125f; }
    *(uint32_t*)(outh + ((size_t)h * S_TOTC + s) * DHC + 2 * t) = packh2(o0, o1);
}

// ---------------------------------------------------------------------------
// fp16 flash attention: cp.async double-buffered K/V, register-resident P,
// epilogue writes fp16 g_aoh directly (out-proj is 2-pass, no A residual).
// ---------------------------------------------------------------------------
#define AQ_U32   0u
#define AK_U32(st)   (4608u + (uint32_t)(st) * 6912u)
#define AVH_U32(st)  (4608u + (uint32_t)(st) * 6912u + 2304u)
#define AVL_U32(st)  (4608u + (uint32_t)(st) * 6912u + 4608u)
#define ATT_SMEM (18432 * 4)
#define NKT (S_TOTC / 64)

__global__ __launch_bounds__(128, 2) void attn_h()
{
    extern __shared__ uint32_t dynsm[];
    const uint32_t smb = (uint32_t)__cvta_generic_to_shared(dynsm);

    const int h = blockIdx.y, qt = blockIdx.x;
    const int tid = threadIdx.x;
    const int w = tid >> 5, lane = tid & 31, g = lane >> 2, tig = lane & 3;
    const int wr = w * 32;
    const int lr16 = lane & 15, lch = lane >> 4;

    const __half* khb = g_kh + (size_t)h * S_TOTC * DHC;
    const __half* vhb = g_vh + (size_t)h * DHC * S_TOTC;
    const __half* vlb = g_vl + (size_t)h * DHC * S_TOTC;

    auto load_stage = [&](int st, int kt) {
        #pragma unroll
        for (int i = tid; i < 512; i += 128) {
            const int row = i >> 3, j = i & 7;
            cp16(smb + (AK_U32(st) + (uint32_t)(row * 36 + j * 4)) * 4,
                 khb + (size_t)(kt * 64 + row) * 64 + j * 8);
        }
        #pragma unroll
        for (int u = tid; u < 512; u += 128) {
            const int d = u >> 3, j = u & 7;
            const size_t off = (size_t)d * S_TOTC + kt * 64 + j * 8;
            cp16(smb + (AVH_U32(st) + (uint32_t)(d * 36 + j * 4)) * 4, vhb + off);
            cp16(smb + (AVL_U32(st) + (uint32_t)(d * 36 + j * 4)) * 4, vlb + off);
        }
    };

    load_stage(0, 0);
    asm volatile("cp.async.commit_group;" ::: "memory");

    const __half* qhb = g_qh + ((size_t)h * S_TOTC + qt * 128) * DHC;
    for (int i = tid; i < 1024; i += 128) {
        const int row = i >> 3, j = i & 7;
        *(uint4*)&dynsm[AQ_U32 + row * 36 + j * 4] = *(const uint4*)(qhb + row * 64 + j * 8);
    }

    float oacc[4][4][4] = {};
    float mrow[4] = {-1e30f, -1e30f, -1e30f, -1e30f};
    float lrow[4] = {0.f, 0.f, 0.f, 0.f};

    for (int kt = 0; kt < NKT; ++kt) {
        __syncthreads();
        if (kt + 1 < NKT) load_stage((kt + 1) & 1, kt + 1);
        asm volatile("cp.async.commit_group;" ::: "memory");
        if (kt + 1 < NKT) { asm volatile("cp.async.wait_group 1;" ::: "memory"); }
        else              { asm volatile("cp.async.wait_group 0;" ::: "memory"); }
        __syncthreads();

        const uint32_t sbK  = smb + AK_U32(kt & 1) * 4;
        const uint32_t sbVh = smb + AVH_U32(kt & 1) * 4;
        const uint32_t sbVl = smb + AVL_U32(kt & 1) * 4;
        const uint32_t sbQ  = smb;

        // ---- S = Q K^T ----
        float sfrag[2][8][4] = {};
        #pragma unroll
        for (int kk2 = 0; kk2 < 32; kk2 += 8) {
            const uint32_t co = (uint32_t)(kk2 + lch * 4) * 4;
            uint32_t a[2][4];
            ldsm4s(a[0], sbQ + (uint32_t)(wr + lr16) * 144 + co);
            ldsm4s(a[1], sbQ + (uint32_t)(wr + 16 + lr16) * 144 + co);
            #pragma unroll
            for (int p = 0; p < 4; ++p) {
                uint32_t bb[4];
                ldsm4s(bb, sbK + (uint32_t)(p * 16 + lr16) * 144 + co);
                #pragma unroll
                for (int e = 0; e < 2; ++e) {
                    uint32_t bf[2] = { bb[e], bb[e + 2] };
                    mma_f16(sfrag[0][p * 2 + e], a[0], bf);
                    mma_f16(sfrag[1][p * 2 + e], a[1], bf);
                }
            }
        }

        // ---- online softmax; register P ----
        uint32_t ph[2][8][2];
        float corrv[4];
        #pragma unroll
        for (int f = 0; f < 4; ++f) {
            const int mi = f >> 1, cb = (f & 1) << 1;
            float mx = mrow[f];
            #pragma unroll
            for (int ni = 0; ni < 8; ++ni)
                mx = fmaxf(mx, fmaxf(sfrag[mi][ni][cb], sfrag[mi][ni][cb + 1]));
            mx = fmaxf(mx, __shfl_xor_sync(0xffffffffu, mx, 1));
            mx = fmaxf(mx, __shfl_xor_sync(0xffffffffu, mx, 2));
            corrv[f] = __expf(mrow[f] - mx);
            mrow[f] = mx;
            float sum = 0.f;
            #pragma unroll
            for (int ni = 0; ni < 8; ++ni) {
                const float p0 = __expf(sfrag[mi][ni][cb]     - mx);
                const float p1 = __expf(sfrag[mi][ni][cb + 1] - mx);
                sum += p0 + p1;
                ph[mi][ni][f & 1] = packh2(p0, p1);
            }
            sum += __shfl_xor_sync(0xffffffffu, sum, 1);
            sum += __shfl_xor_sync(0xffffffffu, sum, 2);
            lrow[f] = lrow[f] * corrv[f] + sum;
        }

        #pragma unroll
        for (int qb = 0; qb < 4; ++qb) {
            const float cA = __shfl_sync(0xffffffffu, corrv[qb], 8 * tig);
            const float cB = __shfl_sync(0xffffffffu, corrv[qb], 8 * tig + 4);
            #pragma unroll
            for (int md = 0; md < 4; ++md) {
                oacc[md][qb][0] *= cA; oacc[md][qb][1] *= cB;
                oacc[md][qb][2] *= cA; oacc[md][qb][3] *= cB;
            }
        }

        // ---- O^T += V^T P^T ----
        #pragma unroll
        for (int kk2 = 0; kk2 < 32; kk2 += 8) {
            const int ni0 = kk2 >> 2;
            const uint32_t co = (uint32_t)(kk2 + lch * 4) * 4;
            uint32_t av[4][4], avl[4][4];
            #pragma unroll
            for (int md = 0; md < 4; ++md) {
                ldsm4s(av[md],  sbVh + (uint32_t)(md * 16 + lr16) * 144 + co);
                ldsm4s(avl[md], sbVl + (uint32_t)(md * 16 + lr16) * 144 + co);
            }
            #pragma unroll
            for (int qb = 0; qb < 4; ++qb) {
                uint32_t b[2] = { ph[qb >> 1][ni0][qb & 1], ph[qb >> 1][ni0 + 1][qb & 1] };
                #pragma unroll
                for (int md = 0; md < 4; ++md) {
                    mma_f16(oacc[md][qb], av[md], b);
                    mma_f16(oacc[md][qb], avl[md], b);
                }
            }
        }
    }

    // ---- epilogue: O = (O^T)^T / l, fp16 out ----
    #pragma unroll
    for (int qb = 0; qb < 4; ++qb) {
        const float lA = __shfl_sync(0xffffffffu, lrow[qb], 8 * tig);
        const float lB = __shfl_sync(0xffffffffu, lrow[qb], 8 * tig + 4);
        const float iA = 1.0f / lA, iB = 1.0f / lB;
        const int q0 = qt * 128 + wr + qb * 8 + 2 * tig;
        #pragma unroll
        for (int md = 0; md < 4; ++md) {
            const int d0 = h * 64 + md * 16 + g;
            g_aoh[(size_t)q0 * DC + d0]           = __float2half_rn(oacc[md][qb][0] * iA);
            g_aoh[(size_t)(q0 + 1) * DC + d0]     = __float2half_rn(oacc[md][qb][1] * iB);
            g_aoh[(size_t)q0 * DC + d0 + 8]       = __float2half_rn(oacc[md][qb][2] * iA);
            g_aoh[(size_t)(q0 + 1) * DC + d0 + 8] = __float2half_rn(oacc[md][qb][3] * iB);
        }
    }
}

// ---------------------------------------------------------------------------
extern "C" void kernel_launch(void* const* d_in, const int* in_sizes, int n_in,
                              void* d_out, int out_size)
{
    (void)in_sizes; (void)n_in; (void)out_size;
    const float* hs  = (const float*)d_in[0];
    const float* ehs = (const float*)d_in[1];
    const float* rc  = (const float*)d_in[2];
    const float* rs  = (const float*)d_in[3];
    const float* bq  = (const float*)d_in[5];
    const float* bk  = (const float*)d_in[7];
    const float* bv  = (const float*)d_in[9];
    const float* baq = (const float*)d_in[11];
    const float* bak = (const float*)d_in[13];
    const float* bav = (const float*)d_in[15];
    const float* bo  = (const float*)d_in[17];
    const float* bao = (const float*)d_in[19];
    const float* gq  = (const float*)d_in[20];
    const float* gk  = (const float*)d_in[21];
    const float* gaq = (const float*)d_in[22];
    const float* gak = (const float*)d_in[23];
    float* out = (float*)d_out;

    __half *xh, *wh, *wl, *aoh;
    cudaGetSymbolAddress((void**)&xh,  g_xh);
    cudaGetSymbolAddress((void**)&wh,  g_wh);
    cudaGetSymbolAddress((void**)&wl,  g_wl);
    cudaGetSymbolAddress((void**)&aoh, g_aoh);

    const int gemm_smem = 4 * 20480;   // 81920 B
    cudaFuncSetAttribute(gemm_h2, cudaFuncAttributeMaxDynamicSharedMemorySize, gemm_smem);
    cudaFuncSetAttribute(attn_h, cudaFuncAttributeMaxDynamicSharedMemorySize, ATT_SMEM);

    SplitJobs jobs;
    jobs.j[0] = { hs,  xh,                       nullptr, S_IMGC * DC };
    jobs.j[1] = { ehs, xh + (size_t)S_IMGC * DC, nullptr, S_TXTC * DC };
    const int wsrc[8] = {4, 6, 8, 10, 12, 14, 16, 18};
    for (int i = 0; i < 8; ++i)
        jobs.j[2 + i] = { (const float*)d_in[wsrc[i]],
                          wh + (size_t)i * WELEM, wl + (size_t)i * WELEM, WELEM };
    {
        dim3 grid((S_IMGC * DC / 4 + 255) / 256, 10);
        split_kernel<<<grid, 256>>>(jobs);
    }

    gemm_h2<<<dim3(DC / 64, S_IMGC / 128, 3), 256, gemm_smem>>>(
        xh, 0, 1, 2, bq, bk, bv, nullptr, 512, 0);
    gemm_h2<<<dim3(DC / 64, S_TXTC / 128, 3), 256, gemm_smem>>>(
        xh + (size_t)S_IMGC * DC, 3, 4, 5, baq, bak, bav, nullptr, 0, 0);

    rmsrope2<<<dim3(S_TOTC / 8, HC, 2), 256>>>(rc, rs, gaq, gq, gak, gk);

    attn_h<<<dim3(S_TOTC / 128, HC), 128, ATT_SMEM>>>();

    gemm_h2<<<dim3(DC / 64, S_IMGC / 128, 1), 256, gemm_smem>>>(
        aoh + (size_t)S_TXTC * DC, 6, 6, 6, bo, bo, bo, out, 0, 1);
    gemm_h2<<<dim3(DC / 64, S_TXTC / 128, 1), 256, gemm_smem>>>(
        aoh, 7, 7, 7, bao, bao, bao, out + (size_t)S_IMGC * DC, 0, 1);
}

// round 13
// speedup vs baseline: 7.5467x; 1.1082x over previous
#include <cuda_runtime.h>
#include <cuda_fp16.h>
#include <math.h>
#include <stdint.h>

#define S_IMGC 2048
#define S_TXTC 512
#define S_TOTC 2560
#define DC     1536
#define HC     24
#define DHC    64
#define WELEM  (DC * DC)

// ---------------- device scratch (allocation-free rule) ----------------
__device__ __half g_qh[(size_t)HC * S_TOTC * DHC];   // normalized+roped, pre-scaled 0.125
__device__ __half g_kh[(size_t)HC * S_TOTC * DHC];
__device__ __half g_vh[(size_t)HC * DHC * S_TOTC];   // [h][d][s] transposed
__device__ __half g_xh[(size_t)S_TOTC * DC];
__device__ __half g_wh[(size_t)8 * WELEM];
__device__ __half g_wl[(size_t)8 * WELEM];
__device__ __half g_aoh[(size_t)S_TOTC * DC];

__device__ __forceinline__ uint32_t packh2(float a, float b) {
    __half2 h = __floats2half2_rn(a, b);
    return *(uint32_t*)&h;
}

__device__ __forceinline__ void mma_f16(float* c, const uint32_t* a, const uint32_t* b) {
    asm volatile(
        "mma.sync.aligned.m16n8k16.row.col.f32.f16.f16.f32 "
        "{%0,%1,%2,%3}, {%4,%5,%6,%7}, {%8,%9}, {%0,%1,%2,%3};"
        : "+f"(c[0]), "+f"(c[1]), "+f"(c[2]), "+f"(c[3])
        : "r"(a[0]), "r"(a[1]), "r"(a[2]), "r"(a[3]), "r"(b[0]), "r"(b[1]));
}

__device__ __forceinline__ void ldsm4s(uint32_t* r, uint32_t saddr) {
    asm volatile("ldmatrix.sync.aligned.m8n8.x4.shared.b16 {%0,%1,%2,%3}, [%4];"
        : "=r"(r[0]), "=r"(r[1]), "=r"(r[2]), "=r"(r[3]) : "r"(saddr));
}

__device__ __forceinline__ void cp16(uint32_t s, const void* g) {
    asm volatile("cp.async.ca.shared.global [%0], [%1], 16;" :: "r"(s), "l"(g));
}

// ---------------------------------------------------------------------------
// Elementwise fp32 -> fp16 h (+ optional l = residual*2048).
// ---------------------------------------------------------------------------
struct SplitJob  { const float* s; __half* h; __half* l; int n; };
struct SplitJobs { SplitJob j[10]; };

__global__ __launch_bounds__(256) void split_kernel(SplitJobs jobs) {
    const SplitJob J = jobs.j[blockIdx.y];
    const int i = (blockIdx.x * 256 + threadIdx.x) * 4;
    if (i >= J.n) return;
    const float4 v = *(const float4*)(J.s + i);
    const __half h0 = __float2half_rn(v.x), h1 = __float2half_rn(v.y);
    const __half h2 = __float2half_rn(v.z), h3 = __float2half_rn(v.w);
    uint2 hw;
    { __half2 p0 = __halves2half2(h0, h1), p1 = __halves2half2(h2, h3);
      hw.x = *(uint32_t*)&p0; hw.y = *(uint32_t*)&p1; }
    *(uint2*)(J.h + i) = hw;
    if (J.l) {
        const float r0 = (v.x - __half2float(h0)) * 2048.f;
        const float r1 = (v.y - __half2float(h1)) * 2048.f;
        const float r2 = (v.z - __half2float(h2)) * 2048.f;
        const float r3 = (v.w - __half2float(h3)) * 2048.f;
        uint2 lw;
        lw.x = packh2(r0, r1); lw.y = packh2(r2, r3);
        *(uint2*)(J.l + i) = lw;
    }
}

// ---------------------------------------------------------------------------
// fp16x2 GEMM: C = Xh*(Wh + Wl/2048)^T + bias. cp.async 4-stage, BK=32.
// Block 128(M) x 64(N) [= one head], 256 threads, warp tile 32x32.
// mode 0, z<2 : fused RMS-norm + RoPE epilogue -> fp16 g_qh/g_kh
// mode 0, z==2: V transposed fp16 [h][d][s] (single precision pass)
// mode 1      : fp32 row-major outp
// ---------------------------------------------------------------------------
#define GST_AH 0u
#define GST_BH 10240u
#define GST_BL 15360u
#define GST_SZ 20480u
#define GNK    (DC / 32)

__global__ __launch_bounds__(256, 2) void gemm_h2(
    const __half* __restrict__ Xh,
    int w0, int w1, int w2,
    const float* __restrict__ b0, const float* __restrict__ b1, const float* __restrict__ b2,
    const float* __restrict__ cosb, const float* __restrict__ sinb,
    const float* __restrict__ gz0, const float* __restrict__ gz1,
    float* __restrict__ outp, int s_off, int mode)
{
    extern __shared__ uint32_t dynsm[];
    const uint32_t smb = (uint32_t)__cvta_generic_to_shared(dynsm);

    const int z = blockIdx.z;
    const int widx    = (z == 0) ? w0 : (z == 1) ? w1 : w2;
    const float* bias = (z == 0) ? b0 : (z == 1) ? b1 : b2;

    const int tid = threadIdx.x, wid = tid >> 5, lane = tid & 31;
    const int g = lane >> 2, tig = lane & 3;
    const int wm = wid & 3, wn = wid >> 2;
    const int lr16 = lane & 15, lch = lane >> 4;

    const int ldrow = tid >> 2;
    const int ldc   = tid & 3;

    const __half* AhG = Xh + (size_t)(blockIdx.y * 128 + ldrow) * DC + ldc * 8;
    const __half* BhG = g_wh + (size_t)widx * WELEM + (size_t)(blockIdx.x * 64 + ldrow) * DC + ldc * 8;
    const __half* BlG = g_wl + (size_t)widx * WELEM + (size_t)(blockIdx.x * 64 + ldrow) * DC + ldc * 8;
    const size_t rstep = (size_t)64 * DC;

    float accm[2][4][4] = {}, accc[2][4][4] = {};

    auto load_stage = [&](int st, int kt) {
        const uint32_t sb = smb + (uint32_t)st * GST_SZ;
        const uint32_t ro = (uint32_t)ldrow * 80 + (uint32_t)ldc * 16;
        const size_t go = (size_t)kt * 32;
        cp16(sb + GST_AH + ro,           AhG + go);
        cp16(sb + GST_AH + ro + 64 * 80, AhG + go + rstep);
        cp16(sb + GST_BH + ro,           BhG + go);
        cp16(sb + GST_BL + ro,           BlG + go);
    };

    load_stage(0, 0);
    asm volatile("cp.async.commit_group;" ::: "memory");
    load_stage(1, 1);
    asm volatile("cp.async.commit_group;" ::: "memory");
    load_stage(2, 2);
    asm volatile("cp.async.commit_group;" ::: "memory");

    for (int kt = 0; kt < GNK; ++kt) {
        asm volatile("cp.async.wait_group 2;" ::: "memory");
        __syncthreads();
        if (kt + 3 < GNK) load_stage((kt + 3) & 3, kt + 3);
        asm volatile("cp.async.commit_group;" ::: "memory");

        const uint32_t sb = smb + (uint32_t)(kt & 3) * GST_SZ;
        const uint32_t arow0 = (uint32_t)(wm * 32 + lr16) * 80;
        const uint32_t arow1 = (uint32_t)(wm * 32 + 16 + lr16) * 80;
        const uint32_t brow0 = (uint32_t)(wn * 32 + lr16) * 80;
        const uint32_t brow1 = (uint32_t)(wn * 32 + 16 + lr16) * 80;

        #pragma unroll
        for (int ks = 0; ks < 16; ks += 8) {
            const uint32_t co = (uint32_t)(ks + lch * 4) * 4;
            uint32_t ah[2][4], bh[2][4], bl[2][4];
            ldsm4s(ah[0], sb + GST_AH + arow0 + co);
            ldsm4s(ah[1], sb + GST_AH + arow1 + co);
            ldsm4s(bh[0], sb + GST_BH + brow0 + co);
            ldsm4s(bh[1], sb + GST_BH + brow1 + co);
            ldsm4s(bl[0], sb + GST_BL + brow0 + co);
            ldsm4s(bl[1], sb + GST_BL + brow1 + co);

            #pragma unroll
            for (int p = 0; p < 2; ++p)
                #pragma unroll
                for (int e = 0; e < 2; ++e) {
                    const int ni = p * 2 + e;
                    uint32_t bhf[2] = { bh[p][e], bh[p][e + 2] };
                    uint32_t blf[2] = { bl[p][e], bl[p][e + 2] };
                    #pragma unroll
                    for (int mi = 0; mi < 2; ++mi) {
                        mma_f16(accm[mi][ni], ah[mi], bhf);
                        mma_f16(accc[mi][ni], ah[mi], blf);
                    }
                }
        }
    }

    // finalize in place: accm = accm + accc/2048 + bias
    const float rescale = 1.0f / 2048.0f;
    #pragma unroll
    for (int mi = 0; mi < 2; ++mi)
        #pragma unroll
        for (int ni = 0; ni < 4; ++ni) {
            const int col0 = blockIdx.x * 64 + wn * 32 + ni * 8 + 2 * tig;
            const float bx = bias[col0], by = bias[col0 + 1];
            accm[mi][ni][0] += accc[mi][ni][0] * rescale + bx;
            accm[mi][ni][1] += accc[mi][ni][1] * rescale + by;
            accm[mi][ni][2] += accc[mi][ni][2] * rescale + bx;
            accm[mi][ni][3] += accc[mi][ni][3] * rescale + by;
        }

    if (mode == 0 && z < 2) {
        // ---- fused RMS-norm + RoPE (block N-tile == one head) ----
        float ssq[4] = {};
        #pragma unroll
        for (int mi = 0; mi < 2; ++mi)
            #pragma unroll
            for (int ni = 0; ni < 4; ++ni) {
                ssq[mi * 2 + 0] += accm[mi][ni][0] * accm[mi][ni][0]
                                 + accm[mi][ni][1] * accm[mi][ni][1];
                ssq[mi * 2 + 1] += accm[mi][ni][2] * accm[mi][ni][2]
                                 + accm[mi][ni][3] * accm[mi][ni][3];
            }
        #pragma unroll
        for (int f = 0; f < 4; ++f) {
            ssq[f] += __shfl_xor_sync(0xffffffffu, ssq[f], 1);
            ssq[f] += __shfl_xor_sync(0xffffffffu, ssq[f], 2);
        }
        __syncthreads();                       // compute phase fully done with smem
        float* sred = (float*)dynsm;           // [2][128]
        if (tig == 0) {
            #pragma unroll
            for (int f = 0; f < 4; ++f) {
                const int rowL = wm * 32 + (f >> 1) * 16 + (f & 1) * 8 + g;
                sred[wn * 128 + rowL] = ssq[f];
            }
        }
        __syncthreads();
        float rinv[4];
        #pragma unroll
        for (int f = 0; f < 4; ++f) {
            const int rowL = wm * 32 + (f >> 1) * 16 + (f & 1) * 8 + g;
            const float tot = ssq[f] + sred[(wn ^ 1) * 128 + rowL];
            rinv[f] = rsqrtf(tot * (1.0f / 64.0f) + 1e-6f) * (z == 0 ? 0.125f : 1.0f);
        }
        const float* gain = (z == 0) ? gz0 : gz1;
        __half* dst = (z == 0) ? g_qh : g_kh;
        const int head = blockIdx.x;
        #pragma unroll
        for (int f = 0; f < 4; ++f) {
            const int mi = f >> 1, p = f & 1;
            const int rowL = wm * 32 + mi * 16 + p * 8 + g;
            const int s = s_off + blockIdx.y * 128 + rowL;
            const float ri = rinv[f];
            #pragma unroll
            for (int ni = 0; ni < 4; ++ni) {
                const int d = wn * 32 + ni * 8 + 2 * tig;
                const float v0 = accm[mi][ni][2 * p];
                const float v1 = accm[mi][ni][2 * p + 1];
                const float cs = cosb[s * 64 + d];
                const float sn = sinb[s * 64 + d];
                const float y0 = v0 * ri * gain[d];
                const float y1 = v1 * ri * gain[d + 1];
                *(uint32_t*)(dst + ((size_t)head * S_TOTC + s) * DHC + d) =
                    packh2(y0 * cs - y1 * sn, y1 * cs + y0 * sn);
            }
        }
    } else {
        #pragma unroll
        for (int mi = 0; mi < 2; ++mi) {
            #pragma unroll
            for (int ni = 0; ni < 4; ++ni) {
                const int row0 = blockIdx.y * 128 + wm * 32 + mi * 16 + g;
                const int col0 = blockIdx.x * 64 + wn * 32 + ni * 8 + 2 * tig;
                const float v00 = accm[mi][ni][0], v01 = accm[mi][ni][1];
                const float v10 = accm[mi][ni][2], v11 = accm[mi][ni][3];
                if (mode == 0) {
                    // V: transposed single-fp16 output [h*64+d][s]
                    const int s0 = s_off + row0;
                    #pragma unroll
                    for (int e = 0; e < 2; ++e) {
                        const float va = e ? v01 : v00;
                        const float vb = e ? v11 : v10;
                        const size_t base = (size_t)(col0 + e) * S_TOTC;
                        g_vh[base + s0]     = __float2half_rn(va);
                        g_vh[base + s0 + 8] = __float2half_rn(vb);
                    }
                } else {
                    *(float2*)(outp + (size_t)row0 * DC + col0) = make_float2(v00, v01);
                    *(float2*)(outp + (size_t)(row0 + 8) * DC + col0) = make_float2(v10, v11);
                }
            }
        }
    }
}

// ---------------------------------------------------------------------------
// fp16 flash attention: cp.async double-buffered K/V, register P, single-pass
// fp16 PV (no V residual). Epilogue writes fp16 g_aoh directly.
// smem (u32): Q[128][36] @0 ; stage st: K[64][36] @4608+st*4608,
//             Vh[64][36] @4608+st*4608+2304. total 13824 u32 = 55296 B.
// ---------------------------------------------------------------------------
#define AQ_U32   0u
#define AK_U32(st)   (4608u + (uint32_t)(st) * 4608u)
#define AVH_U32(st)  (4608u + (uint32_t)(st) * 4608u + 2304u)
#define ATT_SMEM (13824 * 4)
#define NKT (S_TOTC / 64)

__global__ __launch_bounds__(128, 2) void attn_h()
{
    extern __shared__ uint32_t dynsm[];
    const uint32_t smb = (uint32_t)__cvta_generic_to_shared(dynsm);

    const int h = blockIdx.y, qt = blockIdx.x;
    const int tid = threadIdx.x;
    const int w = tid >> 5, lane = tid & 31, g = lane >> 2, tig = lane & 3;
    const int wr = w * 32;
    const int lr16 = lane & 15, lch = lane >> 4;

    const __half* khb = g_kh + (size_t)h * S_TOTC * DHC;
    const __half* vhb = g_vh + (size_t)h * DHC * S_TOTC;

    auto load_stage = [&](int st, int kt) {
        #pragma unroll
        for (int i = tid; i < 512; i += 128) {
            const int row = i >> 3, j = i & 7;
            cp16(smb + (AK_U32(st) + (uint32_t)(row * 36 + j * 4)) * 4,
                 khb + (size_t)(kt * 64 + row) * 64 + j * 8);
        }
        #pragma unroll
        for (int u = tid; u < 512; u += 128) {
            const int d = u >> 3, j = u & 7;
            cp16(smb + (AVH_U32(st) + (uint32_t)(d * 36 + j * 4)) * 4,
                 vhb + (size_t)d * S_TOTC + kt * 64 + j * 8);
        }
    };

    load_stage(0, 0);
    asm volatile("cp.async.commit_group;" ::: "memory");

    const __half* qhb = g_qh + ((size_t)h * S_TOTC + qt * 128) * DHC;
    for (int i = tid; i < 1024; i += 128) {
        const int row = i >> 3, j = i & 7;
        *(uint4*)&dynsm[AQ_U32 + row * 36 + j * 4] = *(const uint4*)(qhb + row * 64 + j * 8);
    }

    float oacc[4][4][4] = {};
    float mrow[4] = {-1e30f, -1e30f, -1e30f, -1e30f};
    float lrow[4] = {0.f, 0.f, 0.f, 0.f};

    for (int kt = 0; kt < NKT; ++kt) {
        __syncthreads();
        if (kt + 1 < NKT) load_stage((kt + 1) & 1, kt + 1);
        asm volatile("cp.async.commit_group;" ::: "memory");
        if (kt + 1 < NKT) { asm volatile("cp.async.wait_group 1;" ::: "memory"); }
        else              { asm volatile("cp.async.wait_group 0;" ::: "memory"); }
        __syncthreads();

        const uint32_t sbK  = smb + AK_U32(kt & 1) * 4;
        const uint32_t sbVh = smb + AVH_U32(kt & 1) * 4;
        const uint32_t sbQ  = smb;

        // ---- S = Q K^T ----
        float sfrag[2][8][4] = {};
        #pragma unroll
        for (int kk2 = 0; kk2 < 32; kk2 += 8) {
            const uint32_t co = (uint32_t)(kk2 + lch * 4) * 4;
            uint32_t a[2][4];
            ldsm4s(a[0], sbQ + (uint32_t)(wr + lr16) * 144 + co);
            ldsm4s(a[1], sbQ + (uint32_t)(wr + 16 + lr16) * 144 + co);
            #pragma unroll
            for (int p = 0; p < 4; ++p) {
                uint32_t bb[4];
                ldsm4s(bb, sbK + (uint32_t)(p * 16 + lr16) * 144 + co);
                #pragma unroll
                for (int e = 0; e < 2; ++e) {
                    uint32_t bf[2] = { bb[e], bb[e + 2] };
                    mma_f16(sfrag[0][p * 2 + e], a[0], bf);
                    mma_f16(sfrag[1][p * 2 + e], a[1], bf);
                }
            }
        }

        // ---- online softmax; register P ----
        uint32_t ph[2][8][2];
        float corrv[4];
        #pragma unroll
        for (int f = 0; f < 4; ++f) {
            const int mi = f >> 1, cb = (f & 1) << 1;
            float mx = mrow[f];
            #pragma unroll
            for (int ni = 0; ni < 8; ++ni)
                mx = fmaxf(mx, fmaxf(sfrag[mi][ni][cb], sfrag[mi][ni][cb + 1]));
            mx = fmaxf(mx, __shfl_xor_sync(0xffffffffu, mx, 1));
            mx = fmaxf(mx, __shfl_xor_sync(0xffffffffu, mx, 2));
            corrv[f] = __expf(mrow[f] - mx);
            mrow[f] = mx;
            float sum = 0.f;
            #pragma unroll
            for (int ni = 0; ni < 8; ++ni) {
                const float p0 = __expf(sfrag[mi][ni][cb]     - mx);
                const float p1 = __expf(sfrag[mi][ni][cb + 1] - mx);
                sum += p0 + p1;
                ph[mi][ni][f & 1] = packh2(p0, p1);
            }
            sum += __shfl_xor_sync(0xffffffffu, sum, 1);
            sum += __shfl_xor_sync(0xffffffffu, sum, 2);
            lrow[f] = lrow[f] * corrv[f] + sum;
        }

        #pragma unroll
        for (int qb = 0; qb < 4; ++qb) {
            const float cA = __shfl_sync(0xffffffffu, corrv[qb], 8 * tig);
            const float cB = __shfl_sync(0xffffffffu, corrv[qb], 8 * tig + 4);
            #pragma unroll
            for (int md = 0; md < 4; ++md) {
                oacc[md][qb][0] *= cA; oacc[md][qb][1] *= cB;
                oacc[md][qb][2] *= cA; oacc[md][qb][3] *= cB;
            }
        }

        // ---- O^T += V^T P^T ----
        #pragma unroll
        for (int kk2 = 0; kk2 < 32; kk2 += 8) {
            const int ni0 = kk2 >> 2;
            const uint32_t co = (uint32_t)(kk2 + lch * 4) * 4;
            uint32_t av[4][4];
            #pragma unroll
            for (int md = 0; md < 4; ++md)
                ldsm4s(av[md], sbVh + (uint32_t)(md * 16 + lr16) * 144 + co);
            #pragma unroll
            for (int qb = 0; qb < 4; ++qb) {
                uint32_t b[2] = { ph[qb >> 1][ni0][qb & 1], ph[qb >> 1][ni0 + 1][qb & 1] };
                #pragma unroll
                for (int md = 0; md < 4; ++md)
                    mma_f16(oacc[md][qb], av[md], b);
            }
        }
    }

    // ---- epilogue: O = (O^T)^T / l, fp16 out ----
    #pragma unroll
    for (int qb = 0; qb < 4; ++qb) {
        const float lA = __shfl_sync(0xffffffffu, lrow[qb], 8 * tig);
        const float lB = __shfl_sync(0xffffffffu, lrow[qb], 8 * tig + 4);
        const float iA = 1.0f / lA, iB = 1.0f / lB;
        const int q0 = qt * 128 + wr + qb * 8 + 2 * tig;
        #pragma unroll
        for (int md = 0; md < 4; ++md) {
            const int d0 = h * 64 + md * 16 + g;
            g_aoh[(size_t)q0 * DC + d0]           = __float2half_rn(oacc[md][qb][0] * iA);
            g_aoh[(size_t)(q0 + 1) * DC + d0]     = __float2half_rn(oacc[md][qb][1] * iB);
            g_aoh[(size_t)q0 * DC + d0 + 8]       = __float2half_rn(oacc[md][qb][2] * iA);
            g_aoh[(size_t)(q0 + 1) * DC + d0 + 8] = __float2half_rn(oacc[md][qb][3] * iB);
        }
    }
}

// ---------------------------------------------------------------------------
extern "C" void kernel_launch(void* const* d_in, const int* in_sizes, int n_in,
                              void* d_out, int out_size)
{
    (void)in_sizes; (void)n_in; (void)out_size;
    const float* hs  = (const float*)d_in[0];
    const float* ehs = (const float*)d_in[1];
    const float* rc  = (const float*)d_in[2];
    const float* rs  = (const float*)d_in[3];
    const float* bq  = (const float*)d_in[5];
    const float* bk  = (const float*)d_in[7];
    const float* bv  = (const float*)d_in[9];
    const float* baq = (const float*)d_in[11];
    const float* bak = (const float*)d_in[13];
    const float* bav = (const float*)d_in[15];
    const float* bo  = (const float*)d_in[17];
    const float* bao = (const float*)d_in[19];
    const float* gq  = (const float*)d_in[20];
    const float* gk  = (const float*)d_in[21];
    const float* gaq = (const float*)d_in[22];
    const float* gak = (const float*)d_in[23];
    float* out = (float*)d_out;

    __half *xh, *wh, *wl, *aoh;
    cudaGetSymbolAddress((void**)&xh,  g_xh);
    cudaGetSymbolAddress((void**)&wh,  g_wh);
    cudaGetSymbolAddress((void**)&wl,  g_wl);
    cudaGetSymbolAddress((void**)&aoh, g_aoh);

    const int gemm_smem = 4 * 20480;   // 81920 B
    cudaFuncSetAttribute(gemm_h2, cudaFuncAttributeMaxDynamicSharedMemorySize, gemm_smem);
    cudaFuncSetAttribute(attn_h, cudaFuncAttributeMaxDynamicSharedMemorySize, ATT_SMEM);

    SplitJobs jobs;
    jobs.j[0] = { hs,  xh,                       nullptr, S_IMGC * DC };
    jobs.j[1] = { ehs, xh + (size_t)S_IMGC * DC, nullptr, S_TXTC * DC };
    const int wsrc[8] = {4, 6, 8, 10, 12, 14, 16, 18};
    for (int i = 0; i < 8; ++i)
        jobs.j[2 + i] = { (const float*)d_in[wsrc[i]],
                          wh + (size_t)i * WELEM, wl + (size_t)i * WELEM, WELEM };
    {
        dim3 grid((S_IMGC * DC / 4 + 255) / 256, 10);
        split_kernel<<<grid, 256>>>(jobs);
    }

    // QKV (img: heads gains gq/gk, txt: gaq/gak); fused rms+rope epilogue
    gemm_h2<<<dim3(DC / 64, S_IMGC / 128, 3), 256, gemm_smem>>>(
        xh, 0, 1, 2, bq, bk, bv, rc, rs, gq, gk, nullptr, 512, 0);
    gemm_h2<<<dim3(DC / 64, S_TXTC / 128, 3), 256, gemm_smem>>>(
        xh + (size_t)S_IMGC * DC, 3, 4, 5, baq, bak, bav, rc, rs, gaq, gak, nullptr, 0, 0);

    attn_h<<<dim3(S_TOTC / 128, HC), 128, ATT_SMEM>>>();

    gemm_h2<<<dim3(DC / 64, S_IMGC / 128, 1), 256, gemm_smem>>>(
        aoh + (size_t)S_TXTC * DC, 6, 6, 6, bo, bo, bo,
        nullptr, nullptr, nullptr, nullptr, out, 0, 1);
    gemm_h2<<<dim3(DC / 64, S_TXTC / 128, 1), 256, gemm_smem>>>(
        aoh, 7, 7, 7, bao, bao, bao,
        nullptr, nullptr, nullptr, nullptr, out + (size_t)S_IMGC * DC, 0, 1);
}

// round 15
// speedup vs baseline: 10.0301x; 1.3291x over previous
#include <cuda_runtime.h>
#include <cuda_fp16.h>
#include <math.h>
#include <stdint.h>

#define S_IMGC 2048
#define S_TXTC 512
#define S_TOTC 2560
#define DC     1536
#define HC     24
#define DHC    64
#define WELEM  (DC * DC)
#define LOG2E  1.44269504f

// ---------------- device scratch (allocation-free rule) ----------------
__device__ __half g_qh[(size_t)HC * S_TOTC * DHC];   // normalized+roped, scale 0.125*log2e
__device__ __half g_kh[(size_t)HC * S_TOTC * DHC];
__device__ __half g_vh[(size_t)HC * DHC * S_TOTC];   // [h][d][s] transposed
__device__ __half g_xh[(size_t)S_TOTC * DC];
__device__ __half g_wh[(size_t)8 * WELEM];
__device__ __half g_aoh[(size_t)S_TOTC * DC];

__device__ __forceinline__ uint32_t packh2(float a, float b) {
    __half2 h = __floats2half2_rn(a, b);
    return *(uint32_t*)&h;
}

__device__ __forceinline__ void mma_f16(float* c, const uint32_t* a, const uint32_t* b) {
    asm volatile(
        "mma.sync.aligned.m16n8k16.row.col.f32.f16.f16.f32 "
        "{%0,%1,%2,%3}, {%4,%5,%6,%7}, {%8,%9}, {%0,%1,%2,%3};"
        : "+f"(c[0]), "+f"(c[1]), "+f"(c[2]), "+f"(c[3])
        : "r"(a[0]), "r"(a[1]), "r"(a[2]), "r"(a[3]), "r"(b[0]), "r"(b[1]));
}

__device__ __forceinline__ void ldsm4s(uint32_t* r, uint32_t saddr) {
    asm volatile("ldmatrix.sync.aligned.m8n8.x4.shared.b16 {%0,%1,%2,%3}, [%4];"
        : "=r"(r[0]), "=r"(r[1]), "=r"(r[2]), "=r"(r[3]) : "r"(saddr));
}

__device__ __forceinline__ void cp16(uint32_t s, const void* g) {
    asm volatile("cp.async.ca.shared.global [%0], [%1], 16;" :: "r"(s), "l"(g));
}

// ---------------------------------------------------------------------------
// Elementwise fp32 -> fp16.
// ---------------------------------------------------------------------------
struct SplitJob  { const float* s; __half* h; int n; };
struct SplitJobs { SplitJob j[10]; };

__global__ __launch_bounds__(256) void split_kernel(SplitJobs jobs) {
    const SplitJob J = jobs.j[blockIdx.y];
    const int i = (blockIdx.x * 256 + threadIdx.x) * 4;
    if (i >= J.n) return;
    const float4 v = *(const float4*)(J.s + i);
    uint2 hw;
    hw.x = packh2(v.x, v.y);
    hw.y = packh2(v.z, v.w);
    *(uint2*)(J.h + i) = hw;
}

// ---------------------------------------------------------------------------
// fp16 GEMM: C = Xh*Wh^T + bias. cp.async 4-stage, BK=32.
// Block 128(M) x 64(N) [= one head], 256 threads, warp tile 32x32.
// mode 0, z<2 : fused RMS-norm + RoPE epilogue -> fp16 g_qh/g_kh
//               (q additionally scaled by 0.125*log2e for exp2 softmax)
// mode 0, z==2: V transposed fp16 [h][d][s]
// mode 1      : fp32 row-major outp
// ---------------------------------------------------------------------------
#define GST_AH 0u
#define GST_BH 10240u
#define GST_SZ 15360u
#define GNK    (DC / 32)

__global__ __launch_bounds__(256, 2) void gemm_h1(
    const __half* __restrict__ Xh,
    int w0, int w1, int w2,
    const float* __restrict__ b0, const float* __restrict__ b1, const float* __restrict__ b2,
    const float* __restrict__ cosb, const float* __restrict__ sinb,
    const float* __restrict__ gz0, const float* __restrict__ gz1,
    float* __restrict__ outp, int s_off, int mode)
{
    extern __shared__ uint32_t dynsm[];
    const uint32_t smb = (uint32_t)__cvta_generic_to_shared(dynsm);

    const int z = blockIdx.z;
    const int widx    = (z == 0) ? w0 : (z == 1) ? w1 : w2;
    const float* bias = (z == 0) ? b0 : (z == 1) ? b1 : b2;

    const int tid = threadIdx.x, wid = tid >> 5, lane = tid & 31;
    const int g = lane >> 2, tig = lane & 3;
    const int wm = wid & 3, wn = wid >> 2;
    const int lr16 = lane & 15, lch = lane >> 4;

    const int ldrow = tid >> 2;
    const int ldc   = tid & 3;

    const __half* AhG = Xh + (size_t)(blockIdx.y * 128 + ldrow) * DC + ldc * 8;
    const __half* BhG = g_wh + (size_t)widx * WELEM + (size_t)(blockIdx.x * 64 + ldrow) * DC + ldc * 8;
    const size_t rstep = (size_t)64 * DC;

    float accm[2][4][4] = {};

    auto load_stage = [&](int st, int kt) {
        const uint32_t sb = smb + (uint32_t)st * GST_SZ;
        const uint32_t ro = (uint32_t)ldrow * 80 + (uint32_t)ldc * 16;
        const size_t go = (size_t)kt * 32;
        cp16(sb + GST_AH + ro,           AhG + go);
        cp16(sb + GST_AH + ro + 64 * 80, AhG + go + rstep);
        cp16(sb + GST_BH + ro,           BhG + go);
    };

    load_stage(0, 0);
    asm volatile("cp.async.commit_group;" ::: "memory");
    load_stage(1, 1);
    asm volatile("cp.async.commit_group;" ::: "memory");
    load_stage(2, 2);
    asm volatile("cp.async.commit_group;" ::: "memory");

    for (int kt = 0; kt < GNK; ++kt) {
        asm volatile("cp.async.wait_group 2;" ::: "memory");
        __syncthreads();
        if (kt + 3 < GNK) load_stage((kt + 3) & 3, kt + 3);
        asm volatile("cp.async.commit_group;" ::: "memory");

        const uint32_t sb = smb + (uint32_t)(kt & 3) * GST_SZ;
        const uint32_t arow0 = (uint32_t)(wm * 32 + lr16) * 80;
        const uint32_t arow1 = (uint32_t)(wm * 32 + 16 + lr16) * 80;
        const uint32_t brow0 = (uint32_t)(wn * 32 + lr16) * 80;
        const uint32_t brow1 = (uint32_t)(wn * 32 + 16 + lr16) * 80;

        #pragma unroll
        for (int ks = 0; ks < 16; ks += 8) {
            const uint32_t co = (uint32_t)(ks + lch * 4) * 4;
            uint32_t ah[2][4], bh[2][4];
            ldsm4s(ah[0], sb + GST_AH + arow0 + co);
            ldsm4s(ah[1], sb + GST_AH + arow1 + co);
            ldsm4s(bh[0], sb + GST_BH + brow0 + co);
            ldsm4s(bh[1], sb + GST_BH + brow1 + co);

            #pragma unroll
            for (int p = 0; p < 2; ++p)
                #pragma unroll
                for (int e = 0; e < 2; ++e) {
                    const int ni = p * 2 + e;
                    uint32_t bhf[2] = { bh[p][e], bh[p][e + 2] };
                    #pragma unroll
                    for (int mi = 0; mi < 2; ++mi)
                        mma_f16(accm[mi][ni], ah[mi], bhf);
                }
        }
    }

    // finalize: + bias
    #pragma unroll
    for (int mi = 0; mi < 2; ++mi)
        #pragma unroll
        for (int ni = 0; ni < 4; ++ni) {
            const int col0 = blockIdx.x * 64 + wn * 32 + ni * 8 + 2 * tig;
            const float bx = bias[col0], by = bias[col0 + 1];
            accm[mi][ni][0] += bx; accm[mi][ni][1] += by;
            accm[mi][ni][2] += bx; accm[mi][ni][3] += by;
        }

    if (mode == 0 && z < 2) {
        // ---- fused RMS-norm + RoPE (block N-tile == one head) ----
        float ssq[4] = {};
        #pragma unroll
        for (int mi = 0; mi < 2; ++mi)
            #pragma unroll
            for (int ni = 0; ni < 4; ++ni) {
                ssq[mi * 2 + 0] += accm[mi][ni][0] * accm[mi][ni][0]
                                 + accm[mi][ni][1] * accm[mi][ni][1];
                ssq[mi * 2 + 1] += accm[mi][ni][2] * accm[mi][ni][2]
                                 + accm[mi][ni][3] * accm[mi][ni][3];
            }
        #pragma unroll
        for (int f = 0; f < 4; ++f) {
            ssq[f] += __shfl_xor_sync(0xffffffffu, ssq[f], 1);
            ssq[f] += __shfl_xor_sync(0xffffffffu, ssq[f], 2);
        }
        __syncthreads();
        float* sred = (float*)dynsm;           // [2][128]
        if (tig == 0) {
            #pragma unroll
            for (int f = 0; f < 4; ++f) {
                const int rowL = wm * 32 + (f >> 1) * 16 + (f & 1) * 8 + g;
                sred[wn * 128 + rowL] = ssq[f];
            }
        }
        __syncthreads();
        float rinv[4];
        #pragma unroll
        for (int f = 0; f < 4; ++f) {
            const int rowL = wm * 32 + (f >> 1) * 16 + (f & 1) * 8 + g;
            const float tot = ssq[f] + sred[(wn ^ 1) * 128 + rowL];
            rinv[f] = rsqrtf(tot * (1.0f / 64.0f) + 1e-6f) * (z == 0 ? 0.125f * LOG2E : 1.0f);
        }
        const float* gain = (z == 0) ? gz0 : gz1;
        __half* dst = (z == 0) ? g_qh : g_kh;
        const int head = blockIdx.x;
        #pragma unroll
        for (int f = 0; f < 4; ++f) {
            const int mi = f >> 1, p = f & 1;
            const int rowL = wm * 32 + mi * 16 + p * 8 + g;
            const int s = s_off + blockIdx.y * 128 + rowL;
            const float ri = rinv[f];
            #pragma unroll
            for (int ni = 0; ni < 4; ++ni) {
                const int d = wn * 32 + ni * 8 + 2 * tig;
                const float v0 = accm[mi][ni][2 * p];
                const float v1 = accm[mi][ni][2 * p + 1];
                const float cs = cosb[s * 64 + d];
                const float sn = sinb[s * 64 + d];
                const float y0 = v0 * ri * gain[d];
                const float y1 = v1 * ri * gain[d + 1];
                *(uint32_t*)(dst + ((size_t)head * S_TOTC + s) * DHC + d) =
                    packh2(y0 * cs - y1 * sn, y1 * cs + y0 * sn);
            }
        }
    } else {
        #pragma unroll
        for (int mi = 0; mi < 2; ++mi) {
            #pragma unroll
            for (int ni = 0; ni < 4; ++ni) {
                const int row0 = blockIdx.y * 128 + wm * 32 + mi * 16 + g;
                const int col0 = blockIdx.x * 64 + wn * 32 + ni * 8 + 2 * tig;
                const float v00 = accm[mi][ni][0], v01 = accm[mi][ni][1];
                const float v10 = accm[mi][ni][2], v11 = accm[mi][ni][3];
                if (mode == 0) {
                    const int s0 = s_off + row0;
                    #pragma unroll
                    for (int e = 0; e < 2; ++e) {
                        const float va = e ? v01 : v00;
                        const float vb = e ? v11 : v10;
                        const size_t base = (size_t)(col0 + e) * S_TOTC;
                        g_vh[base + s0]     = __float2half_rn(va);
                        g_vh[base + s0 + 8] = __float2half_rn(vb);
                    }
                } else {
                    *(float2*)(outp + (size_t)row0 * DC + col0) = make_float2(v00, v01);
                    *(float2*)(outp + (size_t)(row0 + 8) * DC + col0) = make_float2(v10, v11);
                }
            }
        }
    }
}

// ---------------------------------------------------------------------------
// fp16 flash attention: cp.async double-buffered K/V, register P, exp2 softmax
// (q pre-scaled by log2e), single-pass fp16 PV. Epilogue -> fp16 g_aoh.
// ---------------------------------------------------------------------------
#define AQ_U32   0u
#define AK_U32(st)   (4608u + (uint32_t)(st) * 4608u)
#define AVH_U32(st)  (4608u + (uint32_t)(st) * 4608u + 2304u)
#define ATT_SMEM (13824 * 4)
#define NKT (S_TOTC / 64)

__global__ __launch_bounds__(128, 2) void attn_h()
{
    extern __shared__ uint32_t dynsm[];
    const uint32_t smb = (uint32_t)__cvta_generic_to_shared(dynsm);

    const int h = blockIdx.y, qt = blockIdx.x;
    const int tid = threadIdx.x;
    const int w = tid >> 5, lane = tid & 31, g = lane >> 2, tig = lane & 3;
    const int wr = w * 32;
    const int lr16 = lane & 15, lch = lane >> 4;

    const __half* khb = g_kh + (size_t)h * S_TOTC * DHC;
    const __half* vhb = g_vh + (size_t)h * DHC * S_TOTC;

    auto load_stage = [&](int st, int kt) {
        #pragma unroll
        for (int i = tid; i < 512; i += 128) {
            const int row = i >> 3, j = i & 7;
            cp16(smb + (AK_U32(st) + (uint32_t)(row * 36 + j * 4)) * 4,
                 khb + (size_t)(kt * 64 + row) * 64 + j * 8);
        }
        #pragma unroll
        for (int u = tid; u < 512; u += 128) {
            const int d = u >> 3, j = u & 7;
            cp16(smb + (AVH_U32(st) + (uint32_t)(d * 36 + j * 4)) * 4,
                 vhb + (size_t)d * S_TOTC + kt * 64 + j * 8);
        }
    };

    load_stage(0, 0);
    asm volatile("cp.async.commit_group;" ::: "memory");

    const __half* qhb = g_qh + ((size_t)h * S_TOTC + qt * 128) * DHC;
    for (int i = tid; i < 1024; i += 128) {
        const int row = i >> 3, j = i & 7;
        *(uint4*)&dynsm[AQ_U32 + row * 36 + j * 4] = *(const uint4*)(qhb + row * 64 + j * 8);
    }

    float oacc[4][4][4] = {};
    float mrow[4] = {-1e30f, -1e30f, -1e30f, -1e30f};
    float lrow[4] = {0.f, 0.f, 0.f, 0.f};

    for (int kt = 0; kt < NKT; ++kt) {
        __syncthreads();
        if (kt + 1 < NKT) load_stage((kt + 1) & 1, kt + 1);
        asm volatile("cp.async.commit_group;" ::: "memory");
        if (kt + 1 < NKT) { asm volatile("cp.async.wait_group 1;" ::: "memory"); }
        else              { asm volatile("cp.async.wait_group 0;" ::: "memory"); }
        __syncthreads();

        const uint32_t sbK  = smb + AK_U32(kt & 1) * 4;
        const uint32_t sbVh = smb + AVH_U32(kt & 1) * 4;
        const uint32_t sbQ  = smb;

        // ---- S = Q K^T  (log2 domain) ----
        float sfrag[2][8][4] = {};
        #pragma unroll
        for (int kk2 = 0; kk2 < 32; kk2 += 8) {
            const uint32_t co = (uint32_t)(kk2 + lch * 4) * 4;
            uint32_t a[2][4];
            ldsm4s(a[0], sbQ + (uint32_t)(wr + lr16) * 144 + co);
            ldsm4s(a[1], sbQ + (uint32_t)(wr + 16 + lr16) * 144 + co);
            #pragma unroll
            for (int p = 0; p < 4; ++p) {
                uint32_t bb[4];
                ldsm4s(bb, sbK + (uint32_t)(p * 16 + lr16) * 144 + co);
                #pragma unroll
                for (int e = 0; e < 2; ++e) {
                    uint32_t bf[2] = { bb[e], bb[e + 2] };
                    mma_f16(sfrag[0][p * 2 + e], a[0], bf);
                    mma_f16(sfrag[1][p * 2 + e], a[1], bf);
                }
            }
        }

        // ---- online softmax (exp2); register P ----
        uint32_t ph[2][8][2];
        float corrv[4];
        #pragma unroll
        for (int f = 0; f < 4; ++f) {
            const int mi = f >> 1, cb = (f & 1) << 1;
            float mx = mrow[f];
            #pragma unroll
            for (int ni = 0; ni < 8; ++ni)
                mx = fmaxf(mx, fmaxf(sfrag[mi][ni][cb], sfrag[mi][ni][cb + 1]));
            mx = fmaxf(mx, __shfl_xor_sync(0xffffffffu, mx, 1));
            mx = fmaxf(mx, __shfl_xor_sync(0xffffffffu, mx, 2));
            corrv[f] = exp2f(mrow[f] - mx);
            mrow[f] = mx;
            float sum = 0.f;
            #pragma unroll
            for (int ni = 0; ni < 8; ++ni) {
                const float p0 = exp2f(sfrag[mi][ni][cb]     - mx);
                const float p1 = exp2f(sfrag[mi][ni][cb + 1] - mx);
                sum += p0 + p1;
                ph[mi][ni][f & 1] = packh2(p0, p1);
            }
            sum += __shfl_xor_sync(0xffffffffu, sum, 1);
            sum += __shfl_xor_sync(0xffffffffu, sum, 2);
            lrow[f] = lrow[f] * corrv[f] + sum;
        }

        #pragma unroll
        for (int qb = 0; qb < 4; ++qb) {
            const float cA = __shfl_sync(0xffffffffu, corrv[qb], 8 * tig);
            const float cB = __shfl_sync(0xffffffffu, corrv[qb], 8 * tig + 4);
            #pragma unroll
            for (int md = 0; md < 4; ++md) {
                oacc[md][qb][0] *= cA; oacc[md][qb][1] *= cB;
                oacc[md][qb][2] *= cA; oacc[md][qb][3] *= cB;
            }
        }

        // ---- O^T += V^T P^T ----
        #pragma unroll
        for (int kk2 = 0; kk2 < 32; kk2 += 8) {
            const int ni0 = kk2 >> 2;
            const uint32_t co = (uint32_t)(kk2 + lch * 4) * 4;
            uint32_t av[4][4];
            #pragma unroll
            for (int md = 0; md < 4; ++md)
                ldsm4s(av[md], sbVh + (uint32_t)(md * 16 + lr16) * 144 + co);
            #pragma unroll
            for (int qb = 0; qb < 4; ++qb) {
                uint32_t b[2] = { ph[qb >> 1][ni0][qb & 1], ph[qb >> 1][ni0 + 1][qb & 1] };
                #pragma unroll
                for (int md = 0; md < 4; ++md)
                    mma_f16(oacc[md][qb], av[md], b);
            }
        }
    }

    // ---- epilogue: O = (O^T)^T / l, fp16 out ----
    #pragma unroll
    for (int qb = 0; qb < 4; ++qb) {
        const float lA = __shfl_sync(0xffffffffu, lrow[qb], 8 * tig);
        const float lB = __shfl_sync(0xffffffffu, lrow[qb], 8 * tig + 4);
        const float iA = 1.0f / lA, iB = 1.0f / lB;
        const int q0 = qt * 128 + wr + qb * 8 + 2 * tig;
        #pragma unroll
        for (int md = 0; md < 4; ++md) {
            const int d0 = h * 64 + md * 16 + g;
            g_aoh[(size_t)q0 * DC + d0]           = __float2half_rn(oacc[md][qb][0] * iA);
            g_aoh[(size_t)(q0 + 1) * DC + d0]     = __float2half_rn(oacc[md][qb][1] * iB);
            g_aoh[(size_t)q0 * DC + d0 + 8]       = __float2half_rn(oacc[md][qb][2] * iA);
            g_aoh[(size_t)(q0 + 1) * DC + d0 + 8] = __float2half_rn(oacc[md][qb][3] * iB);
        }
    }
}

// ---------------------------------------------------------------------------
extern "C" void kernel_launch(void* const* d_in, const int* in_sizes, int n_in,
                              void* d_out, int out_size)
{
    (void)in_sizes; (void)n_in; (void)out_size;
    const float* hs  = (const float*)d_in[0];
    const float* ehs = (const float*)d_in[1];
    const float* rc  = (const float*)d_in[2];
    const float* rs  = (const float*)d_in[3];
    const float* bq  = (const float*)d_in[5];
    const float* bk  = (const float*)d_in[7];
    const float* bv  = (const float*)d_in[9];
    const float* baq = (const float*)d_in[11];
    const float* bak = (const float*)d_in[13];
    const float* bav = (const float*)d_in[15];
    const float* bo  = (const float*)d_in[17];
    const float* bao = (const float*)d_in[19];
    const float* gq  = (const float*)d_in[20];
    const float* gk  = (const float*)d_in[21];
    const float* gaq = (const float*)d_in[22];
    const float* gak = (const float*)d_in[23];
    float* out = (float*)d_out;

    __half *xh, *wh, *aoh;
    cudaGetSymbolAddress((void**)&xh,  g_xh);
    cudaGetSymbolAddress((void**)&wh,  g_wh);
    cudaGetSymbolAddress((void**)&aoh, g_aoh);

    const int gemm_smem = 4 * 15360;   // 61440 B
    cudaFuncSetAttribute(gemm_h1, cudaFuncAttributeMaxDynamicSharedMemorySize, gemm_smem);
    cudaFuncSetAttribute(attn_h, cudaFuncAttributeMaxDynamicSharedMemorySize, ATT_SMEM);

    SplitJobs jobs;
    jobs.j[0] = { hs,  xh,                       S_IMGC * DC };
    jobs.j[1] = { ehs, xh + (size_t)S_IMGC * DC, S_TXTC * DC };
    const int wsrc[8] = {4, 6, 8, 10, 12, 14, 16, 18};
    for (int i = 0; i < 8; ++i)
        jobs.j[2 + i] = { (const float*)d_in[wsrc[i]], wh + (size_t)i * WELEM, WELEM };
    {
        dim3 grid((S_IMGC * DC / 4 + 255) / 256, 10);
        split_kernel<<<grid, 256>>>(jobs);
    }

    // QKV; fused rms+rope epilogue (q scaled by 0.125*log2e)
    gemm_h1<<<dim3(DC / 64, S_IMGC / 128, 3), 256, gemm_smem>>>(
        xh, 0, 1, 2, bq, bk, bv, rc, rs, gq, gk, nullptr, 512, 0);
    gemm_h1<<<dim3(DC / 64, S_TXTC / 128, 3), 256, gemm_smem>>>(
        xh + (size_t)S_IMGC * DC, 3, 4, 5, baq, bak, bav, rc, rs, gaq, gak, nullptr, 0, 0);

    attn_h<<<dim3(S_TOTC / 128, HC), 128, ATT_SMEM>>>();

    gemm_h1<<<dim3(DC / 64, S_IMGC / 128, 1), 256, gemm_smem>>>(
        aoh + (size_t)S_TXTC * DC, 6, 6, 6, bo, bo, bo,
        nullptr, nullptr, nullptr, nullptr, out, 0, 1);
    gemm_h1<<<dim3(DC / 64, S_TXTC / 128, 1), 256, gemm_smem>>>(
        aoh, 7, 7, 7, bao, bao, bao,
        nullptr, nullptr, nullptr, nullptr, out + (size_t)S_IMGC * DC, 0, 1);
}

// round 17
// speedup vs baseline: 10.9267x; 1.0894x over previous
#include <cuda_runtime.h>
#include <cuda_fp16.h>
#include <math.h>
#include <stdint.h>

#define S_IMGC 2048
#define S_TXTC 512
#define S_TOTC 2560
#define DC     1536
#define HC     24
#define DHC    64
#define WELEM  (DC * DC)
#define LOG2E  1.44269504f

// ---------------- device scratch (allocation-free rule) ----------------
__device__ __half g_qh[(size_t)HC * S_TOTC * DHC];   // normalized+roped, scale 0.125*log2e
__device__ __half g_kh[(size_t)HC * S_TOTC * DHC];
__device__ __half g_vh[(size_t)HC * DHC * S_TOTC];   // [h][d][s] transposed
__device__ __half g_xh[(size_t)S_TOTC * DC];         // img rows 0..2047, txt 2048..2559
__device__ __half g_wh[(size_t)8 * WELEM];           // Wq Wk Wv Waq Wak Wav Wo Wao
__device__ __half g_aoh[(size_t)S_TOTC * DC];        // attention out (s-order: txt, img)

__device__ __forceinline__ uint32_t packh2(float a, float b) {
    __half2 h = __floats2half2_rn(a, b);
    return *(uint32_t*)&h;
}

__device__ __forceinline__ void mma_f16(float* c, const uint32_t* a, const uint32_t* b) {
    asm volatile(
        "mma.sync.aligned.m16n8k16.row.col.f32.f16.f16.f32 "
        "{%0,%1,%2,%3}, {%4,%5,%6,%7}, {%8,%9}, {%0,%1,%2,%3};"
        : "+f"(c[0]), "+f"(c[1]), "+f"(c[2]), "+f"(c[3])
        : "r"(a[0]), "r"(a[1]), "r"(a[2]), "r"(a[3]), "r"(b[0]), "r"(b[1]));
}

__device__ __forceinline__ void ldsm4s(uint32_t* r, uint32_t saddr) {
    asm volatile("ldmatrix.sync.aligned.m8n8.x4.shared.b16 {%0,%1,%2,%3}, [%4];"
        : "=r"(r[0]), "=r"(r[1]), "=r"(r[2]), "=r"(r[3]) : "r"(saddr));
}

__device__ __forceinline__ void cp16(uint32_t s, const void* g) {
    asm volatile("cp.async.ca.shared.global [%0], [%1], 16;" :: "r"(s), "l"(g));
}

// ---------------------------------------------------------------------------
// Elementwise fp32 -> fp16.
// ---------------------------------------------------------------------------
struct SplitJob  { const float* s; __half* h; int n; };
struct SplitJobs { SplitJob j[10]; };

__global__ __launch_bounds__(256) void split_kernel(SplitJobs jobs) {
    const SplitJob J = jobs.j[blockIdx.y];
    const int i = (blockIdx.x * 256 + threadIdx.x) * 4;
    if (i >= J.n) return;
    const float4 v = *(const float4*)(J.s + i);
    uint2 hw;
    hw.x = packh2(v.x, v.y);
    hw.y = packh2(v.z, v.w);
    *(uint2*)(J.h + i) = hw;
}

// ---------------------------------------------------------------------------
// fp16 GEMM over BOTH segments: C = X*W^T + bias. cp.async 4-stage, BK=32.
// Block 128(M) x 64(N) [= one head col-tile], 256 threads, warp tile 32x32.
// mode 0: grid.y = 20 covers xh rows (img 0..15, txt 16..19);
//         z<2 -> fused RMS+RoPE -> g_qh/g_kh (q scaled by 0.125*log2e);
//         z=2 -> V transposed fp16 [h][d][s].
// mode 1: grid.y = 20 covers aoh rows (txt y<4, img y>=4); z=0.
// ---------------------------------------------------------------------------
#define GST_AH 0u
#define GST_BH 10240u
#define GST_SZ 15360u
#define GNK    (DC / 32)

__global__ __launch_bounds__(256, 2) void gemm_h1(
    const __half* __restrict__ Xh,
    const float* __restrict__ bq, const float* __restrict__ bk, const float* __restrict__ bv,
    const float* __restrict__ baq, const float* __restrict__ bak, const float* __restrict__ bav,
    const float* __restrict__ cosb, const float* __restrict__ sinb,
    const float* __restrict__ gq, const float* __restrict__ gk,
    const float* __restrict__ gaq, const float* __restrict__ gak,
    float* __restrict__ outp, int mode)
{
    extern __shared__ uint32_t dynsm[];
    const uint32_t smb = (uint32_t)__cvta_generic_to_shared(dynsm);

    const int z = blockIdx.z;
    const bool seg_txt = (mode == 0) ? (blockIdx.y >= 16) : (blockIdx.y < 4);
    const int widx = (mode == 0) ? (z + (seg_txt ? 3 : 0)) : (seg_txt ? 7 : 6);
    const float* bias;
    if (mode == 0)
        bias = seg_txt ? ((z == 0) ? baq : (z == 1) ? bak : bav)
                       : ((z == 0) ? bq  : (z == 1) ? bk  : bv);
    else
        bias = seg_txt ? bak /*unused slot repurposed below*/ : bav;
    // mode 1 biases actually passed via bq (bo) / bk (bao):
    if (mode == 1) bias = seg_txt ? bk : bq;

    const int tid = threadIdx.x, wid = tid >> 5, lane = tid & 31;
    const int g = lane >> 2, tig = lane & 3;
    const int wm = wid & 3, wn = wid >> 2;
    const int lr16 = lane & 15, lch = lane >> 4;

    const int ldrow = tid >> 2;
    const int ldc   = tid & 3;

    const __half* AhG = Xh + (size_t)(blockIdx.y * 128 + ldrow) * DC + ldc * 8;
    const __half* BhG = g_wh + (size_t)widx * WELEM + (size_t)(blockIdx.x * 64 + ldrow) * DC + ldc * 8;
    const size_t rstep = (size_t)64 * DC;

    float accm[2][4][4] = {};

    auto load_stage = [&](int st, int kt) {
        const uint32_t sb = smb + (uint32_t)st * GST_SZ;
        const uint32_t ro = (uint32_t)ldrow * 80 + (uint32_t)ldc * 16;
        const size_t go = (size_t)kt * 32;
        cp16(sb + GST_AH + ro,           AhG + go);
        cp16(sb + GST_AH + ro + 64 * 80, AhG + go + rstep);
        cp16(sb + GST_BH + ro,           BhG + go);
    };

    load_stage(0, 0);
    asm volatile("cp.async.commit_group;" ::: "memory");
    load_stage(1, 1);
    asm volatile("cp.async.commit_group;" ::: "memory");
    load_stage(2, 2);
    asm volatile("cp.async.commit_group;" ::: "memory");

    for (int kt = 0; kt < GNK; ++kt) {
        asm volatile("cp.async.wait_group 2;" ::: "memory");
        __syncthreads();
        if (kt + 3 < GNK) load_stage((kt + 3) & 3, kt + 3);
        asm volatile("cp.async.commit_group;" ::: "memory");

        const uint32_t sb = smb + (uint32_t)(kt & 3) * GST_SZ;
        const uint32_t arow0 = (uint32_t)(wm * 32 + lr16) * 80;
        const uint32_t arow1 = (uint32_t)(wm * 32 + 16 + lr16) * 80;
        const uint32_t brow0 = (uint32_t)(wn * 32 + lr16) * 80;
        const uint32_t brow1 = (uint32_t)(wn * 32 + 16 + lr16) * 80;

        #pragma unroll
        for (int ks = 0; ks < 16; ks += 8) {
            const uint32_t co = (uint32_t)(ks + lch * 4) * 4;
            uint32_t ah[2][4], bh[2][4];
            ldsm4s(ah[0], sb + GST_AH + arow0 + co);
            ldsm4s(ah[1], sb + GST_AH + arow1 + co);
            ldsm4s(bh[0], sb + GST_BH + brow0 + co);
            ldsm4s(bh[1], sb + GST_BH + brow1 + co);

            #pragma unroll
            for (int p = 0; p < 2; ++p)
                #pragma unroll
                for (int e = 0; e < 2; ++e) {
                    const int ni = p * 2 + e;
                    uint32_t bhf[2] = { bh[p][e], bh[p][e + 2] };
                    #pragma unroll
                    for (int mi = 0; mi < 2; ++mi)
                        mma_f16(accm[mi][ni], ah[mi], bhf);
                }
        }
    }

    // finalize: + bias
    #pragma unroll
    for (int mi = 0; mi < 2; ++mi)
        #pragma unroll
        for (int ni = 0; ni < 4; ++ni) {
            const int col0 = blockIdx.x * 64 + wn * 32 + ni * 8 + 2 * tig;
            const float bx = bias[col0], by = bias[col0 + 1];
            accm[mi][ni][0] += bx; accm[mi][ni][1] += by;
            accm[mi][ni][2] += bx; accm[mi][ni][3] += by;
        }

    if (mode == 0 && z < 2) {
        // ---- fused RMS-norm + RoPE (block N-tile == one head) ----
        float ssq[4] = {};
        #pragma unroll
        for (int mi = 0; mi < 2; ++mi)
            #pragma unroll
            for (int ni = 0; ni < 4; ++ni) {
                ssq[mi * 2 + 0] += accm[mi][ni][0] * accm[mi][ni][0]
                                 + accm[mi][ni][1] * accm[mi][ni][1];
                ssq[mi * 2 + 1] += accm[mi][ni][2] * accm[mi][ni][2]
                                 + accm[mi][ni][3] * accm[mi][ni][3];
            }
        #pragma unroll
        for (int f = 0; f < 4; ++f) {
            ssq[f] += __shfl_xor_sync(0xffffffffu, ssq[f], 1);
            ssq[f] += __shfl_xor_sync(0xffffffffu, ssq[f], 2);
        }
        __syncthreads();
        float* sred = (float*)dynsm;           // [2][128]
        if (tig == 0) {
            #pragma unroll
            for (int f = 0; f < 4; ++f) {
                const int rowL = wm * 32 + (f >> 1) * 16 + (f & 1) * 8 + g;
                sred[wn * 128 + rowL] = ssq[f];
            }
        }
        __syncthreads();
        float rinv[4];
        #pragma unroll
        for (int f = 0; f < 4; ++f) {
            const int rowL = wm * 32 + (f >> 1) * 16 + (f & 1) * 8 + g;
            const float tot = ssq[f] + sred[(wn ^ 1) * 128 + rowL];
            rinv[f] = rsqrtf(tot * (1.0f / 64.0f) + 1e-6f) * (z == 0 ? 0.125f * LOG2E : 1.0f);
        }
        const float* gain = (z == 0) ? (seg_txt ? gaq : gq) : (seg_txt ? gak : gk);
        __half* dst = (z == 0) ? g_qh : g_kh;
        const int head = blockIdx.x;
        #pragma unroll
        for (int f = 0; f < 4; ++f) {
            const int mi = f >> 1, p = f & 1;
            const int rowL = wm * 32 + mi * 16 + p * 8 + g;
            const int r = blockIdx.y * 128 + rowL;
            const int s = seg_txt ? (r - S_IMGC) : (r + S_TXTC);
            const float ri = rinv[f];
            #pragma unroll
            for (int ni = 0; ni < 4; ++ni) {
                const int d = wn * 32 + ni * 8 + 2 * tig;
                const float v0 = accm[mi][ni][2 * p];
                const float v1 = accm[mi][ni][2 * p + 1];
                const float cs = cosb[s * 64 + d];
                const float sn = sinb[s * 64 + d];
                const float y0 = v0 * ri * gain[d];
                const float y1 = v1 * ri * gain[d + 1];
                *(uint32_t*)(dst + ((size_t)head * S_TOTC + s) * DHC + d) =
                    packh2(y0 * cs - y1 * sn, y1 * cs + y0 * sn);
            }
        }
    } else {
        #pragma unroll
        for (int mi = 0; mi < 2; ++mi) {
            #pragma unroll
            for (int ni = 0; ni < 4; ++ni) {
                const int row0 = blockIdx.y * 128 + wm * 32 + mi * 16 + g;
                const int col0 = blockIdx.x * 64 + wn * 32 + ni * 8 + 2 * tig;
                const float v00 = accm[mi][ni][0], v01 = accm[mi][ni][1];
                const float v10 = accm[mi][ni][2], v11 = accm[mi][ni][3];
                if (mode == 0) {
                    // V: transposed single-fp16 output [h*64+d][s]
                    const int s0 = seg_txt ? (row0 - S_IMGC) : (row0 + S_TXTC);
                    #pragma unroll
                    for (int e = 0; e < 2; ++e) {
                        const float va = e ? v01 : v00;
                        const float vb = e ? v11 : v10;
                        const size_t base = (size_t)(col0 + e) * S_TOTC;
                        g_vh[base + s0]     = __float2half_rn(va);
                        g_vh[base + s0 + 8] = __float2half_rn(vb);
                    }
                } else {
                    // out rows: img aoh rows 512.. -> out 0..; txt aoh rows 0..511 -> out 2048..
                    const int orow = seg_txt ? (S_IMGC + row0) : (row0 - S_TXTC);
                    *(float2*)(outp + (size_t)orow * DC + col0) = make_float2(v00, v01);
                    *(float2*)(outp + (size_t)(orow + 8) * DC + col0) = make_float2(v10, v11);
                }
            }
        }
    }
}

// ---------------------------------------------------------------------------
// fp16 flash attention, NO running max (|S_log2| <= 64*0.125*log2e ~= 11.54
// guaranteed by RMS normalization -> exp2 bounded by 2^11.54, safe in
// fp32 l and fp16 P). cp.async double-buffered K/V, register P, exp2 softmax.
// ---------------------------------------------------------------------------
#define AQ_U32   0u
#define AK_U32(st)   (4608u + (uint32_t)(st) * 4608u)
#define AVH_U32(st)  (4608u + (uint32_t)(st) * 4608u + 2304u)
#define ATT_SMEM (13824 * 4)
#define NKT (S_TOTC / 64)

__global__ __launch_bounds__(128, 2) void attn_h()
{
    extern __shared__ uint32_t dynsm[];
    const uint32_t smb = (uint32_t)__cvta_generic_to_shared(dynsm);

    const int h = blockIdx.y, qt = blockIdx.x;
    const int tid = threadIdx.x;
    const int w = tid >> 5, lane = tid & 31, g = lane >> 2, tig = lane & 3;
    const int wr = w * 32;
    const int lr16 = lane & 15, lch = lane >> 4;

    const __half* khb = g_kh + (size_t)h * S_TOTC * DHC;
    const __half* vhb = g_vh + (size_t)h * DHC * S_TOTC;

    auto load_stage = [&](int st, int kt) {
        #pragma unroll
        for (int i = tid; i < 512; i += 128) {
            const int row = i >> 3, j = i & 7;
            cp16(smb + (AK_U32(st) + (uint32_t)(row * 36 + j * 4)) * 4,
                 khb + (size_t)(kt * 64 + row) * 64 + j * 8);
        }
        #pragma unroll
        for (int u = tid; u < 512; u += 128) {
            const int d = u >> 3, j = u & 7;
            cp16(smb + (AVH_U32(st) + (uint32_t)(d * 36 + j * 4)) * 4,
                 vhb + (size_t)d * S_TOTC + kt * 64 + j * 8);
        }
    };

    load_stage(0, 0);
    asm volatile("cp.async.commit_group;" ::: "memory");

    const __half* qhb = g_qh + ((size_t)h * S_TOTC + qt * 128) * DHC;
    for (int i = tid; i < 1024; i += 128) {
        const int row = i >> 3, j = i & 7;
        *(uint4*)&dynsm[AQ_U32 + row * 36 + j * 4] = *(const uint4*)(qhb + row * 64 + j * 8);
    }

    float oacc[4][4][4] = {};
    float lrow[4] = {0.f, 0.f, 0.f, 0.f};

    for (int kt = 0; kt < NKT; ++kt) {
        __syncthreads();
        if (kt + 1 < NKT) load_stage((kt + 1) & 1, kt + 1);
        asm volatile("cp.async.commit_group;" ::: "memory");
        if (kt + 1 < NKT) { asm volatile("cp.async.wait_group 1;" ::: "memory"); }
        else              { asm volatile("cp.async.wait_group 0;" ::: "memory"); }
        __syncthreads();

        const uint32_t sbK  = smb + AK_U32(kt & 1) * 4;
        const uint32_t sbVh = smb + AVH_U32(kt & 1) * 4;
        const uint32_t sbQ  = smb;

        // ---- S = Q K^T  (log2 domain) ----
        float sfrag[2][8][4] = {};
        #pragma unroll
        for (int kk2 = 0; kk2 < 32; kk2 += 8) {
            const uint32_t co = (uint32_t)(kk2 + lch * 4) * 4;
            uint32_t a[2][4];
            ldsm4s(a[0], sbQ + (uint32_t)(wr + lr16) * 144 + co);
            ldsm4s(a[1], sbQ + (uint32_t)(wr + 16 + lr16) * 144 + co);
            #pragma unroll
            for (int p = 0; p < 4; ++p) {
                uint32_t bb[4];
                ldsm4s(bb, sbK + (uint32_t)(p * 16 + lr16) * 144 + co);
                #pragma unroll
                for (int e = 0; e < 2; ++e) {
                    uint32_t bf[2] = { bb[e], bb[e + 2] };
                    mma_f16(sfrag[0][p * 2 + e], a[0], bf);
                    mma_f16(sfrag[1][p * 2 + e], a[1], bf);
                }
            }
        }

        // ---- softmax numerator (no max shift); register P ----
        uint32_t ph[2][8][2];
        #pragma unroll
        for (int f = 0; f < 4; ++f) {
            const int mi = f >> 1, cb = (f & 1) << 1;
            float sum = 0.f;
            #pragma unroll
            for (int ni = 0; ni < 8; ++ni) {
                const float p0 = exp2f(sfrag[mi][ni][cb]);
                const float p1 = exp2f(sfrag[mi][ni][cb + 1]);
                sum += p0 + p1;
                ph[mi][ni][f & 1] = packh2(p0, p1);
            }
            sum += __shfl_xor_sync(0xffffffffu, sum, 1);
            sum += __shfl_xor_sync(0xffffffffu, sum, 2);
            lrow[f] += sum;
        }

        // ---- O^T += V^T P^T ----
        #pragma unroll
        for (int kk2 = 0; kk2 < 32; kk2 += 8) {
            const int ni0 = kk2 >> 2;
            const uint32_t co = (uint32_t)(kk2 + lch * 4) * 4;
            uint32_t av[4][4];
            #pragma unroll
            for (int md = 0; md < 4; ++md)
                ldsm4s(av[md], sbVh + (uint32_t)(md * 16 + lr16) * 144 + co);
            #pragma unroll
            for (int qb = 0; qb < 4; ++qb) {
                uint32_t b[2] = { ph[qb >> 1][ni0][qb & 1], ph[qb >> 1][ni0 + 1][qb & 1] };
                #pragma unroll
                for (int md = 0; md < 4; ++md)
                    mma_f16(oacc[md][qb], av[md], b);
            }
        }
    }

    // ---- epilogue: O = (O^T)^T / l, fp16 out ----
    #pragma unroll
    for (int qb = 0; qb < 4; ++qb) {
        const float lA = __shfl_sync(0xffffffffu, lrow[qb], 8 * tig);
        const float lB = __shfl_sync(0xffffffffu, lrow[qb], 8 * tig + 4);
        const float iA = 1.0f / lA, iB = 1.0f / lB;
        const int q0 = qt * 128 + wr + qb * 8 + 2 * tig;
        #pragma unroll
        for (int md = 0; md < 4; ++md) {
            const int d0 = h * 64 + md * 16 + g;
            g_aoh[(size_t)q0 * DC + d0]           = __float2half_rn(oacc[md][qb][0] * iA);
            g_aoh[(size_t)(q0 + 1) * DC + d0]     = __float2half_rn(oacc[md][qb][1] * iB);
            g_aoh[(size_t)q0 * DC + d0 + 8]       = __float2half_rn(oacc[md][qb][2] * iA);
            g_aoh[(size_t)(q0 + 1) * DC + d0 + 8] = __float2half_rn(oacc[md][qb][3] * iB);
        }
    }
}

// ---------------------------------------------------------------------------
extern "C" void kernel_launch(void* const* d_in, const int* in_sizes, int n_in,
                              void* d_out, int out_size)
{
    (void)in_sizes; (void)n_in; (void)out_size;
    const float* hs  = (const float*)d_in[0];
    const float* ehs = (const float*)d_in[1];
    const float* rc  = (const float*)d_in[2];
    const float* rs  = (const float*)d_in[3];
    const float* bq  = (const float*)d_in[5];
    const float* bk  = (const float*)d_in[7];
    const float* bv  = (const float*)d_in[9];
    const float* baq = (const float*)d_in[11];
    const float* bak = (const float*)d_in[13];
    const float* bav = (const float*)d_in[15];
    const float* bo  = (const float*)d_in[17];
    const float* bao = (const float*)d_in[19];
    const float* gq  = (const float*)d_in[20];
    const float* gk  = (const float*)d_in[21];
    const float* gaq = (const float*)d_in[22];
    const float* gak = (const float*)d_in[23];
    float* out = (float*)d_out;

    __half *xh, *wh, *aoh;
    cudaGetSymbolAddress((void**)&xh,  g_xh);
    cudaGetSymbolAddress((void**)&wh,  g_wh);
    cudaGetSymbolAddress((void**)&aoh, g_aoh);

    const int gemm_smem = 4 * 15360;   // 61440 B
    cudaFuncSetAttribute(gemm_h1, cudaFuncAttributeMaxDynamicSharedMemorySize, gemm_smem);
    cudaFuncSetAttribute(attn_h, cudaFuncAttributeMaxDynamicSharedMemorySize, ATT_SMEM);

    SplitJobs jobs;
    jobs.j[0] = { hs,  xh,                       S_IMGC * DC };
    jobs.j[1] = { ehs, xh + (size_t)S_IMGC * DC, S_TXTC * DC };
    const int wsrc[8] = {4, 6, 8, 10, 12, 14, 16, 18};
    for (int i = 0; i < 8; ++i)
        jobs.j[2 + i] = { (const float*)d_in[wsrc[i]], wh + (size_t)i * WELEM, WELEM };
    {
        dim3 grid((S_IMGC * DC / 4 + 255) / 256, 10);
        split_kernel<<<grid, 256>>>(jobs);
    }

    // QKV both segments in one launch (grid.y: 0..15 img, 16..19 txt)
    gemm_h1<<<dim3(DC / 64, S_TOTC / 128, 3), 256, gemm_smem>>>(
        xh, bq, bk, bv, baq, bak, bav, rc, rs, gq, gk, gaq, gak, nullptr, 0);

    attn_h<<<dim3(S_TOTC / 128, HC), 128, ATT_SMEM>>>();

    // Out-projection both segments in one launch (grid.y: 0..3 txt, 4..19 img).
    // mode 1 biases carried in (bq, bk) slots = (bo, bao).
    gemm_h1<<<dim3(DC / 64, S_TOTC / 128, 1), 256, gemm_smem>>>(
        aoh, bo, bao, nullptr, nullptr, nullptr, nullptr,
        nullptr, nullptr, nullptr, nullptr, nullptr, nullptr, out, 1);
}